// round 1
// baseline (speedup 1.0000x reference)
#include <cuda_runtime.h>
#include <math.h>

#define LQ 1600
#define CD 256
#define NHD 8
#define HD 32
#define DFF 1024
#define GH 40
#define GW 40
#define EPSV 1e-5f
#define QSCALE 0.17677669529663687f  // 1/sqrt(32)

// ---------------- scratch (device globals; no allocation) ----------------
static __device__ float g_t[LQ*CD];
static __device__ float g_qkin[LQ*CD];
static __device__ float g_q[LQ*CD];
static __device__ float g_k[LQ*CD];
static __device__ float g_v[LQ*CD];
static __device__ float g_att[LQ*CD];
static __device__ float g_tgt[LQ*CD];
static __device__ float g_qv[LQ*2*CD];
static __device__ float g_idkv[LQ*264];
static __device__ float g_gK[LQ*CD];
static __device__ float g_gV[LQ*CD];
static __device__ float g_x[LQ*DFF];
static __device__ float g_x2[LQ*DFF];
static __device__ float g_stats[64];

// ---------------- LayerNorm (optionally + pos add) ----------------
__global__ __launch_bounds__(256) void ln_kernel(
    const float* __restrict__ x, const float* __restrict__ g, const float* __restrict__ b,
    float* __restrict__ y, const float* __restrict__ pos, float* __restrict__ qkout) {
  int l = blockIdx.x;
  int c = threadIdx.x;
  float v = x[(size_t)l*CD + c];
  float s = v, s2 = v*v;
  #pragma unroll
  for (int o = 16; o; o >>= 1) {
    s  += __shfl_xor_sync(0xffffffffu, s,  o);
    s2 += __shfl_xor_sync(0xffffffffu, s2, o);
  }
  __shared__ float sh[8], sh2[8], smv[2];
  int w = c >> 5, lane = c & 31;
  if (lane == 0) { sh[w] = s; sh2[w] = s2; }
  __syncthreads();
  if (c == 0) {
    float a = 0.f, a2 = 0.f;
    #pragma unroll
    for (int i = 0; i < 8; i++) { a += sh[i]; a2 += sh2[i]; }
    float mean = a * (1.0f/CD);
    float var  = a2 * (1.0f/CD) - mean*mean;
    smv[0] = mean; smv[1] = rsqrtf(var + EPSV);
  }
  __syncthreads();
  float out = (v - smv[0]) * smv[1] * g[c] + b[c];
  y[(size_t)l*CD + c] = out;
  if (qkout) qkout[(size_t)l*CD + c] = out + pos[(size_t)l*CD + c];
}

// ---------------- GEMM: C[M,N] = A[M,K] @ B[N,K]^T + bias (+res) ----------------
// 64x64 block tile, 16 k-slice, 256 threads, 4x4 microtile.
// Requires: M % 64 == 0, K % 16 == 0.  N arbitrary (guarded).
__global__ __launch_bounds__(256) void gemm_nt(
    const float* __restrict__ A, const float* __restrict__ B,
    const float* __restrict__ bias, const float* __restrict__ res,
    float* __restrict__ Cout, int M, int N, int K) {
  __shared__ float As[16][64];
  __shared__ float Bs[16][64];
  int bm = blockIdx.y * 64, bn = blockIdx.x * 64;
  int tid = threadIdx.x;
  int tx = tid & 15, ty = tid >> 4;
  float acc[4][4] = {};
  int r = tid >> 2, c4 = (tid & 3) << 2;
  for (int k0 = 0; k0 < K; k0 += 16) {
    float4 a = *(const float4*)(A + (size_t)(bm + r)*K + k0 + c4);
    As[c4+0][r] = a.x; As[c4+1][r] = a.y; As[c4+2][r] = a.z; As[c4+3][r] = a.w;
    float4 bv = make_float4(0.f,0.f,0.f,0.f);
    if (bn + r < N) bv = *(const float4*)(B + (size_t)(bn + r)*K + k0 + c4);
    Bs[c4+0][r] = bv.x; Bs[c4+1][r] = bv.y; Bs[c4+2][r] = bv.z; Bs[c4+3][r] = bv.w;
    __syncthreads();
    #pragma unroll
    for (int kk = 0; kk < 16; kk++) {
      float4 a4 = *(const float4*)&As[kk][ty*4];
      float4 b4 = *(const float4*)&Bs[kk][tx*4];
      float av[4] = {a4.x, a4.y, a4.z, a4.w};
      float bw[4] = {b4.x, b4.y, b4.z, b4.w};
      #pragma unroll
      for (int i = 0; i < 4; i++)
        #pragma unroll
        for (int j = 0; j < 4; j++)
          acc[i][j] = fmaf(av[i], bw[j], acc[i][j]);
    }
    __syncthreads();
  }
  #pragma unroll
  for (int i = 0; i < 4; i++) {
    int m = bm + ty*4 + i;
    #pragma unroll
    for (int j = 0; j < 4; j++) {
      int n = bn + tx*4 + j;
      if (n < N) {
        float val = acc[i][j] + bias[n];
        if (res) val += res[(size_t)m*N + n];
        Cout[(size_t)m*N + n] = val;
      }
    }
  }
}

// ---------------- Fused full attention (flash-style, online softmax) ----------------
// grid (25 q-tiles, 8 heads), 256 threads. Head-interleaved (L,C) layout.
__global__ __launch_bounds__(256) void attn_kernel(
    const float* __restrict__ Q, const float* __restrict__ Kp,
    const float* __restrict__ Vp, float* __restrict__ O) {
  __shared__ float Qs[HD][64];
  __shared__ float Ks[HD][64];
  __shared__ float Vs[64][34];
  __shared__ float Ps[64][65];
  const int h = blockIdx.y;
  const int q0 = blockIdx.x * 64;
  const int tid = threadIdx.x;
  const int tx = tid & 15, ty = tid >> 4;

  #pragma unroll
  for (int it = 0; it < 2; it++) {
    int e = tid + it*256;
    int r = e >> 3, d4 = (e & 7) << 2;
    const float4 qv = *(const float4*)(Q + (size_t)(q0 + r)*CD + h*HD + d4);
    Qs[d4+0][r] = qv.x * QSCALE; Qs[d4+1][r] = qv.y * QSCALE;
    Qs[d4+2][r] = qv.z * QSCALE; Qs[d4+3][r] = qv.w * QSCALE;
  }
  float m_i[4], l_i[4], oa[4][2];
  #pragma unroll
  for (int i = 0; i < 4; i++) { m_i[i] = -1e30f; l_i[i] = 0.f; oa[i][0] = 0.f; oa[i][1] = 0.f; }

  for (int k0 = 0; k0 < LQ; k0 += 64) {
    #pragma unroll
    for (int it = 0; it < 2; it++) {
      int e = tid + it*256;
      int r = e >> 3, d4 = (e & 7) << 2;
      const float4 kv = *(const float4*)(Kp + (size_t)(k0 + r)*CD + h*HD + d4);
      Ks[d4+0][r] = kv.x; Ks[d4+1][r] = kv.y; Ks[d4+2][r] = kv.z; Ks[d4+3][r] = kv.w;
      const float4 vv = *(const float4*)(Vp + (size_t)(k0 + r)*CD + h*HD + d4);
      Vs[r][d4+0] = vv.x; Vs[r][d4+1] = vv.y; Vs[r][d4+2] = vv.z; Vs[r][d4+3] = vv.w;
    }
    __syncthreads();
    float s[4][4] = {};
    #pragma unroll
    for (int d = 0; d < HD; d++) {
      float4 a4 = *(const float4*)&Qs[d][ty*4];
      float4 b4 = *(const float4*)&Ks[d][tx*4];
      float av[4] = {a4.x, a4.y, a4.z, a4.w};
      float bw[4] = {b4.x, b4.y, b4.z, b4.w};
      #pragma unroll
      for (int i = 0; i < 4; i++)
        #pragma unroll
        for (int j = 0; j < 4; j++)
          s[i][j] = fmaf(av[i], bw[j], s[i][j]);
    }
    #pragma unroll
    for (int i = 0; i < 4; i++) {
      float rm = fmaxf(fmaxf(s[i][0], s[i][1]), fmaxf(s[i][2], s[i][3]));
      #pragma unroll
      for (int o = 8; o; o >>= 1) rm = fmaxf(rm, __shfl_xor_sync(0xffffffffu, rm, o));
      float mnew = fmaxf(m_i[i], rm);
      float alpha = __expf(m_i[i] - mnew);
      float rs = 0.f;
      #pragma unroll
      for (int j = 0; j < 4; j++) {
        float p = __expf(s[i][j] - mnew);
        Ps[ty*4+i][tx*4+j] = p;
        rs += p;
      }
      #pragma unroll
      for (int o = 8; o; o >>= 1) rs += __shfl_xor_sync(0xffffffffu, rs, o);
      l_i[i] = l_i[i]*alpha + rs;
      m_i[i] = mnew;
      oa[i][0] *= alpha; oa[i][1] *= alpha;
    }
    __syncthreads();
    #pragma unroll 4
    for (int kk = 0; kk < 64; kk++) {
      float2 v2 = *(const float2*)&Vs[kk][tx*2];
      #pragma unroll
      for (int i = 0; i < 4; i++) {
        float p = Ps[ty*4+i][kk];
        oa[i][0] = fmaf(p, v2.x, oa[i][0]);
        oa[i][1] = fmaf(p, v2.y, oa[i][1]);
      }
    }
    __syncthreads();
  }
  #pragma unroll
  for (int i = 0; i < 4; i++) {
    float inv = 1.f / l_i[i];
    int row = q0 + ty*4 + i;
    O[(size_t)row*CD + h*HD + tx*2+0] = oa[i][0]*inv;
    O[(size_t)row*CD + h*HD + tx*2+1] = oa[i][1]*inv;
  }
}

// ---------------- curr_Q / global_K / global_V construction ----------------
__global__ __launch_bounds__(256) void make_kv_kernel(
    const float* __restrict__ qv, const float* __restrict__ idkv,
    float* __restrict__ q, float* __restrict__ gK, float* __restrict__ gV) {
  int l = blockIdx.x, c = threadIdx.x;
  float cq  = qv[(size_t)l*512 + c];
  float cv  = qv[(size_t)l*512 + 256 + c];
  float idk = idkv[(size_t)l*264 + (c >> 5)];
  float idv = idkv[(size_t)l*264 + 8 + c];
  q [(size_t)l*CD + c] = cq;
  gK[(size_t)l*CD + c] = cq * (1.f + tanhf(idk));
  gV[(size_t)l*CD + c] = cv + idv;
}

// ---------------- Local 15x15 window attention ----------------
// grid LQ blocks, 8 warps (one per head), lane = head dim.
__global__ __launch_bounds__(256) void local_attn_kernel(
    const float* __restrict__ Q, const float* __restrict__ Kp,
    const float* __restrict__ Vp, float* __restrict__ O) {
  __shared__ float p_sh[8][226];
  int n = blockIdx.x;
  int r = n / GW, c = n % GW;
  int h = threadIdx.x >> 5, lane = threadIdx.x & 31;
  float qd = Q[(size_t)n*CD + h*HD + lane] * QSCALE;
  int w = 0;
  for (int i = 0; i < 15; i++) {
    int rr = r + i - 7;
    for (int j = 0; j < 15; j++, w++) {
      int cc = c + j - 7;
      float logit = -1e30f;
      if ((unsigned)rr < (unsigned)GH && (unsigned)cc < (unsigned)GW) {
        float t = qd * Kp[(size_t)(rr*GW + cc)*CD + h*HD + lane];
        #pragma unroll
        for (int o = 16; o; o >>= 1) t += __shfl_xor_sync(0xffffffffu, t, o);
        logit = t;
      }
      if (lane == 0) p_sh[h][w] = logit;
    }
  }
  __syncwarp();
  float m = -1e30f;
  for (int ww = lane; ww < 225; ww += 32) m = fmaxf(m, p_sh[h][ww]);
  #pragma unroll
  for (int o = 16; o; o >>= 1) m = fmaxf(m, __shfl_xor_sync(0xffffffffu, m, o));
  float ssum = 0.f;
  for (int ww = lane; ww < 225; ww += 32) {
    float p = __expf(p_sh[h][ww] - m);
    p_sh[h][ww] = p;
    ssum += p;
  }
  #pragma unroll
  for (int o = 16; o; o >>= 1) ssum += __shfl_xor_sync(0xffffffffu, ssum, o);
  float inv = 1.f / ssum;
  __syncwarp();
  float oacc = 0.f;
  w = 0;
  for (int i = 0; i < 15; i++) {
    int rr = r + i - 7;
    for (int j = 0; j < 15; j++, w++) {
      int cc = c + j - 7;
      if ((unsigned)rr < (unsigned)GH && (unsigned)cc < (unsigned)GW)
        oacc = fmaf(p_sh[h][w], Vp[(size_t)(rr*GW + cc)*CD + h*HD + lane], oacc);
    }
  }
  O[(size_t)n*CD + h*HD + lane] = oacc * inv;
}

// ---------------- GroupNorm stats (per group: 32 ch x 1600 pos) ----------------
__global__ __launch_bounds__(1024) void gn_stats_kernel(
    const float* __restrict__ x, float* __restrict__ stats) {
  int g = blockIdx.x;
  float s = 0.f, s2 = 0.f;
  for (int idx = threadIdx.x; idx < LQ*32; idx += 1024) {
    int l = idx >> 5, ch = idx & 31;
    float v = x[(size_t)l*DFF + g*32 + ch];
    s += v; s2 += v*v;
  }
  #pragma unroll
  for (int o = 16; o; o >>= 1) {
    s  += __shfl_xor_sync(0xffffffffu, s,  o);
    s2 += __shfl_xor_sync(0xffffffffu, s2, o);
  }
  __shared__ float sh[32], sh2[32];
  int w = threadIdx.x >> 5, lane = threadIdx.x & 31;
  if (lane == 0) { sh[w] = s; sh2[w] = s2; }
  __syncthreads();
  if (w == 0) {
    s = sh[lane]; s2 = sh2[lane];
    #pragma unroll
    for (int o = 16; o; o >>= 1) {
      s  += __shfl_xor_sync(0xffffffffu, s,  o);
      s2 += __shfl_xor_sync(0xffffffffu, s2, o);
    }
    if (lane == 0) {
      const float invn = 1.f / (LQ * 32.f);
      float mean = s * invn;
      float var  = s2 * invn - mean*mean;
      stats[g*2]   = mean;
      stats[g*2+1] = rsqrtf(var + EPSV);
    }
  }
}

// ---------------- GN apply + exact GELU ----------------
__global__ __launch_bounds__(256) void gn_gelu_kernel(
    const float* __restrict__ x, const float* __restrict__ gg, const float* __restrict__ gb,
    const float* __restrict__ stats, float* __restrict__ y) {
  int idx = blockIdx.x * 256 + threadIdx.x;
  int ch = idx & (DFF-1);
  int g = ch >> 5;
  float v = (x[idx] - stats[g*2]) * stats[g*2+1] * gg[ch] + gb[ch];
  y[idx] = 0.5f * v * (1.f + erff(v * 0.70710678118654752f));
}

// ---------------- 5x5 depthwise conv, pad 2 ----------------
// grid (5,5,32): 8x8 spatial tile x 32-channel group; 12x12 shared halo tile.
__global__ __launch_bounds__(256) void dwconv_kernel(
    const float* __restrict__ x, const float* __restrict__ kern, float* __restrict__ y) {
  __shared__ float tile[12][12][32];
  __shared__ float kw[32][25];
  int tid = threadIdx.x;
  int ch0 = blockIdx.z * 32;
  int r0 = blockIdx.y * 8 - 2, c0 = blockIdx.x * 8 - 2;
  for (int e = tid; e < 12*12*32; e += 256) {
    int ch = e & 31;
    int sp = e >> 5;
    int ri = sp / 12, ci = sp % 12;
    int rr = r0 + ri, cc = c0 + ci;
    float v = 0.f;
    if ((unsigned)rr < (unsigned)GH && (unsigned)cc < (unsigned)GW)
      v = x[(size_t)(rr*GW + cc)*DFF + ch0 + ch];
    tile[ri][ci][ch] = v;
  }
  for (int e = tid; e < 32*25; e += 256)
    kw[e/25][e%25] = kern[(size_t)(ch0 + e/25)*25 + e%25];
  __syncthreads();
  for (int e = tid; e < 8*8*32; e += 256) {
    int ch = e & 31;
    int sp = e >> 5;
    int ri = sp >> 3, ci = sp & 7;
    float acc = 0.f;
    #pragma unroll
    for (int i = 0; i < 5; i++)
      #pragma unroll
      for (int j = 0; j < 5; j++)
        acc = fmaf(tile[ri+i][ci+j][ch], kw[ch][i*5+j], acc);
    int rr = blockIdx.y*8 + ri, cc = blockIdx.x*8 + ci;
    y[(size_t)(rr*GW + cc)*DFF + ch0 + ch] = acc;
  }
}

// ---------------- launcher ----------------
extern "C" void kernel_launch(void* const* d_in, const int* in_sizes, int n_in,
                              void* d_out, int out_size) {
  const float* in_tgt   = (const float*)d_in[0];
  const float* id_emb   = (const float*)d_in[1];
  const float* self_pos = (const float*)d_in[2];
  const float* ln1_g = (const float*)d_in[3];
  const float* ln1_b = (const float*)d_in[4];
  const float* sa_wq = (const float*)d_in[5];
  const float* sa_bq = (const float*)d_in[6];
  const float* sa_wk = (const float*)d_in[7];
  const float* sa_bk = (const float*)d_in[8];
  const float* sa_wv = (const float*)d_in[9];
  const float* sa_bv = (const float*)d_in[10];
  const float* sa_wo = (const float*)d_in[11];
  const float* sa_bo = (const float*)d_in[12];
  const float* ln2_g = (const float*)d_in[13];
  const float* ln2_b = (const float*)d_in[14];
  const float* w_qv = (const float*)d_in[15];
  const float* b_qv = (const float*)d_in[16];
  const float* w_id = (const float*)d_in[17];
  const float* b_id = (const float*)d_in[18];
  const float* lt_wo = (const float*)d_in[19];
  const float* lt_bo = (const float*)d_in[20];
  const float* st_wo = (const float*)d_in[21];
  const float* st_bo = (const float*)d_in[22];
  const float* ln3_g = (const float*)d_in[23];
  const float* ln3_b = (const float*)d_in[24];
  const float* w1 = (const float*)d_in[25];
  const float* b1 = (const float*)d_in[26];
  const float* gn_g = (const float*)d_in[27];
  const float* gn_b = (const float*)d_in[28];
  const float* dw_k = (const float*)d_in[29];
  const float* w2 = (const float*)d_in[30];
  const float* b2 = (const float*)d_in[31];
  float* out = (float*)d_out;

  float *t, *qkin, *q, *k, *v, *att, *tgtb, *qv, *idkv, *gK, *gV, *x, *x2, *stats;
  cudaGetSymbolAddress((void**)&t,     g_t);
  cudaGetSymbolAddress((void**)&qkin,  g_qkin);
  cudaGetSymbolAddress((void**)&q,     g_q);
  cudaGetSymbolAddress((void**)&k,     g_k);
  cudaGetSymbolAddress((void**)&v,     g_v);
  cudaGetSymbolAddress((void**)&att,   g_att);
  cudaGetSymbolAddress((void**)&tgtb,  g_tgt);
  cudaGetSymbolAddress((void**)&qv,    g_qv);
  cudaGetSymbolAddress((void**)&idkv,  g_idkv);
  cudaGetSymbolAddress((void**)&gK,    g_gK);
  cudaGetSymbolAddress((void**)&gV,    g_gV);
  cudaGetSymbolAddress((void**)&x,     g_x);
  cudaGetSymbolAddress((void**)&x2,    g_x2);
  cudaGetSymbolAddress((void**)&stats, g_stats);

  dim3 g66(4, 25);      // N=256 GEMMs
  dim3 gAttn(25, 8);

  // residual copy
  cudaMemcpyAsync(tgtb, in_tgt, sizeof(float)*LQ*CD, cudaMemcpyDeviceToDevice, 0);

  // --- self attention ---
  ln_kernel<<<LQ,256>>>(in_tgt, ln1_g, ln1_b, t, self_pos, qkin);
  gemm_nt<<<g66,256>>>(qkin, sa_wq, sa_bq, nullptr, q, LQ, CD, CD);
  gemm_nt<<<g66,256>>>(qkin, sa_wk, sa_bk, nullptr, k, LQ, CD, CD);
  gemm_nt<<<g66,256>>>(t,    sa_wv, sa_bv, nullptr, v, LQ, CD, CD);
  attn_kernel<<<gAttn,256>>>(q, k, v, att);
  gemm_nt<<<g66,256>>>(att, sa_wo, sa_bo, tgtb, tgtb, LQ, CD, CD);

  // --- long/short term attention ---
  ln_kernel<<<LQ,256>>>(tgtb, ln2_g, ln2_b, t, nullptr, nullptr);
  gemm_nt<<<dim3(8,25),256>>>(t, w_qv, b_qv, nullptr, qv, LQ, 512, CD);
  gemm_nt<<<dim3(5,25),256>>>(id_emb, w_id, b_id, nullptr, idkv, LQ, 264, CD);
  make_kv_kernel<<<LQ,256>>>(qv, idkv, q, gK, gV);
  attn_kernel<<<gAttn,256>>>(q, gK, gV, att);
  gemm_nt<<<g66,256>>>(att, lt_wo, lt_bo, tgtb, tgtb, LQ, CD, CD);
  local_attn_kernel<<<LQ,256>>>(q, gK, gV, att);
  gemm_nt<<<g66,256>>>(att, st_wo, st_bo, tgtb, tgtb, LQ, CD, CD);

  // --- MLP: LN -> w1 -> GN -> GELU -> dwconv -> w2 ---
  ln_kernel<<<LQ,256>>>(tgtb, ln3_g, ln3_b, t, nullptr, nullptr);
  gemm_nt<<<dim3(16,25),256>>>(t, w1, b1, nullptr, x, LQ, DFF, CD);
  gn_stats_kernel<<<32,1024>>>(x, stats);
  gn_gelu_kernel<<<(LQ*DFF)/256,256>>>(x, gn_g, gn_b, stats, x2);
  dwconv_kernel<<<dim3(5,5,32),256>>>(x2, dw_k, x);
  gemm_nt<<<g66,256>>>(x, w2, b2, tgtb, out, LQ, CD, DFF);
}

// round 2
// speedup vs baseline: 1.1808x; 1.1808x over previous
#include <cuda_runtime.h>
#include <math.h>

#define LQ 1600
#define CD 256
#define NHD 8
#define HD 32
#define DFF 1024
#define GH 40
#define GW 40
#define EPSV 1e-5f
#define QSCALE 0.17677669529663687f  // 1/sqrt(32)

// ---------------- scratch (device globals; no allocation) ----------------
static __device__ float g_t[LQ*CD];
static __device__ float g_qkin[LQ*CD];
static __device__ float g_q[LQ*CD];
static __device__ float g_k[LQ*CD];
static __device__ float g_v[LQ*CD];
static __device__ float g_attcat[LQ*512];
static __device__ float g_tgt[LQ*CD];
static __device__ float g_qv[LQ*2*CD];
static __device__ float g_idkv[LQ*264];
static __device__ float g_gK[LQ*CD];
static __device__ float g_gV[LQ*CD];
static __device__ float g_x[LQ*DFF];
static __device__ float g_x2[LQ*DFF];
static __device__ float g_stats[64];
static __device__ float g_wcat[256*512];
static __device__ float g_bcat[256];

// ---------------- LayerNorm (optionally + pos add) ----------------
__global__ __launch_bounds__(256) void ln_kernel(
    const float* __restrict__ x, const float* __restrict__ g, const float* __restrict__ b,
    float* __restrict__ y, const float* __restrict__ pos, float* __restrict__ qkout) {
  int l = blockIdx.x;
  int c = threadIdx.x;
  float v = x[(size_t)l*CD + c];
  float s = v, s2 = v*v;
  #pragma unroll
  for (int o = 16; o; o >>= 1) {
    s  += __shfl_xor_sync(0xffffffffu, s,  o);
    s2 += __shfl_xor_sync(0xffffffffu, s2, o);
  }
  __shared__ float sh[8], sh2[8], smv[2];
  int w = c >> 5, lane = c & 31;
  if (lane == 0) { sh[w] = s; sh2[w] = s2; }
  __syncthreads();
  if (c == 0) {
    float a = 0.f, a2 = 0.f;
    #pragma unroll
    for (int i = 0; i < 8; i++) { a += sh[i]; a2 += sh2[i]; }
    float mean = a * (1.0f/CD);
    float var  = a2 * (1.0f/CD) - mean*mean;
    smv[0] = mean; smv[1] = rsqrtf(var + EPSV);
  }
  __syncthreads();
  float out = (v - smv[0]) * smv[1] * g[c] + b[c];
  y[(size_t)l*CD + c] = out;
  if (qkout) qkout[(size_t)l*CD + c] = out + pos[(size_t)l*CD + c];
}

// ---------------- GEMM core: C[M,N] = A[M,K] @ B[N,K]^T + bias (+res) -------
// 64x64 tile, K-chunk 32, double-buffered smem, 256 threads, 4x4 microtile.
// Requires: M % 64 == 0, K % 32 == 0. N arbitrary (guarded).
__device__ __forceinline__ void gemm_body(
    const float* __restrict__ A, const float* __restrict__ B,
    const float* __restrict__ bias, const float* __restrict__ res,
    float* __restrict__ Cout, int M, int N, int K, int bm, int bn) {
  __shared__ float As[2][32][68];
  __shared__ float Bs[2][32][68];
  const int tid = threadIdx.x;
  const int tx = tid & 15, ty = tid >> 4;
  const int lr = tid >> 2;          // row within tile 0..63
  const int lc = (tid & 3) << 2;    // k offset 0,4,8,12
  float acc[4][4] = {};
  const int nk = K >> 5;

  float4 a0, a1, b0, b1;
  const bool bok = (bn + lr) < N;
  {
    const float* Ap = A + (size_t)(bm + lr)*K + lc;
    a0 = *(const float4*)(Ap);
    a1 = *(const float4*)(Ap + 16);
    const float* Bp = B + (size_t)(bn + lr)*K + lc;
    b0 = bok ? *(const float4*)(Bp)      : make_float4(0.f,0.f,0.f,0.f);
    b1 = bok ? *(const float4*)(Bp + 16) : make_float4(0.f,0.f,0.f,0.f);
  }
  // store chunk 0
  As[0][lc+0][lr]=a0.x; As[0][lc+1][lr]=a0.y; As[0][lc+2][lr]=a0.z; As[0][lc+3][lr]=a0.w;
  As[0][lc+16][lr]=a1.x; As[0][lc+17][lr]=a1.y; As[0][lc+18][lr]=a1.z; As[0][lc+19][lr]=a1.w;
  Bs[0][lc+0][lr]=b0.x; Bs[0][lc+1][lr]=b0.y; Bs[0][lc+2][lr]=b0.z; Bs[0][lc+3][lr]=b0.w;
  Bs[0][lc+16][lr]=b1.x; Bs[0][lc+17][lr]=b1.y; Bs[0][lc+18][lr]=b1.z; Bs[0][lc+19][lr]=b1.w;
  __syncthreads();

  for (int ch = 0; ch < nk; ch++) {
    const int buf = ch & 1;
    if (ch + 1 < nk) {
      const int k0 = (ch + 1) << 5;
      const float* Ap = A + (size_t)(bm + lr)*K + k0 + lc;
      a0 = *(const float4*)(Ap);
      a1 = *(const float4*)(Ap + 16);
      const float* Bp = B + (size_t)(bn + lr)*K + k0 + lc;
      b0 = bok ? *(const float4*)(Bp)      : make_float4(0.f,0.f,0.f,0.f);
      b1 = bok ? *(const float4*)(Bp + 16) : make_float4(0.f,0.f,0.f,0.f);
    }
    #pragma unroll
    for (int kk = 0; kk < 32; kk++) {
      float4 a4 = *(const float4*)&As[buf][kk][ty*4];
      float4 b4 = *(const float4*)&Bs[buf][kk][tx*4];
      float av[4] = {a4.x, a4.y, a4.z, a4.w};
      float bw[4] = {b4.x, b4.y, b4.z, b4.w};
      #pragma unroll
      for (int i = 0; i < 4; i++)
        #pragma unroll
        for (int j = 0; j < 4; j++)
          acc[i][j] = fmaf(av[i], bw[j], acc[i][j]);
    }
    if (ch + 1 < nk) {
      const int nb = buf ^ 1;
      As[nb][lc+0][lr]=a0.x; As[nb][lc+1][lr]=a0.y; As[nb][lc+2][lr]=a0.z; As[nb][lc+3][lr]=a0.w;
      As[nb][lc+16][lr]=a1.x; As[nb][lc+17][lr]=a1.y; As[nb][lc+18][lr]=a1.z; As[nb][lc+19][lr]=a1.w;
      Bs[nb][lc+0][lr]=b0.x; Bs[nb][lc+1][lr]=b0.y; Bs[nb][lc+2][lr]=b0.z; Bs[nb][lc+3][lr]=b0.w;
      Bs[nb][lc+16][lr]=b1.x; Bs[nb][lc+17][lr]=b1.y; Bs[nb][lc+18][lr]=b1.z; Bs[nb][lc+19][lr]=b1.w;
      __syncthreads();
    }
  }
  #pragma unroll
  for (int i = 0; i < 4; i++) {
    int m = bm + ty*4 + i;
    #pragma unroll
    for (int j = 0; j < 4; j++) {
      int n = bn + tx*4 + j;
      if (n < N) {
        float val = acc[i][j] + bias[n];
        if (res) val += res[(size_t)m*N + n];
        Cout[(size_t)m*N + n] = val;
      }
    }
  }
}

__global__ __launch_bounds__(256) void gemm_nt(
    const float* __restrict__ A, const float* __restrict__ B,
    const float* __restrict__ bias, const float* __restrict__ res,
    float* __restrict__ Cout, int M, int N, int K) {
  gemm_body(A, B, bias, res, Cout, M, N, K, blockIdx.y*64, blockIdx.x*64);
}

// fused q/k/v projections (z selects operand set)
__global__ __launch_bounds__(256) void gemm_qkv(
    const float* __restrict__ qkin, const float* __restrict__ t,
    const float* __restrict__ wq, const float* __restrict__ wk, const float* __restrict__ wv,
    const float* __restrict__ bq, const float* __restrict__ bk, const float* __restrict__ bv,
    float* __restrict__ q, float* __restrict__ k, float* __restrict__ v) {
  int z = blockIdx.z;
  const float* A = (z == 2) ? t : qkin;
  const float* B = (z == 0) ? wq : (z == 1 ? wk : wv);
  const float* bias = (z == 0) ? bq : (z == 1 ? bk : bv);
  float* C = (z == 0) ? q : (z == 1 ? k : v);
  gemm_body(A, B, bias, nullptr, C, LQ, CD, CD, blockIdx.y*64, blockIdx.x*64);
}

// pack [lt_wo | st_wo] into (256,512) + combined bias
__global__ __launch_bounds__(256) void pack_w(
    const float* __restrict__ lt, const float* __restrict__ st,
    const float* __restrict__ ltb, const float* __restrict__ stb,
    float* __restrict__ wcat, float* __restrict__ bcat) {
  int idx = blockIdx.x * 256 + threadIdx.x;
  int nrow = idx >> 9, k = idx & 511;
  wcat[idx] = (k < 256) ? lt[nrow*256 + k] : st[nrow*256 + k - 256];
  if (idx < 256) bcat[idx] = ltb[idx] + stb[idx];
}

// ---------------- Fused full attention (flash-style, online softmax) --------
// grid (25 q-tiles, 8 heads), 256 threads. O written with row stride ostride.
__global__ __launch_bounds__(256) void attn_kernel(
    const float* __restrict__ Q, const float* __restrict__ Kp,
    const float* __restrict__ Vp, float* __restrict__ O, int ostride, int ooff) {
  __shared__ float Qs[HD][64];
  __shared__ float Ks[HD][64];
  __shared__ float Vs[64][34];
  __shared__ float Ps[64][68];
  const int h = blockIdx.y;
  const int q0 = blockIdx.x * 64;
  const int tid = threadIdx.x;
  const int tx = tid & 15, ty = tid >> 4;

  #pragma unroll
  for (int it = 0; it < 2; it++) {
    int e = tid + it*256;
    int r = e >> 3, d4 = (e & 7) << 2;
    const float4 qv = *(const float4*)(Q + (size_t)(q0 + r)*CD + h*HD + d4);
    Qs[d4+0][r] = qv.x * QSCALE; Qs[d4+1][r] = qv.y * QSCALE;
    Qs[d4+2][r] = qv.z * QSCALE; Qs[d4+3][r] = qv.w * QSCALE;
  }
  float m_i[4], l_i[4], oa[4][2];
  #pragma unroll
  for (int i = 0; i < 4; i++) { m_i[i] = -1e30f; l_i[i] = 0.f; oa[i][0] = 0.f; oa[i][1] = 0.f; }

  for (int k0 = 0; k0 < LQ; k0 += 64) {
    #pragma unroll
    for (int it = 0; it < 2; it++) {
      int e = tid + it*256;
      int r = e >> 3, d4 = (e & 7) << 2;
      const float4 kv = *(const float4*)(Kp + (size_t)(k0 + r)*CD + h*HD + d4);
      Ks[d4+0][r] = kv.x; Ks[d4+1][r] = kv.y; Ks[d4+2][r] = kv.z; Ks[d4+3][r] = kv.w;
      const float4 vv = *(const float4*)(Vp + (size_t)(k0 + r)*CD + h*HD + d4);
      Vs[r][d4+0] = vv.x; Vs[r][d4+1] = vv.y; Vs[r][d4+2] = vv.z; Vs[r][d4+3] = vv.w;
    }
    __syncthreads();
    float s[4][4] = {};
    #pragma unroll
    for (int d = 0; d < HD; d++) {
      float4 a4 = *(const float4*)&Qs[d][ty*4];
      float4 b4 = *(const float4*)&Ks[d][tx*4];
      float av[4] = {a4.x, a4.y, a4.z, a4.w};
      float bw[4] = {b4.x, b4.y, b4.z, b4.w};
      #pragma unroll
      for (int i = 0; i < 4; i++)
        #pragma unroll
        for (int j = 0; j < 4; j++)
          s[i][j] = fmaf(av[i], bw[j], s[i][j]);
    }
    #pragma unroll
    for (int i = 0; i < 4; i++) {
      float rm = fmaxf(fmaxf(s[i][0], s[i][1]), fmaxf(s[i][2], s[i][3]));
      #pragma unroll
      for (int o = 8; o; o >>= 1) rm = fmaxf(rm, __shfl_xor_sync(0xffffffffu, rm, o));
      float mnew = fmaxf(m_i[i], rm);
      float alpha = __expf(m_i[i] - mnew);
      float rs = 0.f;
      #pragma unroll
      for (int j = 0; j < 4; j++) {
        float p = __expf(s[i][j] - mnew);
        Ps[ty*4+i][tx*4+j] = p;
        rs += p;
      }
      #pragma unroll
      for (int o = 8; o; o >>= 1) rs += __shfl_xor_sync(0xffffffffu, rs, o);
      l_i[i] = l_i[i]*alpha + rs;
      m_i[i] = mnew;
      oa[i][0] *= alpha; oa[i][1] *= alpha;
    }
    __syncthreads();
    #pragma unroll 4
    for (int k4 = 0; k4 < 16; k4++) {
      float4 p4[4];
      #pragma unroll
      for (int i = 0; i < 4; i++) p4[i] = *(const float4*)&Ps[ty*4+i][k4*4];
      #pragma unroll
      for (int t = 0; t < 4; t++) {
        float2 v2 = *(const float2*)&Vs[k4*4+t][tx*2];
        float pi[4] = { (&p4[0].x)[t], (&p4[1].x)[t], (&p4[2].x)[t], (&p4[3].x)[t] };
        #pragma unroll
        for (int i = 0; i < 4; i++) {
          oa[i][0] = fmaf(pi[i], v2.x, oa[i][0]);
          oa[i][1] = fmaf(pi[i], v2.y, oa[i][1]);
        }
      }
    }
    __syncthreads();
  }
  #pragma unroll
  for (int i = 0; i < 4; i++) {
    float inv = 1.f / l_i[i];
    int row = q0 + ty*4 + i;
    O[(size_t)row*ostride + ooff + h*HD + tx*2+0] = oa[i][0]*inv;
    O[(size_t)row*ostride + ooff + h*HD + tx*2+1] = oa[i][1]*inv;
  }
}

// ---------------- curr_Q / global_K / global_V construction ----------------
__global__ __launch_bounds__(256) void make_kv_kernel(
    const float* __restrict__ qv, const float* __restrict__ idkv,
    float* __restrict__ q, float* __restrict__ gK, float* __restrict__ gV) {
  int l = blockIdx.x, c = threadIdx.x;
  float cq  = qv[(size_t)l*512 + c];
  float cv  = qv[(size_t)l*512 + 256 + c];
  float idk = idkv[(size_t)l*264 + (c >> 5)];
  float idv = idkv[(size_t)l*264 + 8 + c];
  q [(size_t)l*CD + c] = cq;
  gK[(size_t)l*CD + c] = cq * (1.f + tanhf(idk));
  gV[(size_t)l*CD + c] = cv + idv;
}

// ---------------- Local 15x15 window attention ----------------
// grid LQ blocks, 8 warps (one per head). Phase A: lane = neighbor.
__global__ __launch_bounds__(256) void local_attn_kernel(
    const float* __restrict__ Q, const float* __restrict__ Kp,
    const float* __restrict__ Vp, float* __restrict__ O, int ostride, int ooff) {
  __shared__ float p_sh[8][232];
  int n = blockIdx.x;
  int r = n / GW, c = n % GW;
  int h = threadIdx.x >> 5, lane = threadIdx.x & 31;

  const float* qp = Q + (size_t)n*CD + h*HD;
  float4 qreg[8];
  #pragma unroll
  for (int i = 0; i < 8; i++) {
    qreg[i] = *(const float4*)(qp + i*4);
    qreg[i].x *= QSCALE; qreg[i].y *= QSCALE; qreg[i].z *= QSCALE; qreg[i].w *= QSCALE;
  }
  int i0 = max(7 - r, 0), i1 = min(GH + 7 - r, 15);
  int j0 = max(7 - c, 0), j1 = min(GW + 7 - c, 15);

  // phase A: logits, each lane owns whole neighbor dot products
  for (int w = lane; w < 225; w += 32) {
    int wi = w / 15, wj = w - wi*15;
    float logit = -1e30f;
    if (wi >= i0 && wi < i1 && wj >= j0 && wj < j1) {
      const float* kp = Kp + (size_t)((r+wi-7)*GW + (c+wj-7))*CD + h*HD;
      float acc = 0.f;
      #pragma unroll
      for (int i4 = 0; i4 < 8; i4++) {
        float4 kv = *(const float4*)(kp + i4*4);
        acc = fmaf(qreg[i4].x, kv.x, acc);
        acc = fmaf(qreg[i4].y, kv.y, acc);
        acc = fmaf(qreg[i4].z, kv.z, acc);
        acc = fmaf(qreg[i4].w, kv.w, acc);
      }
      logit = acc;
    }
    p_sh[h][w] = logit;
  }
  __syncwarp();
  // softmax over 225
  float m = -1e30f;
  for (int ww = lane; ww < 225; ww += 32) m = fmaxf(m, p_sh[h][ww]);
  #pragma unroll
  for (int o = 16; o; o >>= 1) m = fmaxf(m, __shfl_xor_sync(0xffffffffu, m, o));
  float ssum = 0.f;
  for (int ww = lane; ww < 225; ww += 32) {
    float p = __expf(p_sh[h][ww] - m);
    p_sh[h][ww] = p;
    ssum += p;
  }
  #pragma unroll
  for (int o = 16; o; o >>= 1) ssum += __shfl_xor_sync(0xffffffffu, ssum, o);
  float inv = 1.f / ssum;
  __syncwarp();
  // phase B: lane = dim, iterate valid window only
  float oacc = 0.f;
  for (int wi = i0; wi < i1; wi++) {
    const float* vrow = Vp + (size_t)((r+wi-7)*GW + (c+j0-7))*CD + h*HD + lane;
    #pragma unroll 3
    for (int wj = j0; wj < j1; wj++, vrow += CD)
      oacc = fmaf(p_sh[h][wi*15+wj], *vrow, oacc);
  }
  O[(size_t)n*ostride + ooff + h*HD + lane] = oacc * inv;
}

// ---------------- GroupNorm stats ----------------
__global__ __launch_bounds__(1024) void gn_stats_kernel(
    const float* __restrict__ x, float* __restrict__ stats) {
  int g = blockIdx.x;
  float s = 0.f, s2 = 0.f;
  for (int idx = threadIdx.x; idx < LQ*32; idx += 1024) {
    int l = idx >> 5, ch = idx & 31;
    float v = x[(size_t)l*DFF + g*32 + ch];
    s += v; s2 += v*v;
  }
  #pragma unroll
  for (int o = 16; o; o >>= 1) {
    s  += __shfl_xor_sync(0xffffffffu, s,  o);
    s2 += __shfl_xor_sync(0xffffffffu, s2, o);
  }
  __shared__ float sh[32], sh2[32];
  int w = threadIdx.x >> 5, lane = threadIdx.x & 31;
  if (lane == 0) { sh[w] = s; sh2[w] = s2; }
  __syncthreads();
  if (w == 0) {
    s = sh[lane]; s2 = sh2[lane];
    #pragma unroll
    for (int o = 16; o; o >>= 1) {
      s  += __shfl_xor_sync(0xffffffffu, s,  o);
      s2 += __shfl_xor_sync(0xffffffffu, s2, o);
    }
    if (lane == 0) {
      const float invn = 1.f / (LQ * 32.f);
      float mean = s * invn;
      float var  = s2 * invn - mean*mean;
      stats[g*2]   = mean;
      stats[g*2+1] = rsqrtf(var + EPSV);
    }
  }
}

// ---------------- GN apply + exact GELU ----------------
__global__ __launch_bounds__(256) void gn_gelu_kernel(
    const float* __restrict__ x, const float* __restrict__ gg, const float* __restrict__ gb,
    const float* __restrict__ stats, float* __restrict__ y) {
  int idx = blockIdx.x * 256 + threadIdx.x;
  int ch = idx & (DFF-1);
  int g = ch >> 5;
  float v = (x[idx] - stats[g*2]) * stats[g*2+1] * gg[ch] + gb[ch];
  y[idx] = 0.5f * v * (1.f + erff(v * 0.70710678118654752f));
}

// ---------------- 5x5 depthwise conv, pad 2 ----------------
__global__ __launch_bounds__(256) void dwconv_kernel(
    const float* __restrict__ x, const float* __restrict__ kern, float* __restrict__ y) {
  __shared__ float tile[12][12][32];
  __shared__ float kw[32][25];
  int tid = threadIdx.x;
  int ch0 = blockIdx.z * 32;
  int r0 = blockIdx.y * 8 - 2, c0 = blockIdx.x * 8 - 2;
  for (int e = tid; e < 12*12*32; e += 256) {
    int ch = e & 31;
    int sp = e >> 5;
    int ri = sp / 12, ci = sp % 12;
    int rr = r0 + ri, cc = c0 + ci;
    float v = 0.f;
    if ((unsigned)rr < (unsigned)GH && (unsigned)cc < (unsigned)GW)
      v = x[(size_t)(rr*GW + cc)*DFF + ch0 + ch];
    tile[ri][ci][ch] = v;
  }
  for (int e = tid; e < 32*25; e += 256)
    kw[e/25][e%25] = kern[(size_t)(ch0 + e/25)*25 + e%25];
  __syncthreads();
  for (int e = tid; e < 8*8*32; e += 256) {
    int ch = e & 31;
    int sp = e >> 5;
    int ri = sp >> 3, ci = sp & 7;
    float acc = 0.f;
    #pragma unroll
    for (int i = 0; i < 5; i++)
      #pragma unroll
      for (int j = 0; j < 5; j++)
        acc = fmaf(tile[ri+i][ci+j][ch], kw[ch][i*5+j], acc);
    int rr = blockIdx.y*8 + ri, cc = blockIdx.x*8 + ci;
    y[(size_t)(rr*GW + cc)*DFF + ch0 + ch] = acc;
  }
}

// ---------------- launcher ----------------
extern "C" void kernel_launch(void* const* d_in, const int* in_sizes, int n_in,
                              void* d_out, int out_size) {
  const float* in_tgt   = (const float*)d_in[0];
  const float* id_emb   = (const float*)d_in[1];
  const float* self_pos = (const float*)d_in[2];
  const float* ln1_g = (const float*)d_in[3];
  const float* ln1_b = (const float*)d_in[4];
  const float* sa_wq = (const float*)d_in[5];
  const float* sa_bq = (const float*)d_in[6];
  const float* sa_wk = (const float*)d_in[7];
  const float* sa_bk = (const float*)d_in[8];
  const float* sa_wv = (const float*)d_in[9];
  const float* sa_bv = (const float*)d_in[10];
  const float* sa_wo = (const float*)d_in[11];
  const float* sa_bo = (const float*)d_in[12];
  const float* ln2_g = (const float*)d_in[13];
  const float* ln2_b = (const float*)d_in[14];
  const float* w_qv = (const float*)d_in[15];
  const float* b_qv = (const float*)d_in[16];
  const float* w_id = (const float*)d_in[17];
  const float* b_id = (const float*)d_in[18];
  const float* lt_wo = (const float*)d_in[19];
  const float* lt_bo = (const float*)d_in[20];
  const float* st_wo = (const float*)d_in[21];
  const float* st_bo = (const float*)d_in[22];
  const float* ln3_g = (const float*)d_in[23];
  const float* ln3_b = (const float*)d_in[24];
  const float* w1 = (const float*)d_in[25];
  const float* b1 = (const float*)d_in[26];
  const float* gn_g = (const float*)d_in[27];
  const float* gn_b = (const float*)d_in[28];
  const float* dw_k = (const float*)d_in[29];
  const float* w2 = (const float*)d_in[30];
  const float* b2 = (const float*)d_in[31];
  float* out = (float*)d_out;

  float *t, *qkin, *q, *k, *v, *attcat, *tgtb, *qv, *idkv, *gK, *gV, *x, *x2, *stats, *wcat, *bcat;
  cudaGetSymbolAddress((void**)&t,      g_t);
  cudaGetSymbolAddress((void**)&qkin,   g_qkin);
  cudaGetSymbolAddress((void**)&q,      g_q);
  cudaGetSymbolAddress((void**)&k,      g_k);
  cudaGetSymbolAddress((void**)&v,      g_v);
  cudaGetSymbolAddress((void**)&attcat, g_attcat);
  cudaGetSymbolAddress((void**)&tgtb,   g_tgt);
  cudaGetSymbolAddress((void**)&qv,     g_qv);
  cudaGetSymbolAddress((void**)&idkv,   g_idkv);
  cudaGetSymbolAddress((void**)&gK,     g_gK);
  cudaGetSymbolAddress((void**)&gV,     g_gV);
  cudaGetSymbolAddress((void**)&x,      g_x);
  cudaGetSymbolAddress((void**)&x2,     g_x2);
  cudaGetSymbolAddress((void**)&stats,  g_stats);
  cudaGetSymbolAddress((void**)&wcat,   g_wcat);
  cudaGetSymbolAddress((void**)&bcat,   g_bcat);

  dim3 g66(4, 25);         // N=256 GEMMs
  dim3 gQKV(4, 25, 3);
  dim3 gAttn(25, 8);

  // independent prep
  pack_w<<<512,256>>>(lt_wo, st_wo, lt_bo, st_bo, wcat, bcat);
  cudaMemcpyAsync(tgtb, in_tgt, sizeof(float)*LQ*CD, cudaMemcpyDeviceToDevice, 0);

  // --- self attention ---
  ln_kernel<<<LQ,256>>>(in_tgt, ln1_g, ln1_b, t, self_pos, qkin);
  gemm_qkv<<<gQKV,256>>>(qkin, t, sa_wq, sa_wk, sa_wv, sa_bq, sa_bk, sa_bv, q, k, v);
  attn_kernel<<<gAttn,256>>>(q, k, v, attcat, 256, 0);
  gemm_nt<<<g66,256>>>(attcat, sa_wo, sa_bo, tgtb, tgtb, LQ, CD, CD);

  // --- long/short term attention ---
  ln_kernel<<<LQ,256>>>(tgtb, ln2_g, ln2_b, t, nullptr, nullptr);
  gemm_nt<<<dim3(8,25),256>>>(t, w_qv, b_qv, nullptr, qv, LQ, 512, CD);
  gemm_nt<<<dim3(5,25),256>>>(id_emb, w_id, b_id, nullptr, idkv, LQ, 264, CD);
  make_kv_kernel<<<LQ,256>>>(qv, idkv, q, gK, gV);
  attn_kernel<<<gAttn,256>>>(q, gK, gV, attcat, 512, 0);
  local_attn_kernel<<<LQ,256>>>(q, gK, gV, attcat, 512, 256);
  gemm_nt<<<g66,256>>>(attcat, wcat, bcat, tgtb, tgtb, LQ, CD, 512);

  // --- MLP: LN -> w1 -> GN -> GELU -> dwconv -> w2 ---
  ln_kernel<<<LQ,256>>>(tgtb, ln3_g, ln3_b, t, nullptr, nullptr);
  gemm_nt<<<dim3(16,25),256>>>(t, w1, b1, nullptr, x, LQ, DFF, CD);
  gn_stats_kernel<<<32,1024>>>(x, stats);
  gn_gelu_kernel<<<(LQ*DFF)/256,256>>>(x, gn_g, gn_b, stats, x2);
  dwconv_kernel<<<dim3(5,5,32),256>>>(x2, dw_k, x);
  gemm_nt<<<g66,256>>>(x, w2, b2, tgtb, out, LQ, CD, DFF);
}

// round 3
// speedup vs baseline: 1.3753x; 1.1647x over previous
#include <cuda_runtime.h>
#include <math.h>

#define LQ 1600
#define CD 256
#define NHD 8
#define HD 32
#define DFF 1024
#define GH 40
#define GW 40
#define EPSV 1e-5f
#define QSCALE 0.17677669529663687f  // 1/sqrt(32)

typedef unsigned long long ull;

// ---------------- f32x2 packed math helpers ----------------
__device__ __forceinline__ ull pk2(float x, float y) {
  ull r; asm("mov.b64 %0, {%1, %2};" : "=l"(r) : "f"(x), "f"(y)); return r;
}
__device__ __forceinline__ float2 up2(ull v) {
  float lo, hi; asm("mov.b64 {%0, %1}, %2;" : "=f"(lo), "=f"(hi) : "l"(v));
  return make_float2(lo, hi);
}
__device__ __forceinline__ void fma2(ull &d, ull a, ull b) {
  asm("fma.rn.f32x2 %0, %1, %2, %0;" : "+l"(d) : "l"(a), "l"(b));
}
__device__ __forceinline__ void mul2(ull &d, ull a) {
  asm("mul.rn.f32x2 %0, %0, %1;" : "+l"(d) : "l"(a));
}

// ---------------- scratch (device globals; no allocation) ----------------
static __device__ float g_t[LQ*CD];
static __device__ float g_qkin[LQ*CD];
static __device__ float g_q[LQ*CD];
static __device__ float g_k[LQ*CD];
static __device__ float g_v[LQ*CD];
static __device__ float g_attcat[LQ*512];
static __device__ float g_tgt[LQ*CD];
static __device__ float g_qv[LQ*2*CD];
static __device__ float g_idkv[LQ*264];
static __device__ float g_gK[LQ*CD];
static __device__ float g_gV[LQ*CD];
static __device__ float g_x[LQ*DFF];
static __device__ float g_x2[LQ*DFF];
static __device__ float g_stats[64];
static __device__ float g_wcat[256*512];
static __device__ float g_bcat[256];
static __device__ float g_opart[2*LQ*CD];
static __device__ float2 g_ml[2*LQ*NHD];

// ---------------- LayerNorm (optionally + pos add) ----------------
__global__ __launch_bounds__(256) void ln_kernel(
    const float* __restrict__ x, const float* __restrict__ g, const float* __restrict__ b,
    float* __restrict__ y, const float* __restrict__ pos, float* __restrict__ qkout) {
  int l = blockIdx.x;
  int c = threadIdx.x;
  float v = x[(size_t)l*CD + c];
  float s = v, s2 = v*v;
  #pragma unroll
  for (int o = 16; o; o >>= 1) {
    s  += __shfl_xor_sync(0xffffffffu, s,  o);
    s2 += __shfl_xor_sync(0xffffffffu, s2, o);
  }
  __shared__ float sh[8], sh2[8], smv[2];
  int w = c >> 5, lane = c & 31;
  if (lane == 0) { sh[w] = s; sh2[w] = s2; }
  __syncthreads();
  if (c == 0) {
    float a = 0.f, a2 = 0.f;
    #pragma unroll
    for (int i = 0; i < 8; i++) { a += sh[i]; a2 += sh2[i]; }
    float mean = a * (1.0f/CD);
    float var  = a2 * (1.0f/CD) - mean*mean;
    smv[0] = mean; smv[1] = rsqrtf(var + EPSV);
  }
  __syncthreads();
  float out = (v - smv[0]) * smv[1] * g[c] + b[c];
  y[(size_t)l*CD + c] = out;
  if (qkout) qkout[(size_t)l*CD + c] = out + pos[(size_t)l*CD + c];
}

// ---------------- GEMM core (f32x2): C[M,N]=A[M,K]@B[N,K]^T + bias (+res) ---
// 64x64 tile, K-chunk 32, double-buffered smem, 256 threads, 4x4 microtile.
__device__ __forceinline__ void gemm_body(
    const float* __restrict__ A, const float* __restrict__ B,
    const float* __restrict__ bias, const float* __restrict__ res,
    float* __restrict__ Cout, int M, int N, int K, int bm, int bn) {
  __shared__ float As[2][32][68];
  __shared__ float Bs[2][32][68];
  const int tid = threadIdx.x;
  const int tx = tid & 15, ty = tid >> 4;
  const int lr = tid >> 2;
  const int lc = (tid & 3) << 2;
  ull acc2[4][2] = {};
  const int nk = K >> 5;

  float4 a0, a1, b0, b1;
  const bool bok = (bn + lr) < N;
  {
    const float* Ap = A + (size_t)(bm + lr)*K + lc;
    a0 = *(const float4*)(Ap);
    a1 = *(const float4*)(Ap + 16);
    const float* Bp = B + (size_t)(bn + lr)*K + lc;
    b0 = bok ? *(const float4*)(Bp)      : make_float4(0.f,0.f,0.f,0.f);
    b1 = bok ? *(const float4*)(Bp + 16) : make_float4(0.f,0.f,0.f,0.f);
  }
  As[0][lc+0][lr]=a0.x; As[0][lc+1][lr]=a0.y; As[0][lc+2][lr]=a0.z; As[0][lc+3][lr]=a0.w;
  As[0][lc+16][lr]=a1.x; As[0][lc+17][lr]=a1.y; As[0][lc+18][lr]=a1.z; As[0][lc+19][lr]=a1.w;
  Bs[0][lc+0][lr]=b0.x; Bs[0][lc+1][lr]=b0.y; Bs[0][lc+2][lr]=b0.z; Bs[0][lc+3][lr]=b0.w;
  Bs[0][lc+16][lr]=b1.x; Bs[0][lc+17][lr]=b1.y; Bs[0][lc+18][lr]=b1.z; Bs[0][lc+19][lr]=b1.w;
  __syncthreads();

  for (int ch = 0; ch < nk; ch++) {
    const int buf = ch & 1;
    if (ch + 1 < nk) {
      const int k0 = (ch + 1) << 5;
      const float* Ap = A + (size_t)(bm + lr)*K + k0 + lc;
      a0 = *(const float4*)(Ap);
      a1 = *(const float4*)(Ap + 16);
      const float* Bp = B + (size_t)(bn + lr)*K + k0 + lc;
      b0 = bok ? *(const float4*)(Bp)      : make_float4(0.f,0.f,0.f,0.f);
      b1 = bok ? *(const float4*)(Bp + 16) : make_float4(0.f,0.f,0.f,0.f);
    }
    #pragma unroll
    for (int kk = 0; kk < 32; kk++) {
      float4 a4 = *(const float4*)&As[buf][kk][ty*4];
      const ull* bp = (const ull*)&Bs[buf][kk][tx*4];
      ull b01 = bp[0], b23 = bp[1];
      float av[4] = {a4.x, a4.y, a4.z, a4.w};
      #pragma unroll
      for (int i = 0; i < 4; i++) {
        ull aa = pk2(av[i], av[i]);
        fma2(acc2[i][0], aa, b01);
        fma2(acc2[i][1], aa, b23);
      }
    }
    if (ch + 1 < nk) {
      const int nb = buf ^ 1;
      As[nb][lc+0][lr]=a0.x; As[nb][lc+1][lr]=a0.y; As[nb][lc+2][lr]=a0.z; As[nb][lc+3][lr]=a0.w;
      As[nb][lc+16][lr]=a1.x; As[nb][lc+17][lr]=a1.y; As[nb][lc+18][lr]=a1.z; As[nb][lc+19][lr]=a1.w;
      Bs[nb][lc+0][lr]=b0.x; Bs[nb][lc+1][lr]=b0.y; Bs[nb][lc+2][lr]=b0.z; Bs[nb][lc+3][lr]=b0.w;
      Bs[nb][lc+16][lr]=b1.x; Bs[nb][lc+17][lr]=b1.y; Bs[nb][lc+18][lr]=b1.z; Bs[nb][lc+19][lr]=b1.w;
      __syncthreads();
    }
  }
  #pragma unroll
  for (int i = 0; i < 4; i++) {
    int m = bm + ty*4 + i;
    float2 v01 = up2(acc2[i][0]);
    float2 v23 = up2(acc2[i][1]);
    float vals[4] = {v01.x, v01.y, v23.x, v23.y};
    #pragma unroll
    for (int j = 0; j < 4; j++) {
      int n = bn + tx*4 + j;
      if (n < N) {
        float val = vals[j] + bias[n];
        if (res) val += res[(size_t)m*N + n];
        Cout[(size_t)m*N + n] = val;
      }
    }
  }
}

__global__ __launch_bounds__(256) void gemm_nt(
    const float* __restrict__ A, const float* __restrict__ B,
    const float* __restrict__ bias, const float* __restrict__ res,
    float* __restrict__ Cout, int M, int N, int K) {
  gemm_body(A, B, bias, res, Cout, M, N, K, blockIdx.y*64, blockIdx.x*64);
}

__global__ __launch_bounds__(256) void gemm_qkv(
    const float* __restrict__ qkin, const float* __restrict__ t,
    const float* __restrict__ wq, const float* __restrict__ wk, const float* __restrict__ wv,
    const float* __restrict__ bq, const float* __restrict__ bk, const float* __restrict__ bv,
    float* __restrict__ q, float* __restrict__ k, float* __restrict__ v) {
  int z = blockIdx.z;
  const float* A = (z == 2) ? t : qkin;
  const float* B = (z == 0) ? wq : (z == 1 ? wk : wv);
  const float* bias = (z == 0) ? bq : (z == 1 ? bk : bv);
  float* C = (z == 0) ? q : (z == 1 ? k : v);
  gemm_body(A, B, bias, nullptr, C, LQ, CD, CD, blockIdx.y*64, blockIdx.x*64);
}

// pack [lt_wo | st_wo] into (256,512) + combined bias
__global__ __launch_bounds__(256) void pack_w(
    const float* __restrict__ lt, const float* __restrict__ st,
    const float* __restrict__ ltb, const float* __restrict__ stb,
    float* __restrict__ wcat, float* __restrict__ bcat) {
  int idx = blockIdx.x * 256 + threadIdx.x;
  int nrow = idx >> 9, k = idx & 511;
  wcat[idx] = (k < 256) ? lt[nrow*256 + k] : st[nrow*256 + k - 256];
  if (idx < 256) bcat[idx] = ltb[idx] + stb[idx];
}

// ---------------- Fused full attention, split-KV x2, f32x2 math -------------
// grid (25 q-tiles, 8 heads, 2 kv-splits), 256 threads.
// Writes UNNORMALIZED partial O and per-row (m, l).
__global__ __launch_bounds__(256) void attn_kernel(
    const float* __restrict__ Q, const float* __restrict__ Kp,
    const float* __restrict__ Vp, float* __restrict__ Opart, float2* __restrict__ ml) {
  __shared__ float Qs[HD][64];
  __shared__ float Ks[HD][64];
  __shared__ float Vs[64][34];
  __shared__ float Ps[64][68];
  const int h = blockIdx.y;
  const int z = blockIdx.z;
  const int q0 = blockIdx.x * 64;
  const int kt0 = z ? 13 : 0, kt1 = z ? 25 : 13;
  const int tid = threadIdx.x;
  const int tx = tid & 15, ty = tid >> 4;

  #pragma unroll
  for (int it = 0; it < 2; it++) {
    int e = tid + it*256;
    int r = e >> 3, d4 = (e & 7) << 2;
    const float4 qv = *(const float4*)(Q + (size_t)(q0 + r)*CD + h*HD + d4);
    Qs[d4+0][r] = qv.x * QSCALE; Qs[d4+1][r] = qv.y * QSCALE;
    Qs[d4+2][r] = qv.z * QSCALE; Qs[d4+3][r] = qv.w * QSCALE;
  }
  float m_i[4], l_i[4];
  ull oa2[4];
  #pragma unroll
  for (int i = 0; i < 4; i++) { m_i[i] = -1e30f; l_i[i] = 0.f; oa2[i] = 0ull; }

  for (int kt = kt0; kt < kt1; kt++) {
    const int k0 = kt * 64;
    #pragma unroll
    for (int it = 0; it < 2; it++) {
      int e = tid + it*256;
      int r = e >> 3, d4 = (e & 7) << 2;
      const float4 kv = *(const float4*)(Kp + (size_t)(k0 + r)*CD + h*HD + d4);
      Ks[d4+0][r] = kv.x; Ks[d4+1][r] = kv.y; Ks[d4+2][r] = kv.z; Ks[d4+3][r] = kv.w;
      const float4 vv = *(const float4*)(Vp + (size_t)(k0 + r)*CD + h*HD + d4);
      Vs[r][d4+0] = vv.x; Vs[r][d4+1] = vv.y; Vs[r][d4+2] = vv.z; Vs[r][d4+3] = vv.w;
    }
    __syncthreads();
    // --- QK^T: s2[i][jp] packed pairs over j ---
    ull s2[4][2] = {};
    #pragma unroll
    for (int d = 0; d < HD; d++) {
      float4 a4 = *(const float4*)&Qs[d][ty*4];
      const ull* bp = (const ull*)&Ks[d][tx*4];
      ull b01 = bp[0], b23 = bp[1];
      float av[4] = {a4.x, a4.y, a4.z, a4.w};
      #pragma unroll
      for (int i = 0; i < 4; i++) {
        ull aa = pk2(av[i], av[i]);
        fma2(s2[i][0], aa, b01);
        fma2(s2[i][1], aa, b23);
      }
    }
    // --- online softmax ---
    #pragma unroll
    for (int i = 0; i < 4; i++) {
      float2 s01 = up2(s2[i][0]);
      float2 s23 = up2(s2[i][1]);
      float sv[4] = {s01.x, s01.y, s23.x, s23.y};
      float rm = fmaxf(fmaxf(sv[0], sv[1]), fmaxf(sv[2], sv[3]));
      #pragma unroll
      for (int o = 8; o; o >>= 1) rm = fmaxf(rm, __shfl_xor_sync(0xffffffffu, rm, o));
      float mnew = fmaxf(m_i[i], rm);
      float alpha = __expf(m_i[i] - mnew);
      float rs = 0.f;
      #pragma unroll
      for (int j = 0; j < 4; j++) {
        float p = __expf(sv[j] - mnew);
        Ps[ty*4+i][tx*4+j] = p;
        rs += p;
      }
      #pragma unroll
      for (int o = 8; o; o >>= 1) rs += __shfl_xor_sync(0xffffffffu, rs, o);
      l_i[i] = l_i[i]*alpha + rs;
      m_i[i] = mnew;
      mul2(oa2[i], pk2(alpha, alpha));
    }
    __syncthreads();
    // --- P @ V ---
    #pragma unroll 4
    for (int k4 = 0; k4 < 16; k4++) {
      float4 p4[4];
      #pragma unroll
      for (int i = 0; i < 4; i++) p4[i] = *(const float4*)&Ps[ty*4+i][k4*4];
      #pragma unroll
      for (int t = 0; t < 4; t++) {
        ull v2 = *(const ull*)&Vs[k4*4+t][tx*2];
        float pi[4] = { (&p4[0].x)[t], (&p4[1].x)[t], (&p4[2].x)[t], (&p4[3].x)[t] };
        #pragma unroll
        for (int i = 0; i < 4; i++)
          fma2(oa2[i], pk2(pi[i], pi[i]), v2);
      }
    }
    __syncthreads();
  }
  #pragma unroll
  for (int i = 0; i < 4; i++) {
    int row = q0 + ty*4 + i;
    float2 o2 = up2(oa2[i]);
    Opart[((size_t)z*LQ + row)*CD + h*HD + tx*2+0] = o2.x;
    Opart[((size_t)z*LQ + row)*CD + h*HD + tx*2+1] = o2.y;
    if (tx == 0) ml[(z*LQ + row)*NHD + h] = make_float2(m_i[i], l_i[i]);
  }
}

// merge the 2 kv-splits
__global__ __launch_bounds__(256) void attn_merge(
    const float* __restrict__ Opart, const float2* __restrict__ ml,
    float* __restrict__ O, int ostride, int ooff) {
  int row = blockIdx.x, c = threadIdx.x;
  int h = c >> 5;
  float2 ml0 = ml[row*NHD + h];
  float2 ml1 = ml[(LQ + row)*NHD + h];
  float m = fmaxf(ml0.x, ml1.x);
  float e0 = __expf(ml0.x - m), e1 = __expf(ml1.x - m);
  float l = ml0.y*e0 + ml1.y*e1;
  float o0 = Opart[(size_t)row*CD + c];
  float o1 = Opart[(size_t)(LQ + row)*CD + c];
  O[(size_t)row*ostride + ooff + c] = (o0*e0 + o1*e1) / l;
}

// ---------------- curr_Q / global_K / global_V construction ----------------
__global__ __launch_bounds__(256) void make_kv_kernel(
    const float* __restrict__ qv, const float* __restrict__ idkv,
    float* __restrict__ q, float* __restrict__ gK, float* __restrict__ gV) {
  int l = blockIdx.x, c = threadIdx.x;
  float cq  = qv[(size_t)l*512 + c];
  float cv  = qv[(size_t)l*512 + 256 + c];
  float idk = idkv[(size_t)l*264 + (c >> 5)];
  float idv = idkv[(size_t)l*264 + 8 + c];
  q [(size_t)l*CD + c] = cq;
  gK[(size_t)l*CD + c] = cq * (1.f + tanhf(idk));
  gV[(size_t)l*CD + c] = cv + idv;
}

// ---------------- Local 15x15 window attention ----------------
__global__ __launch_bounds__(256) void local_attn_kernel(
    const float* __restrict__ Q, const float* __restrict__ Kp,
    const float* __restrict__ Vp, float* __restrict__ O, int ostride, int ooff) {
  __shared__ float p_sh[8][232];
  int n = blockIdx.x;
  int r = n / GW, c = n % GW;
  int h = threadIdx.x >> 5, lane = threadIdx.x & 31;

  const float* qp = Q + (size_t)n*CD + h*HD;
  float4 qreg[8];
  #pragma unroll
  for (int i = 0; i < 8; i++) {
    qreg[i] = *(const float4*)(qp + i*4);
    qreg[i].x *= QSCALE; qreg[i].y *= QSCALE; qreg[i].z *= QSCALE; qreg[i].w *= QSCALE;
  }
  int i0 = max(7 - r, 0), i1 = min(GH + 7 - r, 15);
  int j0 = max(7 - c, 0), j1 = min(GW + 7 - c, 15);

  for (int w = lane; w < 225; w += 32) {
    int wi = w / 15, wj = w - wi*15;
    float logit = -1e30f;
    if (wi >= i0 && wi < i1 && wj >= j0 && wj < j1) {
      const float* kp = Kp + (size_t)((r+wi-7)*GW + (c+wj-7))*CD + h*HD;
      float acc = 0.f;
      #pragma unroll
      for (int i4 = 0; i4 < 8; i4++) {
        float4 kv = *(const float4*)(kp + i4*4);
        acc = fmaf(qreg[i4].x, kv.x, acc);
        acc = fmaf(qreg[i4].y, kv.y, acc);
        acc = fmaf(qreg[i4].z, kv.z, acc);
        acc = fmaf(qreg[i4].w, kv.w, acc);
      }
      logit = acc;
    }
    p_sh[h][w] = logit;
  }
  __syncwarp();
  float m = -1e30f;
  for (int ww = lane; ww < 225; ww += 32) m = fmaxf(m, p_sh[h][ww]);
  #pragma unroll
  for (int o = 16; o; o >>= 1) m = fmaxf(m, __shfl_xor_sync(0xffffffffu, m, o));
  float ssum = 0.f;
  for (int ww = lane; ww < 225; ww += 32) {
    float p = __expf(p_sh[h][ww] - m);
    p_sh[h][ww] = p;
    ssum += p;
  }
  #pragma unroll
  for (int o = 16; o; o >>= 1) ssum += __shfl_xor_sync(0xffffffffu, ssum, o);
  float inv = 1.f / ssum;
  __syncwarp();
  float oacc = 0.f;
  for (int wi = i0; wi < i1; wi++) {
    const float* vrow = Vp + (size_t)((r+wi-7)*GW + (c+j0-7))*CD + h*HD + lane;
    #pragma unroll 3
    for (int wj = j0; wj < j1; wj++, vrow += CD)
      oacc = fmaf(p_sh[h][wi*15+wj], *vrow, oacc);
  }
  O[(size_t)n*ostride + ooff + h*HD + lane] = oacc * inv;
}

// ---------------- GroupNorm stats ----------------
__global__ __launch_bounds__(1024) void gn_stats_kernel(
    const float* __restrict__ x, float* __restrict__ stats) {
  int g = blockIdx.x;
  float s = 0.f, s2 = 0.f;
  for (int idx = threadIdx.x; idx < LQ*32; idx += 1024) {
    int l = idx >> 5, ch = idx & 31;
    float v = x[(size_t)l*DFF + g*32 + ch];
    s += v; s2 += v*v;
  }
  #pragma unroll
  for (int o = 16; o; o >>= 1) {
    s  += __shfl_xor_sync(0xffffffffu, s,  o);
    s2 += __shfl_xor_sync(0xffffffffu, s2, o);
  }
  __shared__ float sh[32], sh2[32];
  int w = threadIdx.x >> 5, lane = threadIdx.x & 31;
  if (lane == 0) { sh[w] = s; sh2[w] = s2; }
  __syncthreads();
  if (w == 0) {
    s = sh[lane]; s2 = sh2[lane];
    #pragma unroll
    for (int o = 16; o; o >>= 1) {
      s  += __shfl_xor_sync(0xffffffffu, s,  o);
      s2 += __shfl_xor_sync(0xffffffffu, s2, o);
    }
    if (lane == 0) {
      const float invn = 1.f / (LQ * 32.f);
      float mean = s * invn;
      float var  = s2 * invn - mean*mean;
      stats[g*2]   = mean;
      stats[g*2+1] = rsqrtf(var + EPSV);
    }
  }
}

// ---------------- GN apply + exact GELU ----------------
__global__ __launch_bounds__(256) void gn_gelu_kernel(
    const float* __restrict__ x, const float* __restrict__ gg, const float* __restrict__ gb,
    const float* __restrict__ stats, float* __restrict__ y) {
  int idx = blockIdx.x * 256 + threadIdx.x;
  int ch = idx & (DFF-1);
  int g = ch >> 5;
  float v = (x[idx] - stats[g*2]) * stats[g*2+1] * gg[ch] + gb[ch];
  y[idx] = 0.5f * v * (1.f + erff(v * 0.70710678118654752f));
}

// ---------------- 5x5 depthwise conv, pad 2 ----------------
__global__ __launch_bounds__(256) void dwconv_kernel(
    const float* __restrict__ x, const float* __restrict__ kern, float* __restrict__ y) {
  __shared__ float tile[12][12][32];
  __shared__ float kw[32][25];
  int tid = threadIdx.x;
  int ch0 = blockIdx.z * 32;
  int r0 = blockIdx.y * 8 - 2, c0 = blockIdx.x * 8 - 2;
  for (int e = tid; e < 12*12*32; e += 256) {
    int ch = e & 31;
    int sp = e >> 5;
    int ri = sp / 12, ci = sp % 12;
    int rr = r0 + ri, cc = c0 + ci;
    float v = 0.f;
    if ((unsigned)rr < (unsigned)GH && (unsigned)cc < (unsigned)GW)
      v = x[(size_t)(rr*GW + cc)*DFF + ch0 + ch];
    tile[ri][ci][ch] = v;
  }
  for (int e = tid; e < 32*25; e += 256)
    kw[e/25][e%25] = kern[(size_t)(ch0 + e/25)*25 + e%25];
  __syncthreads();
  for (int e = tid; e < 8*8*32; e += 256) {
    int ch = e & 31;
    int sp = e >> 5;
    int ri = sp >> 3, ci = sp & 7;
    float acc = 0.f;
    #pragma unroll
    for (int i = 0; i < 5; i++)
      #pragma unroll
      for (int j = 0; j < 5; j++)
        acc = fmaf(tile[ri+i][ci+j][ch], kw[ch][i*5+j], acc);
    int rr = blockIdx.y*8 + ri, cc = blockIdx.x*8 + ci;
    y[(size_t)(rr*GW + cc)*DFF + ch0 + ch] = acc;
  }
}

// ---------------- launcher ----------------
extern "C" void kernel_launch(void* const* d_in, const int* in_sizes, int n_in,
                              void* d_out, int out_size) {
  const float* in_tgt   = (const float*)d_in[0];
  const float* id_emb   = (const float*)d_in[1];
  const float* self_pos = (const float*)d_in[2];
  const float* ln1_g = (const float*)d_in[3];
  const float* ln1_b = (const float*)d_in[4];
  const float* sa_wq = (const float*)d_in[5];
  const float* sa_bq = (const float*)d_in[6];
  const float* sa_wk = (const float*)d_in[7];
  const float* sa_bk = (const float*)d_in[8];
  const float* sa_wv = (const float*)d_in[9];
  const float* sa_bv = (const float*)d_in[10];
  const float* sa_wo = (const float*)d_in[11];
  const float* sa_bo = (const float*)d_in[12];
  const float* ln2_g = (const float*)d_in[13];
  const float* ln2_b = (const float*)d_in[14];
  const float* w_qv = (const float*)d_in[15];
  const float* b_qv = (const float*)d_in[16];
  const float* w_id = (const float*)d_in[17];
  const float* b_id = (const float*)d_in[18];
  const float* lt_wo = (const float*)d_in[19];
  const float* lt_bo = (const float*)d_in[20];
  const float* st_wo = (const float*)d_in[21];
  const float* st_bo = (const float*)d_in[22];
  const float* ln3_g = (const float*)d_in[23];
  const float* ln3_b = (const float*)d_in[24];
  const float* w1 = (const float*)d_in[25];
  const float* b1 = (const float*)d_in[26];
  const float* gn_g = (const float*)d_in[27];
  const float* gn_b = (const float*)d_in[28];
  const float* dw_k = (const float*)d_in[29];
  const float* w2 = (const float*)d_in[30];
  const float* b2 = (const float*)d_in[31];
  float* out = (float*)d_out;

  float *t, *qkin, *q, *k, *v, *attcat, *tgtb, *qv, *idkv, *gK, *gV, *x, *x2, *stats, *wcat, *bcat, *opart;
  float2 *ml;
  cudaGetSymbolAddress((void**)&t,      g_t);
  cudaGetSymbolAddress((void**)&qkin,   g_qkin);
  cudaGetSymbolAddress((void**)&q,      g_q);
  cudaGetSymbolAddress((void**)&k,      g_k);
  cudaGetSymbolAddress((void**)&v,      g_v);
  cudaGetSymbolAddress((void**)&attcat, g_attcat);
  cudaGetSymbolAddress((void**)&tgtb,   g_tgt);
  cudaGetSymbolAddress((void**)&qv,     g_qv);
  cudaGetSymbolAddress((void**)&idkv,   g_idkv);
  cudaGetSymbolAddress((void**)&gK,     g_gK);
  cudaGetSymbolAddress((void**)&gV,     g_gV);
  cudaGetSymbolAddress((void**)&x,      g_x);
  cudaGetSymbolAddress((void**)&x2,     g_x2);
  cudaGetSymbolAddress((void**)&stats,  g_stats);
  cudaGetSymbolAddress((void**)&wcat,   g_wcat);
  cudaGetSymbolAddress((void**)&bcat,   g_bcat);
  cudaGetSymbolAddress((void**)&opart,  g_opart);
  cudaGetSymbolAddress((void**)&ml,     g_ml);

  dim3 g66(4, 25);
  dim3 gQKV(4, 25, 3);
  dim3 gAttn(25, 8, 2);

  pack_w<<<512,256>>>(lt_wo, st_wo, lt_bo, st_bo, wcat, bcat);
  cudaMemcpyAsync(tgtb, in_tgt, sizeof(float)*LQ*CD, cudaMemcpyDeviceToDevice, 0);

  // --- self attention ---
  ln_kernel<<<LQ,256>>>(in_tgt, ln1_g, ln1_b, t, self_pos, qkin);
  gemm_qkv<<<gQKV,256>>>(qkin, t, sa_wq, sa_wk, sa_wv, sa_bq, sa_bk, sa_bv, q, k, v);
  attn_kernel<<<gAttn,256>>>(q, k, v, opart, ml);
  attn_merge<<<LQ,256>>>(opart, ml, attcat, 256, 0);
  gemm_nt<<<g66,256>>>(attcat, sa_wo, sa_bo, tgtb, tgtb, LQ, CD, CD);

  // --- long/short term attention ---
  ln_kernel<<<LQ,256>>>(tgtb, ln2_g, ln2_b, t, nullptr, nullptr);
  gemm_nt<<<dim3(8,25),256>>>(t, w_qv, b_qv, nullptr, qv, LQ, 512, CD);
  gemm_nt<<<dim3(5,25),256>>>(id_emb, w_id, b_id, nullptr, idkv, LQ, 264, CD);
  make_kv_kernel<<<LQ,256>>>(qv, idkv, q, gK, gV);
  attn_kernel<<<gAttn,256>>>(q, gK, gV, opart, ml);
  attn_merge<<<LQ,256>>>(opart, ml, attcat, 512, 0);
  local_attn_kernel<<<LQ,256>>>(q, gK, gV, attcat, 512, 256);
  gemm_nt<<<g66,256>>>(attcat, wcat, bcat, tgtb, tgtb, LQ, CD, 512);

  // --- MLP: LN -> w1 -> GN -> GELU -> dwconv -> w2 ---
  ln_kernel<<<LQ,256>>>(tgtb, ln3_g, ln3_b, t, nullptr, nullptr);
  gemm_nt<<<dim3(16,25),256>>>(t, w1, b1, nullptr, x, LQ, DFF, CD);
  gn_stats_kernel<<<32,1024>>>(x, stats);
  gn_gelu_kernel<<<(LQ*DFF)/256,256>>>(x, gn_g, gn_b, stats, x2);
  dwconv_kernel<<<dim3(5,5,32),256>>>(x2, dw_k, x);
  gemm_nt<<<g66,256>>>(x, w2, b2, tgtb, out, LQ, CD, DFF);
}

// round 5
// speedup vs baseline: 1.4030x; 1.0201x over previous
#include <cuda_runtime.h>
#include <math.h>

#define LQ 1600
#define CD 256
#define NHD 8
#define HD 32
#define DFF 1024
#define GH 40
#define GW 40
#define EPSV 1e-5f
#define QSCALE 0.17677669529663687f  // 1/sqrt(32)

typedef unsigned long long ull;

// ---------------- f32x2 packed math helpers ----------------
__device__ __forceinline__ ull pk2(float x, float y) {
  ull r; asm("mov.b64 %0, {%1, %2};" : "=l"(r) : "f"(x), "f"(y)); return r;
}
__device__ __forceinline__ float2 up2(ull v) {
  float lo, hi; asm("mov.b64 {%0, %1}, %2;" : "=f"(lo), "=f"(hi) : "l"(v));
  return make_float2(lo, hi);
}
__device__ __forceinline__ void fma2(ull &d, ull a, ull b) {
  asm("fma.rn.f32x2 %0, %1, %2, %0;" : "+l"(d) : "l"(a), "l"(b));
}
__device__ __forceinline__ void mul2(ull &d, ull a) {
  asm("mul.rn.f32x2 %0, %0, %1;" : "+l"(d) : "l"(a));
}

// ---------------- scratch (device globals; no allocation) ----------------
static __device__ float g_t[LQ*CD];
static __device__ float g_qkin[LQ*CD];
static __device__ float g_q[LQ*CD];
static __device__ float g_k[LQ*CD];
static __device__ float g_v[LQ*CD];
static __device__ float g_attcat[LQ*512];
static __device__ float g_tgt[LQ*CD];
static __device__ float g_qv[LQ*2*CD];
static __device__ float g_idkv[LQ*264];
static __device__ float g_gK[LQ*CD];
static __device__ float g_gV[LQ*CD];
static __device__ float g_x[LQ*DFF];
static __device__ float g_x2[LQ*DFF];
static __device__ float g_stats[64];
static __device__ float g_wcat[256*512];
static __device__ float g_bcat[256];
static __device__ float g_opart[2*LQ*CD];
static __device__ float2 g_ml[2*LQ*NHD];

// ---------------- LayerNorm (optionally + pos add) ----------------
__global__ __launch_bounds__(256) void ln_kernel(
    const float* __restrict__ x, const float* __restrict__ g, const float* __restrict__ b,
    float* __restrict__ y, const float* __restrict__ pos, float* __restrict__ qkout) {
  int l = blockIdx.x;
  int c = threadIdx.x;
  float v = x[(size_t)l*CD + c];
  float s = v, s2 = v*v;
  #pragma unroll
  for (int o = 16; o; o >>= 1) {
    s  += __shfl_xor_sync(0xffffffffu, s,  o);
    s2 += __shfl_xor_sync(0xffffffffu, s2, o);
  }
  __shared__ float sh[8], sh2[8], smv[2];
  int w = c >> 5, lane = c & 31;
  if (lane == 0) { sh[w] = s; sh2[w] = s2; }
  __syncthreads();
  if (c == 0) {
    float a = 0.f, a2 = 0.f;
    #pragma unroll
    for (int i = 0; i < 8; i++) { a += sh[i]; a2 += sh2[i]; }
    float mean = a * (1.0f/CD);
    float var  = a2 * (1.0f/CD) - mean*mean;
    smv[0] = mean; smv[1] = rsqrtf(var + EPSV);
  }
  __syncthreads();
  float out = (v - smv[0]) * smv[1] * g[c] + b[c];
  y[(size_t)l*CD + c] = out;
  if (qkout) qkout[(size_t)l*CD + c] = out + pos[(size_t)l*CD + c];
}

// ---------------- GEMM core (f32x2): C[M,N]=A[M,K]@B[N,K]^T + bias (+res) ---
// 64x64 tile, K-chunk 32, double-buffered smem, 128 threads, 8x4 microtile.
__device__ __forceinline__ void gemm_body(
    const float* __restrict__ A, const float* __restrict__ B,
    const float* __restrict__ bias, const float* __restrict__ res,
    float* __restrict__ Cout, int M, int N, int K, int bm, int bn) {
  __shared__ float As[2][32][68];
  __shared__ float Bs[2][32][68];
  const int tid = threadIdx.x;
  const int tx = tid & 15, ty = tid >> 4;          // ty 0..7
  const int lr = tid >> 1;                          // loader row 0..63
  const int lc = (tid & 1) << 4;                    // loader k base 0 or 16
  ull acc2[8][2] = {};
  const int nk = K >> 5;

  float4 a[4], b[4];
  const bool bok = (bn + lr) < N;
  {
    const float* Ap = A + (size_t)(bm + lr)*K + lc;
    const float* Bp = B + (size_t)(bn + lr)*K + lc;
    #pragma unroll
    for (int u = 0; u < 4; u++) {
      a[u] = *(const float4*)(Ap + u*4);
      b[u] = bok ? *(const float4*)(Bp + u*4) : make_float4(0.f,0.f,0.f,0.f);
    }
  }
  #pragma unroll
  for (int u = 0; u < 4; u++) {
    int kk = lc + u*4;
    As[0][kk+0][lr]=a[u].x; As[0][kk+1][lr]=a[u].y; As[0][kk+2][lr]=a[u].z; As[0][kk+3][lr]=a[u].w;
    Bs[0][kk+0][lr]=b[u].x; Bs[0][kk+1][lr]=b[u].y; Bs[0][kk+2][lr]=b[u].z; Bs[0][kk+3][lr]=b[u].w;
  }
  __syncthreads();

  for (int ch = 0; ch < nk; ch++) {
    const int buf = ch & 1;
    if (ch + 1 < nk) {
      const int k0 = (ch + 1) << 5;
      const float* Ap = A + (size_t)(bm + lr)*K + k0 + lc;
      const float* Bp = B + (size_t)(bn + lr)*K + k0 + lc;
      #pragma unroll
      for (int u = 0; u < 4; u++) {
        a[u] = *(const float4*)(Ap + u*4);
        b[u] = bok ? *(const float4*)(Bp + u*4) : make_float4(0.f,0.f,0.f,0.f);
      }
    }
    #pragma unroll
    for (int kk = 0; kk < 32; kk++) {
      float4 a4a = *(const float4*)&As[buf][kk][ty*8];
      float4 a4b = *(const float4*)&As[buf][kk][ty*8+4];
      const ull* bp = (const ull*)&Bs[buf][kk][tx*4];
      ull b01 = bp[0], b23 = bp[1];
      float av[8] = {a4a.x, a4a.y, a4a.z, a4a.w, a4b.x, a4b.y, a4b.z, a4b.w};
      #pragma unroll
      for (int i = 0; i < 8; i++) {
        ull aa = pk2(av[i], av[i]);
        fma2(acc2[i][0], aa, b01);
        fma2(acc2[i][1], aa, b23);
      }
    }
    if (ch + 1 < nk) {
      const int nb = buf ^ 1;
      #pragma unroll
      for (int u = 0; u < 4; u++) {
        int kk = lc + u*4;
        As[nb][kk+0][lr]=a[u].x; As[nb][kk+1][lr]=a[u].y; As[nb][kk+2][lr]=a[u].z; As[nb][kk+3][lr]=a[u].w;
        Bs[nb][kk+0][lr]=b[u].x; Bs[nb][kk+1][lr]=b[u].y; Bs[nb][kk+2][lr]=b[u].z; Bs[nb][kk+3][lr]=b[u].w;
      }
      __syncthreads();
    }
  }
  #pragma unroll
  for (int i = 0; i < 8; i++) {
    int m = bm + ty*8 + i;
    float2 v01 = up2(acc2[i][0]);
    float2 v23 = up2(acc2[i][1]);
    float vals[4] = {v01.x, v01.y, v23.x, v23.y};
    #pragma unroll
    for (int j = 0; j < 4; j++) {
      int n = bn + tx*4 + j;
      if (n < N) {
        float val = vals[j] + bias[n];
        if (res) val += res[(size_t)m*N + n];
        Cout[(size_t)m*N + n] = val;
      }
    }
  }
}

__global__ __launch_bounds__(128) void gemm_nt(
    const float* __restrict__ A, const float* __restrict__ B,
    const float* __restrict__ bias, const float* __restrict__ res,
    float* __restrict__ Cout, int M, int N, int K) {
  gemm_body(A, B, bias, res, Cout, M, N, K, blockIdx.y*64, blockIdx.x*64);
}

__global__ __launch_bounds__(128) void gemm_qkv(
    const float* __restrict__ qkin, const float* __restrict__ t,
    const float* __restrict__ wq, const float* __restrict__ wk, const float* __restrict__ wv,
    const float* __restrict__ bq, const float* __restrict__ bk, const float* __restrict__ bv,
    float* __restrict__ q, float* __restrict__ k, float* __restrict__ v) {
  int z = blockIdx.z;
  const float* A = (z == 2) ? t : qkin;
  const float* B = (z == 0) ? wq : (z == 1 ? wk : wv);
  const float* bias = (z == 0) ? bq : (z == 1 ? bk : bv);
  float* C = (z == 0) ? q : (z == 1 ? k : v);
  gemm_body(A, B, bias, nullptr, C, LQ, CD, CD, blockIdx.y*64, blockIdx.x*64);
}

// pack [lt_wo | st_wo] into (256,512) + combined bias
__global__ __launch_bounds__(256) void pack_w(
    const float* __restrict__ lt, const float* __restrict__ st,
    const float* __restrict__ ltb, const float* __restrict__ stb,
    float* __restrict__ wcat, float* __restrict__ bcat) {
  int idx = blockIdx.x * 256 + threadIdx.x;
  int nrow = idx >> 9, k = idx & 511;
  wcat[idx] = (k < 256) ? lt[nrow*256 + k] : st[nrow*256 + k - 256];
  if (idx < 256) bcat[idx] = ltb[idx] + stb[idx];
}

// ---------------- Fused full attention, split-KV x2, f32x2, 8x4 microtile ---
// grid (25 q-tiles, 8 heads, 2 kv-splits), 128 threads.
__global__ __launch_bounds__(128) void attn_kernel(
    const float* __restrict__ Q, const float* __restrict__ Kp,
    const float* __restrict__ Vp, float* __restrict__ Opart, float2* __restrict__ ml) {
  __shared__ float Qs[HD][64];
  __shared__ float Ks[HD][64];
  __shared__ float Vs[64][34];
  __shared__ float Ps[64][68];
  const int h = blockIdx.y;
  const int z = blockIdx.z;
  const int q0 = blockIdx.x * 64;
  const int kt0 = z ? 13 : 0, kt1 = z ? 25 : 13;
  const int tid = threadIdx.x;
  const int tx = tid & 15, ty = tid >> 4;   // ty 0..7

  #pragma unroll
  for (int it = 0; it < 4; it++) {
    int e = tid + it*128;
    int r = e >> 3, d4 = (e & 7) << 2;
    const float4 qv = *(const float4*)(Q + (size_t)(q0 + r)*CD + h*HD + d4);
    Qs[d4+0][r] = qv.x * QSCALE; Qs[d4+1][r] = qv.y * QSCALE;
    Qs[d4+2][r] = qv.z * QSCALE; Qs[d4+3][r] = qv.w * QSCALE;
  }
  float m_i[8], l_i[8];
  ull oa2[8];
  #pragma unroll
  for (int i = 0; i < 8; i++) { m_i[i] = -1e30f; l_i[i] = 0.f; oa2[i] = 0ull; }

  for (int kt = kt0; kt < kt1; kt++) {
    const int k0 = kt * 64;
    #pragma unroll
    for (int it = 0; it < 4; it++) {
      int e = tid + it*128;
      int r = e >> 3, d4 = (e & 7) << 2;
      const float4 kv = *(const float4*)(Kp + (size_t)(k0 + r)*CD + h*HD + d4);
      Ks[d4+0][r] = kv.x; Ks[d4+1][r] = kv.y; Ks[d4+2][r] = kv.z; Ks[d4+3][r] = kv.w;
      const float4 vv = *(const float4*)(Vp + (size_t)(k0 + r)*CD + h*HD + d4);
      Vs[r][d4+0] = vv.x; Vs[r][d4+1] = vv.y; Vs[r][d4+2] = vv.z; Vs[r][d4+3] = vv.w;
    }
    __syncthreads();
    // --- QK^T: 8 rows x 4 keys per thread, packed pairs over keys ---
    ull s2[8][2] = {};
    #pragma unroll
    for (int d = 0; d < HD; d++) {
      float4 a4a = *(const float4*)&Qs[d][ty*8];
      float4 a4b = *(const float4*)&Qs[d][ty*8+4];
      const ull* bp = (const ull*)&Ks[d][tx*4];
      ull b01 = bp[0], b23 = bp[1];
      float av[8] = {a4a.x, a4a.y, a4a.z, a4a.w, a4b.x, a4b.y, a4b.z, a4b.w};
      #pragma unroll
      for (int i = 0; i < 8; i++) {
        ull aa = pk2(av[i], av[i]);
        fma2(s2[i][0], aa, b01);
        fma2(s2[i][1], aa, b23);
      }
    }
    // --- online softmax ---
    #pragma unroll
    for (int i = 0; i < 8; i++) {
      float2 s01 = up2(s2[i][0]);
      float2 s23 = up2(s2[i][1]);
      float sv[4] = {s01.x, s01.y, s23.x, s23.y};
      float rm = fmaxf(fmaxf(sv[0], sv[1]), fmaxf(sv[2], sv[3]));
      #pragma unroll
      for (int o = 8; o; o >>= 1) rm = fmaxf(rm, __shfl_xor_sync(0xffffffffu, rm, o));
      float mnew = fmaxf(m_i[i], rm);
      float alpha = __expf(m_i[i] - mnew);
      float p0 = __expf(sv[0] - mnew);
      float p1 = __expf(sv[1] - mnew);
      float p2 = __expf(sv[2] - mnew);
      float p3 = __expf(sv[3] - mnew);
      *(float4*)&Ps[ty*8+i][tx*4] = make_float4(p0, p1, p2, p3);
      float rs = (p0 + p1) + (p2 + p3);
      #pragma unroll
      for (int o = 8; o; o >>= 1) rs += __shfl_xor_sync(0xffffffffu, rs, o);
      l_i[i] = l_i[i]*alpha + rs;
      m_i[i] = mnew;
      mul2(oa2[i], pk2(alpha, alpha));
    }
    __syncthreads();
    // --- P @ V ---
    #pragma unroll 2
    for (int k4 = 0; k4 < 16; k4++) {
      float4 p4[8];
      #pragma unroll
      for (int i = 0; i < 8; i++) p4[i] = *(const float4*)&Ps[ty*8+i][k4*4];
      #pragma unroll
      for (int t = 0; t < 4; t++) {
        ull v2 = *(const ull*)&Vs[k4*4+t][tx*2];
        #pragma unroll
        for (int i = 0; i < 8; i++) {
          float p = (&p4[i].x)[t];
          fma2(oa2[i], pk2(p, p), v2);
        }
      }
    }
    __syncthreads();
  }
  #pragma unroll
  for (int i = 0; i < 8; i++) {
    int row = q0 + ty*8 + i;
    float2 o2 = up2(oa2[i]);
    Opart[((size_t)z*LQ + row)*CD + h*HD + tx*2+0] = o2.x;
    Opart[((size_t)z*LQ + row)*CD + h*HD + tx*2+1] = o2.y;
    if (tx == 0) ml[(z*LQ + row)*NHD + h] = make_float2(m_i[i], l_i[i]);
  }
}

// merge the 2 kv-splits
__global__ __launch_bounds__(256) void attn_merge(
    const float* __restrict__ Opart, const float2* __restrict__ ml,
    float* __restrict__ O, int ostride, int ooff) {
  int row = blockIdx.x, c = threadIdx.x;
  int h = c >> 5;
  float2 ml0 = ml[row*NHD + h];
  float2 ml1 = ml[(LQ + row)*NHD + h];
  float m = fmaxf(ml0.x, ml1.x);
  float e0 = __expf(ml0.x - m), e1 = __expf(ml1.x - m);
  float l = ml0.y*e0 + ml1.y*e1;
  float o0 = Opart[(size_t)row*CD + c];
  float o1 = Opart[(size_t)(LQ + row)*CD + c];
  O[(size_t)row*ostride + ooff + c] = (o0*e0 + o1*e1) / l;
}

// ---------------- curr_Q / global_K / global_V construction ----------------
__global__ __launch_bounds__(256) void make_kv_kernel(
    const float* __restrict__ qv, const float* __restrict__ idkv,
    float* __restrict__ q, float* __restrict__ gK, float* __restrict__ gV) {
  int l = blockIdx.x, c = threadIdx.x;
  float cq  = qv[(size_t)l*512 + c];
  float cv  = qv[(size_t)l*512 + 256 + c];
  float idk = idkv[(size_t)l*264 + (c >> 5)];
  float idv = idkv[(size_t)l*264 + 8 + c];
  q [(size_t)l*CD + c] = cq;
  gK[(size_t)l*CD + c] = cq * (1.f + tanhf(idk));
  gV[(size_t)l*CD + c] = cv + idv;
}

// ---------------- Local 15x15 window attention ----------------
__global__ __launch_bounds__(256) void local_attn_kernel(
    const float* __restrict__ Q, const float* __restrict__ Kp,
    const float* __restrict__ Vp, float* __restrict__ O, int ostride, int ooff) {
  __shared__ float p_sh[8][232];
  int n = blockIdx.x;
  int r = n / GW, c = n % GW;
  int h = threadIdx.x >> 5, lane = threadIdx.x & 31;

  const float* qp = Q + (size_t)n*CD + h*HD;
  float4 qreg[8];
  #pragma unroll
  for (int i = 0; i < 8; i++) {
    qreg[i] = *(const float4*)(qp + i*4);
    qreg[i].x *= QSCALE; qreg[i].y *= QSCALE; qreg[i].z *= QSCALE; qreg[i].w *= QSCALE;
  }
  int i0 = max(7 - r, 0), i1 = min(GH + 7 - r, 15);
  int j0 = max(7 - c, 0), j1 = min(GW + 7 - c, 15);

  for (int w = lane; w < 225; w += 32) {
    int wi = w / 15, wj = w - wi*15;
    float logit = -1e30f;
    if (wi >= i0 && wi < i1 && wj >= j0 && wj < j1) {
      const float* kp = Kp + (size_t)((r+wi-7)*GW + (c+wj-7))*CD + h*HD;
      float acc = 0.f;
      #pragma unroll
      for (int i4 = 0; i4 < 8; i4++) {
        float4 kv = *(const float4*)(kp + i4*4);
        acc = fmaf(qreg[i4].x, kv.x, acc);
        acc = fmaf(qreg[i4].y, kv.y, acc);
        acc = fmaf(qreg[i4].z, kv.z, acc);
        acc = fmaf(qreg[i4].w, kv.w, acc);
      }
      logit = acc;
    }
    p_sh[h][w] = logit;
  }
  __syncwarp();
  float m = -1e30f;
  for (int ww = lane; ww < 225; ww += 32) m = fmaxf(m, p_sh[h][ww]);
  #pragma unroll
  for (int o = 16; o; o >>= 1) m = fmaxf(m, __shfl_xor_sync(0xffffffffu, m, o));
  float ssum = 0.f;
  for (int ww = lane; ww < 225; ww += 32) {
    float p = __expf(p_sh[h][ww] - m);
    p_sh[h][ww] = p;
    ssum += p;
  }
  #pragma unroll
  for (int o = 16; o; o >>= 1) ssum += __shfl_xor_sync(0xffffffffu, ssum, o);
  float inv = 1.f / ssum;
  __syncwarp();
  float oacc = 0.f;
  for (int wi = i0; wi < i1; wi++) {
    const float* vrow = Vp + (size_t)((r+wi-7)*GW + (c+j0-7))*CD + h*HD + lane;
    #pragma unroll 3
    for (int wj = j0; wj < j1; wj++, vrow += CD)
      oacc = fmaf(p_sh[h][wi*15+wj], *vrow, oacc);
  }
  O[(size_t)n*ostride + ooff + h*HD + lane] = oacc * inv;
}

// ---------------- GroupNorm stats ----------------
__global__ __launch_bounds__(1024) void gn_stats_kernel(
    const float* __restrict__ x, float* __restrict__ stats) {
  int g = blockIdx.x;
  float s = 0.f, s2 = 0.f;
  for (int idx = threadIdx.x; idx < LQ*32; idx += 1024) {
    int l = idx >> 5, ch = idx & 31;
    float v = x[(size_t)l*DFF + g*32 + ch];
    s += v; s2 += v*v;
  }
  #pragma unroll
  for (int o = 16; o; o >>= 1) {
    s  += __shfl_xor_sync(0xffffffffu, s,  o);
    s2 += __shfl_xor_sync(0xffffffffu, s2, o);
  }
  __shared__ float sh[32], sh2[32];
  int w = threadIdx.x >> 5, lane = threadIdx.x & 31;
  if (lane == 0) { sh[w] = s; sh2[w] = s2; }
  __syncthreads();
  if (w == 0) {
    s = sh[lane]; s2 = sh2[lane];
    #pragma unroll
    for (int o = 16; o; o >>= 1) {
      s  += __shfl_xor_sync(0xffffffffu, s,  o);
      s2 += __shfl_xor_sync(0xffffffffu, s2, o);
    }
    if (lane == 0) {
      const float invn = 1.f / (LQ * 32.f);
      float mean = s * invn;
      float var  = s2 * invn - mean*mean;
      stats[g*2]   = mean;
      stats[g*2+1] = rsqrtf(var + EPSV);
    }
  }
}

// ---------------- GN apply + exact GELU ----------------
__global__ __launch_bounds__(256) void gn_gelu_kernel(
    const float* __restrict__ x, const float* __restrict__ gg, const float* __restrict__ gb,
    const float* __restrict__ stats, float* __restrict__ y) {
  int idx = blockIdx.x * 256 + threadIdx.x;
  int ch = idx & (DFF-1);
  int g = ch >> 5;
  float v = (x[idx] - stats[g*2]) * stats[g*2+1] * gg[ch] + gb[ch];
  y[idx] = 0.5f * v * (1.f + erff(v * 0.70710678118654752f));
}

// ---------------- 5x5 depthwise conv, pad 2 ----------------
__global__ __launch_bounds__(256) void dwconv_kernel(
    const float* __restrict__ x, const float* __restrict__ kern, float* __restrict__ y) {
  __shared__ float tile[12][12][32];
  __shared__ float kw[32][25];
  int tid = threadIdx.x;
  int ch0 = blockIdx.z * 32;
  int r0 = blockIdx.y * 8 - 2, c0 = blockIdx.x * 8 - 2;
  for (int e = tid; e < 12*12*32; e += 256) {
    int ch = e & 31;
    int sp = e >> 5;
    int ri = sp / 12, ci = sp % 12;
    int rr = r0 + ri, cc = c0 + ci;
    float v = 0.f;
    if ((unsigned)rr < (unsigned)GH && (unsigned)cc < (unsigned)GW)
      v = x[(size_t)(rr*GW + cc)*DFF + ch0 + ch];
    tile[ri][ci][ch] = v;
  }
  for (int e = tid; e < 32*25; e += 256)
    kw[e/25][e%25] = kern[(size_t)(ch0 + e/25)*25 + e%25];
  __syncthreads();
  for (int e = tid; e < 8*8*32; e += 256) {
    int ch = e & 31;
    int sp = e >> 5;
    int ri = sp >> 3, ci = sp & 7;
    float acc = 0.f;
    #pragma unroll
    for (int i = 0; i < 5; i++)
      #pragma unroll
      for (int j = 0; j < 5; j++)
        acc = fmaf(tile[ri+i][ci+j][ch], kw[ch][i*5+j], acc);
    int rr = blockIdx.y*8 + ri, cc = blockIdx.x*8 + ci;
    y[(size_t)(rr*GW + cc)*DFF + ch0 + ch] = acc;
  }
}

// ---------------- launcher ----------------
extern "C" void kernel_launch(void* const* d_in, const int* in_sizes, int n_in,
                              void* d_out, int out_size) {
  const float* in_tgt   = (const float*)d_in[0];
  const float* id_emb   = (const float*)d_in[1];
  const float* self_pos = (const float*)d_in[2];
  const float* ln1_g = (const float*)d_in[3];
  const float* ln1_b = (const float*)d_in[4];
  const float* sa_wq = (const float*)d_in[5];
  const float* sa_bq = (const float*)d_in[6];
  const float* sa_wk = (const float*)d_in[7];
  const float* sa_bk = (const float*)d_in[8];
  const float* sa_wv = (const float*)d_in[9];
  const float* sa_bv = (const float*)d_in[10];
  const float* sa_wo = (const float*)d_in[11];
  const float* sa_bo = (const float*)d_in[12];
  const float* ln2_g = (const float*)d_in[13];
  const float* ln2_b = (const float*)d_in[14];
  const float* w_qv = (const float*)d_in[15];
  const float* b_qv = (const float*)d_in[16];
  const float* w_id = (const float*)d_in[17];
  const float* b_id = (const float*)d_in[18];
  const float* lt_wo = (const float*)d_in[19];
  const float* lt_bo = (const float*)d_in[20];
  const float* st_wo = (const float*)d_in[21];
  const float* st_bo = (const float*)d_in[22];
  const float* ln3_g = (const float*)d_in[23];
  const float* ln3_b = (const float*)d_in[24];
  const float* w1 = (const float*)d_in[25];
  const float* b1 = (const float*)d_in[26];
  const float* gn_g = (const float*)d_in[27];
  const float* gn_b = (const float*)d_in[28];
  const float* dw_k = (const float*)d_in[29];
  const float* w2 = (const float*)d_in[30];
  const float* b2 = (const float*)d_in[31];
  float* out = (float*)d_out;

  float *t, *qkin, *q, *k, *v, *attcat, *tgtb, *qv, *idkv, *gK, *gV, *x, *x2, *stats, *wcat, *bcat, *opart;
  float2 *ml;
  cudaGetSymbolAddress((void**)&t,      g_t);
  cudaGetSymbolAddress((void**)&qkin,   g_qkin);
  cudaGetSymbolAddress((void**)&q,      g_q);
  cudaGetSymbolAddress((void**)&k,      g_k);
  cudaGetSymbolAddress((void**)&v,      g_v);
  cudaGetSymbolAddress((void**)&attcat, g_attcat);
  cudaGetSymbolAddress((void**)&tgtb,   g_tgt);
  cudaGetSymbolAddress((void**)&qv,     g_qv);
  cudaGetSymbolAddress((void**)&idkv,   g_idkv);
  cudaGetSymbolAddress((void**)&gK,     g_gK);
  cudaGetSymbolAddress((void**)&gV,     g_gV);
  cudaGetSymbolAddress((void**)&x,      g_x);
  cudaGetSymbolAddress((void**)&x2,     g_x2);
  cudaGetSymbolAddress((void**)&stats,  g_stats);
  cudaGetSymbolAddress((void**)&wcat,   g_wcat);
  cudaGetSymbolAddress((void**)&bcat,   g_bcat);
  cudaGetSymbolAddress((void**)&opart,  g_opart);
  cudaGetSymbolAddress((void**)&ml,     g_ml);

  dim3 g66(4, 25);
  dim3 gQKV(4, 25, 3);
  dim3 gAttn(25, 8, 2);

  pack_w<<<512,256>>>(lt_wo, st_wo, lt_bo, st_bo, wcat, bcat);
  cudaMemcpyAsync(tgtb, in_tgt, sizeof(float)*LQ*CD, cudaMemcpyDeviceToDevice, 0);

  // --- self attention ---
  ln_kernel<<<LQ,256>>>(in_tgt, ln1_g, ln1_b, t, self_pos, qkin);
  gemm_qkv<<<gQKV,128>>>(qkin, t, sa_wq, sa_wk, sa_wv, sa_bq, sa_bk, sa_bv, q, k, v);
  attn_kernel<<<gAttn,128>>>(q, k, v, opart, ml);
  attn_merge<<<LQ,256>>>(opart, ml, attcat, 256, 0);
  gemm_nt<<<g66,128>>>(attcat, sa_wo, sa_bo, tgtb, tgtb, LQ, CD, CD);

  // --- long/short term attention ---
  ln_kernel<<<LQ,256>>>(tgtb, ln2_g, ln2_b, t, nullptr, nullptr);
  gemm_nt<<<dim3(8,25),128>>>(t, w_qv, b_qv, nullptr, qv, LQ, 512, CD);
  gemm_nt<<<dim3(5,25),128>>>(id_emb, w_id, b_id, nullptr, idkv, LQ, 264, CD);
  make_kv_kernel<<<LQ,256>>>(qv, idkv, q, gK, gV);
  attn_kernel<<<gAttn,128>>>(q, gK, gV, opart, ml);
  attn_merge<<<LQ,256>>>(opart, ml, attcat, 512, 0);
  local_attn_kernel<<<LQ,256>>>(q, gK, gV, attcat, 512, 256);
  gemm_nt<<<g66,128>>>(attcat, wcat, bcat, tgtb, tgtb, LQ, CD, 512);

  // --- MLP: LN -> w1 -> GN -> GELU -> dwconv -> w2 ---
  ln_kernel<<<LQ,256>>>(tgtb, ln3_g, ln3_b, t, nullptr, nullptr);
  gemm_nt<<<dim3(16,25),128>>>(t, w1, b1, nullptr, x, LQ, DFF, CD);
  gn_stats_kernel<<<32,1024>>>(x, stats);
  gn_gelu_kernel<<<(LQ*DFF)/256,256>>>(x, gn_g, gn_b, stats, x2);
  dwconv_kernel<<<dim3(5,5,32),256>>>(x2, dw_k, x);
  gemm_nt<<<g66,128>>>(x, w2, b2, tgtb, out, LQ, CD, DFF);
}

// round 6
// speedup vs baseline: 1.4657x; 1.0447x over previous
#include <cuda_runtime.h>
#include <math.h>

#define LQ 1600
#define CD 256
#define NHD 8
#define HD 32
#define DFF 1024
#define GH 40
#define GW 40
#define EPSV 1e-5f
#define QSCALE 0.17677669529663687f  // 1/sqrt(32)
#define NSPLIT 4

typedef unsigned long long ull;

// ---------------- f32x2 packed math helpers ----------------
__device__ __forceinline__ ull pk2(float x, float y) {
  ull r; asm("mov.b64 %0, {%1, %2};" : "=l"(r) : "f"(x), "f"(y)); return r;
}
__device__ __forceinline__ float2 up2(ull v) {
  float lo, hi; asm("mov.b64 {%0, %1}, %2;" : "=f"(lo), "=f"(hi) : "l"(v));
  return make_float2(lo, hi);
}
__device__ __forceinline__ void fma2(ull &d, ull a, ull b) {
  asm("fma.rn.f32x2 %0, %1, %2, %0;" : "+l"(d) : "l"(a), "l"(b));
}
__device__ __forceinline__ void mul2(ull &d, ull a) {
  asm("mul.rn.f32x2 %0, %0, %1;" : "+l"(d) : "l"(a));
}

// ---------------- scratch (device globals; no allocation) ----------------
static __device__ float g_t[LQ*CD];
static __device__ float g_qkin[LQ*CD];
static __device__ float g_q[LQ*CD];
static __device__ float g_k[LQ*CD];
static __device__ float g_v[LQ*CD];
static __device__ float g_attcat[LQ*512];
static __device__ float g_tgt[LQ*CD];
static __device__ float g_qv[LQ*2*CD];
static __device__ float g_idkv[LQ*264];
static __device__ float g_gK[LQ*CD];
static __device__ float g_gV[LQ*CD];
static __device__ float g_x[LQ*DFF];
static __device__ float g_x2[LQ*DFF];
static __device__ float g_stats[64];
static __device__ float g_wcat[256*512];
static __device__ float g_bcat[256];
static __device__ float g_opart[NSPLIT*LQ*CD];
static __device__ float2 g_ml[NSPLIT*LQ*NHD];

// ---------------- LayerNorm (optionally + pos add) ----------------
__global__ __launch_bounds__(256) void ln_kernel(
    const float* __restrict__ x, const float* __restrict__ g, const float* __restrict__ b,
    float* __restrict__ y, const float* __restrict__ pos, float* __restrict__ qkout) {
  int l = blockIdx.x;
  int c = threadIdx.x;
  float v = x[(size_t)l*CD + c];
  float s = v, s2 = v*v;
  #pragma unroll
  for (int o = 16; o; o >>= 1) {
    s  += __shfl_xor_sync(0xffffffffu, s,  o);
    s2 += __shfl_xor_sync(0xffffffffu, s2, o);
  }
  __shared__ float sh[8], sh2[8], smv[2];
  int w = c >> 5, lane = c & 31;
  if (lane == 0) { sh[w] = s; sh2[w] = s2; }
  __syncthreads();
  if (c == 0) {
    float a = 0.f, a2 = 0.f;
    #pragma unroll
    for (int i = 0; i < 8; i++) { a += sh[i]; a2 += sh2[i]; }
    float mean = a * (1.0f/CD);
    float var  = a2 * (1.0f/CD) - mean*mean;
    smv[0] = mean; smv[1] = rsqrtf(var + EPSV);
  }
  __syncthreads();
  float out = (v - smv[0]) * smv[1] * g[c] + b[c];
  y[(size_t)l*CD + c] = out;
  if (qkout) qkout[(size_t)l*CD + c] = out + pos[(size_t)l*CD + c];
}

// ---------------- GEMM core (f32x2, intra-CTA split-K x2) -------------------
// C[M,N]=A[M,K]@B[N,K]^T + bias (+res). 64x64 tile, 256 threads (2 halves of
// 128), each half does K/2 with its own single-buffered smem tile + register
// prefetch; half 1 reduces through smem. 8x4 microtile per thread.
__device__ __forceinline__ void gemm_body(
    const float* __restrict__ A, const float* __restrict__ B,
    const float* __restrict__ bias, const float* __restrict__ res,
    float* __restrict__ Cout, int M, int N, int K, int bm, int bn) {
  __shared__ float As[2][32][68];
  __shared__ float Bs[2][32][68];
  const int tid = threadIdx.x;
  const int h = tid >> 7;            // split-K half
  const int htid = tid & 127;
  const int tx = htid & 15, ty = htid >> 4;  // microtile coords
  const int lr = htid >> 1;          // loader row 0..63
  const int lc = (htid & 1) << 4;    // loader k base 0 or 16
  ull acc2[8][2] = {};
  const int nk = K >> 5;
  const int nh = nk >> 1;            // chunks per half

  float4 a[4], b[4];
  const bool bok = (bn + lr) < N;
  // prefetch first chunk of this half into registers
  {
    const int k0 = (h * nh) << 5;
    const float* Ap = A + (size_t)(bm + lr)*K + k0 + lc;
    const float* Bp = B + (size_t)(bn + lr)*K + k0 + lc;
    #pragma unroll
    for (int u = 0; u < 4; u++) {
      a[u] = *(const float4*)(Ap + u*4);
      b[u] = bok ? *(const float4*)(Bp + u*4) : make_float4(0.f,0.f,0.f,0.f);
    }
  }

  for (int c = 0; c < nh; c++) {
    __syncthreads();   // previous compute (both halves) done before overwrite
    #pragma unroll
    for (int u = 0; u < 4; u++) {
      int kk = lc + u*4;
      As[h][kk+0][lr]=a[u].x; As[h][kk+1][lr]=a[u].y; As[h][kk+2][lr]=a[u].z; As[h][kk+3][lr]=a[u].w;
      Bs[h][kk+0][lr]=b[u].x; Bs[h][kk+1][lr]=b[u].y; Bs[h][kk+2][lr]=b[u].z; Bs[h][kk+3][lr]=b[u].w;
    }
    __syncthreads();
    if (c + 1 < nh) {
      const int k0 = (h * nh + c + 1) << 5;
      const float* Ap = A + (size_t)(bm + lr)*K + k0 + lc;
      const float* Bp = B + (size_t)(bn + lr)*K + k0 + lc;
      #pragma unroll
      for (int u = 0; u < 4; u++) {
        a[u] = *(const float4*)(Ap + u*4);
        b[u] = bok ? *(const float4*)(Bp + u*4) : make_float4(0.f,0.f,0.f,0.f);
      }
    }
    #pragma unroll
    for (int kk = 0; kk < 32; kk++) {
      float4 a4a = *(const float4*)&As[h][kk][ty*8];
      float4 a4b = *(const float4*)&As[h][kk][ty*8+4];
      const ull* bp = (const ull*)&Bs[h][kk][tx*4];
      ull b01 = bp[0], b23 = bp[1];
      float av[8] = {a4a.x, a4a.y, a4a.z, a4a.w, a4b.x, a4b.y, a4b.z, a4b.w};
      #pragma unroll
      for (int i = 0; i < 8; i++) {
        ull aa = pk2(av[i], av[i]);
        fma2(acc2[i][0], aa, b01);
        fma2(acc2[i][1], aa, b23);
      }
    }
  }

  // cross-half reduction through smem (reuse Bs as 64x68 buffer)
  float (*red)[68] = (float(*)[68])&Bs[0][0][0];
  __syncthreads();   // all compute done before red overwrites Bs
  if (h == 1) {
    #pragma unroll
    for (int i = 0; i < 8; i++) {
      float2 v01 = up2(acc2[i][0]);
      float2 v23 = up2(acc2[i][1]);
      *(float4*)&red[ty*8+i][tx*4] = make_float4(v01.x, v01.y, v23.x, v23.y);
    }
  }
  __syncthreads();
  if (h == 0) {
    #pragma unroll
    for (int i = 0; i < 8; i++) {
      int m = bm + ty*8 + i;
      float2 v01 = up2(acc2[i][0]);
      float2 v23 = up2(acc2[i][1]);
      float4 r4 = *(const float4*)&red[ty*8+i][tx*4];
      float vals[4] = {v01.x + r4.x, v01.y + r4.y, v23.x + r4.z, v23.y + r4.w};
      #pragma unroll
      for (int j = 0; j < 4; j++) {
        int n = bn + tx*4 + j;
        if (n < N) {
          float val = vals[j] + bias[n];
          if (res) val += res[(size_t)m*N + n];
          Cout[(size_t)m*N + n] = val;
        }
      }
    }
  }
}

__global__ __launch_bounds__(256) void gemm_nt(
    const float* __restrict__ A, const float* __restrict__ B,
    const float* __restrict__ bias, const float* __restrict__ res,
    float* __restrict__ Cout, int M, int N, int K) {
  gemm_body(A, B, bias, res, Cout, M, N, K, blockIdx.y*64, blockIdx.x*64);
}

__global__ __launch_bounds__(256) void gemm_qkv(
    const float* __restrict__ qkin, const float* __restrict__ t,
    const float* __restrict__ wq, const float* __restrict__ wk, const float* __restrict__ wv,
    const float* __restrict__ bq, const float* __restrict__ bk, const float* __restrict__ bv,
    float* __restrict__ q, float* __restrict__ k, float* __restrict__ v) {
  int z = blockIdx.z;
  const float* A = (z == 2) ? t : qkin;
  const float* B = (z == 0) ? wq : (z == 1 ? wk : wv);
  const float* bias = (z == 0) ? bq : (z == 1 ? bk : bv);
  float* C = (z == 0) ? q : (z == 1 ? k : v);
  gemm_body(A, B, bias, nullptr, C, LQ, CD, CD, blockIdx.y*64, blockIdx.x*64);
}

// pack [lt_wo | st_wo] into (256,512) + combined bias
__global__ __launch_bounds__(256) void pack_w(
    const float* __restrict__ lt, const float* __restrict__ st,
    const float* __restrict__ ltb, const float* __restrict__ stb,
    float* __restrict__ wcat, float* __restrict__ bcat) {
  int idx = blockIdx.x * 256 + threadIdx.x;
  int nrow = idx >> 9, k = idx & 511;
  wcat[idx] = (k < 256) ? lt[nrow*256 + k] : st[nrow*256 + k - 256];
  if (idx < 256) bcat[idx] = ltb[idx] + stb[idx];
}

// ---------------- Fused full attention, split-KV x4, f32x2, 8x4 microtile ---
// grid (25 q-tiles, 8 heads, 4 kv-splits), 128 threads.
__global__ __launch_bounds__(128) void attn_kernel(
    const float* __restrict__ Q, const float* __restrict__ Kp,
    const float* __restrict__ Vp, float* __restrict__ Opart, float2* __restrict__ ml) {
  __shared__ float Qs[HD][64];
  __shared__ float Ks[HD][64];
  __shared__ float Vs[64][34];
  __shared__ float Ps[64][68];
  const int h = blockIdx.y;
  const int z = blockIdx.z;
  const int q0 = blockIdx.x * 64;
  const int kt0 = (z == 0) ? 0 : 7 + (z - 1) * 6;
  const int kt1 = kt0 + ((z == 0) ? 7 : 6);
  const int tid = threadIdx.x;
  const int tx = tid & 15, ty = tid >> 4;   // ty 0..7

  #pragma unroll
  for (int it = 0; it < 4; it++) {
    int e = tid + it*128;
    int r = e >> 3, d4 = (e & 7) << 2;
    const float4 qv = *(const float4*)(Q + (size_t)(q0 + r)*CD + h*HD + d4);
    Qs[d4+0][r] = qv.x * QSCALE; Qs[d4+1][r] = qv.y * QSCALE;
    Qs[d4+2][r] = qv.z * QSCALE; Qs[d4+3][r] = qv.w * QSCALE;
  }
  float m_i[8], l_i[8];
  ull oa2[8];
  #pragma unroll
  for (int i = 0; i < 8; i++) { m_i[i] = -1e30f; l_i[i] = 0.f; oa2[i] = 0ull; }

  for (int kt = kt0; kt < kt1; kt++) {
    const int k0 = kt * 64;
    #pragma unroll
    for (int it = 0; it < 4; it++) {
      int e = tid + it*128;
      int r = e >> 3, d4 = (e & 7) << 2;
      const float4 kv = *(const float4*)(Kp + (size_t)(k0 + r)*CD + h*HD + d4);
      Ks[d4+0][r] = kv.x; Ks[d4+1][r] = kv.y; Ks[d4+2][r] = kv.z; Ks[d4+3][r] = kv.w;
      const float4 vv = *(const float4*)(Vp + (size_t)(k0 + r)*CD + h*HD + d4);
      Vs[r][d4+0] = vv.x; Vs[r][d4+1] = vv.y; Vs[r][d4+2] = vv.z; Vs[r][d4+3] = vv.w;
    }
    __syncthreads();
    // --- QK^T: 8 rows x 4 keys per thread, packed pairs over keys ---
    ull s2[8][2] = {};
    #pragma unroll
    for (int d = 0; d < HD; d++) {
      float4 a4a = *(const float4*)&Qs[d][ty*8];
      float4 a4b = *(const float4*)&Qs[d][ty*8+4];
      const ull* bp = (const ull*)&Ks[d][tx*4];
      ull b01 = bp[0], b23 = bp[1];
      float av[8] = {a4a.x, a4a.y, a4a.z, a4a.w, a4b.x, a4b.y, a4b.z, a4b.w};
      #pragma unroll
      for (int i = 0; i < 8; i++) {
        ull aa = pk2(av[i], av[i]);
        fma2(s2[i][0], aa, b01);
        fma2(s2[i][1], aa, b23);
      }
    }
    // --- online softmax ---
    #pragma unroll
    for (int i = 0; i < 8; i++) {
      float2 s01 = up2(s2[i][0]);
      float2 s23 = up2(s2[i][1]);
      float sv[4] = {s01.x, s01.y, s23.x, s23.y};
      float rm = fmaxf(fmaxf(sv[0], sv[1]), fmaxf(sv[2], sv[3]));
      #pragma unroll
      for (int o = 8; o; o >>= 1) rm = fmaxf(rm, __shfl_xor_sync(0xffffffffu, rm, o));
      float mnew = fmaxf(m_i[i], rm);
      float alpha = __expf(m_i[i] - mnew);
      float p0 = __expf(sv[0] - mnew);
      float p1 = __expf(sv[1] - mnew);
      float p2 = __expf(sv[2] - mnew);
      float p3 = __expf(sv[3] - mnew);
      *(float4*)&Ps[ty*8+i][tx*4] = make_float4(p0, p1, p2, p3);
      float rs = (p0 + p1) + (p2 + p3);
      #pragma unroll
      for (int o = 8; o; o >>= 1) rs += __shfl_xor_sync(0xffffffffu, rs, o);
      l_i[i] = l_i[i]*alpha + rs;
      m_i[i] = mnew;
      mul2(oa2[i], pk2(alpha, alpha));
    }
    __syncthreads();
    // --- P @ V ---
    #pragma unroll 2
    for (int k4 = 0; k4 < 16; k4++) {
      float4 p4[8];
      #pragma unroll
      for (int i = 0; i < 8; i++) p4[i] = *(const float4*)&Ps[ty*8+i][k4*4];
      #pragma unroll
      for (int t = 0; t < 4; t++) {
        ull v2 = *(const ull*)&Vs[k4*4+t][tx*2];
        #pragma unroll
        for (int i = 0; i < 8; i++) {
          float p = (&p4[i].x)[t];
          fma2(oa2[i], pk2(p, p), v2);
        }
      }
    }
    __syncthreads();
  }
  #pragma unroll
  for (int i = 0; i < 8; i++) {
    int row = q0 + ty*8 + i;
    float2 o2 = up2(oa2[i]);
    Opart[((size_t)z*LQ + row)*CD + h*HD + tx*2+0] = o2.x;
    Opart[((size_t)z*LQ + row)*CD + h*HD + tx*2+1] = o2.y;
    if (tx == 0) ml[(z*LQ + row)*NHD + h] = make_float2(m_i[i], l_i[i]);
  }
}

// merge the 4 kv-splits
__global__ __launch_bounds__(256) void attn_merge(
    const float* __restrict__ Opart, const float2* __restrict__ ml,
    float* __restrict__ O, int ostride, int ooff) {
  int row = blockIdx.x, c = threadIdx.x;
  int h = c >> 5;
  float2 mlp[NSPLIT];
  float m = -1e30f;
  #pragma unroll
  for (int p = 0; p < NSPLIT; p++) {
    mlp[p] = ml[(p*LQ + row)*NHD + h];
    m = fmaxf(m, mlp[p].x);
  }
  float l = 0.f, o = 0.f;
  #pragma unroll
  for (int p = 0; p < NSPLIT; p++) {
    float e = __expf(mlp[p].x - m);
    l += mlp[p].y * e;
    o += Opart[((size_t)p*LQ + row)*CD + c] * e;
  }
  O[(size_t)row*ostride + ooff + c] = o / l;
}

// ---------------- curr_Q / global_K / global_V construction ----------------
__global__ __launch_bounds__(256) void make_kv_kernel(
    const float* __restrict__ qv, const float* __restrict__ idkv,
    float* __restrict__ q, float* __restrict__ gK, float* __restrict__ gV) {
  int l = blockIdx.x, c = threadIdx.x;
  float cq  = qv[(size_t)l*512 + c];
  float cv  = qv[(size_t)l*512 + 256 + c];
  float idk = idkv[(size_t)l*264 + (c >> 5)];
  float idv = idkv[(size_t)l*264 + 8 + c];
  q [(size_t)l*CD + c] = cq;
  gK[(size_t)l*CD + c] = cq * (1.f + tanhf(idk));
  gV[(size_t)l*CD + c] = cv + idv;
}

// ---------------- Local 15x15 window attention ----------------
__global__ __launch_bounds__(256) void local_attn_kernel(
    const float* __restrict__ Q, const float* __restrict__ Kp,
    const float* __restrict__ Vp, float* __restrict__ O, int ostride, int ooff) {
  __shared__ float p_sh[8][232];
  int n = blockIdx.x;
  int r = n / GW, c = n % GW;
  int h = threadIdx.x >> 5, lane = threadIdx.x & 31;

  const float* qp = Q + (size_t)n*CD + h*HD;
  float4 qreg[8];
  #pragma unroll
  for (int i = 0; i < 8; i++) {
    qreg[i] = *(const float4*)(qp + i*4);
    qreg[i].x *= QSCALE; qreg[i].y *= QSCALE; qreg[i].z *= QSCALE; qreg[i].w *= QSCALE;
  }
  int i0 = max(7 - r, 0), i1 = min(GH + 7 - r, 15);
  int j0 = max(7 - c, 0), j1 = min(GW + 7 - c, 15);

  for (int w = lane; w < 225; w += 32) {
    int wi = w / 15, wj = w - wi*15;
    float logit = -1e30f;
    if (wi >= i0 && wi < i1 && wj >= j0 && wj < j1) {
      const float* kp = Kp + (size_t)((r+wi-7)*GW + (c+wj-7))*CD + h*HD;
      float acc = 0.f;
      #pragma unroll
      for (int i4 = 0; i4 < 8; i4++) {
        float4 kv = *(const float4*)(kp + i4*4);
        acc = fmaf(qreg[i4].x, kv.x, acc);
        acc = fmaf(qreg[i4].y, kv.y, acc);
        acc = fmaf(qreg[i4].z, kv.z, acc);
        acc = fmaf(qreg[i4].w, kv.w, acc);
      }
      logit = acc;
    }
    p_sh[h][w] = logit;
  }
  __syncwarp();
  float m = -1e30f;
  for (int ww = lane; ww < 225; ww += 32) m = fmaxf(m, p_sh[h][ww]);
  #pragma unroll
  for (int o = 16; o; o >>= 1) m = fmaxf(m, __shfl_xor_sync(0xffffffffu, m, o));
  float ssum = 0.f;
  for (int ww = lane; ww < 225; ww += 32) {
    float p = __expf(p_sh[h][ww] - m);
    p_sh[h][ww] = p;
    ssum += p;
  }
  #pragma unroll
  for (int o = 16; o; o >>= 1) ssum += __shfl_xor_sync(0xffffffffu, ssum, o);
  float inv = 1.f / ssum;
  __syncwarp();
  float oacc = 0.f;
  for (int wi = i0; wi < i1; wi++) {
    const float* vrow = Vp + (size_t)((r+wi-7)*GW + (c+j0-7))*CD + h*HD + lane;
    #pragma unroll 3
    for (int wj = j0; wj < j1; wj++, vrow += CD)
      oacc = fmaf(p_sh[h][wi*15+wj], *vrow, oacc);
  }
  O[(size_t)n*ostride + ooff + h*HD + lane] = oacc * inv;
}

// ---------------- GroupNorm stats ----------------
__global__ __launch_bounds__(1024) void gn_stats_kernel(
    const float* __restrict__ x, float* __restrict__ stats) {
  int g = blockIdx.x;
  float s = 0.f, s2 = 0.f;
  for (int idx = threadIdx.x; idx < LQ*32; idx += 1024) {
    int l = idx >> 5, ch = idx & 31;
    float v = x[(size_t)l*DFF + g*32 + ch];
    s += v; s2 += v*v;
  }
  #pragma unroll
  for (int o = 16; o; o >>= 1) {
    s  += __shfl_xor_sync(0xffffffffu, s,  o);
    s2 += __shfl_xor_sync(0xffffffffu, s2, o);
  }
  __shared__ float sh[32], sh2[32];
  int w = threadIdx.x >> 5, lane = threadIdx.x & 31;
  if (lane == 0) { sh[w] = s; sh2[w] = s2; }
  __syncthreads();
  if (w == 0) {
    s = sh[lane]; s2 = sh2[lane];
    #pragma unroll
    for (int o = 16; o; o >>= 1) {
      s  += __shfl_xor_sync(0xffffffffu, s,  o);
      s2 += __shfl_xor_sync(0xffffffffu, s2, o);
    }
    if (lane == 0) {
      const float invn = 1.f / (LQ * 32.f);
      float mean = s * invn;
      float var  = s2 * invn - mean*mean;
      stats[g*2]   = mean;
      stats[g*2+1] = rsqrtf(var + EPSV);
    }
  }
}

// ---------------- GN apply + exact GELU ----------------
__global__ __launch_bounds__(256) void gn_gelu_kernel(
    const float* __restrict__ x, const float* __restrict__ gg, const float* __restrict__ gb,
    const float* __restrict__ stats, float* __restrict__ y) {
  int idx = blockIdx.x * 256 + threadIdx.x;
  int ch = idx & (DFF-1);
  int g = ch >> 5;
  float v = (x[idx] - stats[g*2]) * stats[g*2+1] * gg[ch] + gb[ch];
  y[idx] = 0.5f * v * (1.f + erff(v * 0.70710678118654752f));
}

// ---------------- 5x5 depthwise conv, pad 2 ----------------
__global__ __launch_bounds__(256) void dwconv_kernel(
    const float* __restrict__ x, const float* __restrict__ kern, float* __restrict__ y) {
  __shared__ float tile[12][12][32];
  __shared__ float kw[32][25];
  int tid = threadIdx.x;
  int ch0 = blockIdx.z * 32;
  int r0 = blockIdx.y * 8 - 2, c0 = blockIdx.x * 8 - 2;
  for (int e = tid; e < 12*12*32; e += 256) {
    int ch = e & 31;
    int sp = e >> 5;
    int ri = sp / 12, ci = sp % 12;
    int rr = r0 + ri, cc = c0 + ci;
    float v = 0.f;
    if ((unsigned)rr < (unsigned)GH && (unsigned)cc < (unsigned)GW)
      v = x[(size_t)(rr*GW + cc)*DFF + ch0 + ch];
    tile[ri][ci][ch] = v;
  }
  for (int e = tid; e < 32*25; e += 256)
    kw[e/25][e%25] = kern[(size_t)(ch0 + e/25)*25 + e%25];
  __syncthreads();
  for (int e = tid; e < 8*8*32; e += 256) {
    int ch = e & 31;
    int sp = e >> 5;
    int ri = sp >> 3, ci = sp & 7;
    float acc = 0.f;
    #pragma unroll
    for (int i = 0; i < 5; i++)
      #pragma unroll
      for (int j = 0; j < 5; j++)
        acc = fmaf(tile[ri+i][ci+j][ch], kw[ch][i*5+j], acc);
    int rr = blockIdx.y*8 + ri, cc = blockIdx.x*8 + ci;
    y[(size_t)(rr*GW + cc)*DFF + ch0 + ch] = acc;
  }
}

// ---------------- launcher ----------------
extern "C" void kernel_launch(void* const* d_in, const int* in_sizes, int n_in,
                              void* d_out, int out_size) {
  const float* in_tgt   = (const float*)d_in[0];
  const float* id_emb   = (const float*)d_in[1];
  const float* self_pos = (const float*)d_in[2];
  const float* ln1_g = (const float*)d_in[3];
  const float* ln1_b = (const float*)d_in[4];
  const float* sa_wq = (const float*)d_in[5];
  const float* sa_bq = (const float*)d_in[6];
  const float* sa_wk = (const float*)d_in[7];
  const float* sa_bk = (const float*)d_in[8];
  const float* sa_wv = (const float*)d_in[9];
  const float* sa_bv = (const float*)d_in[10];
  const float* sa_wo = (const float*)d_in[11];
  const float* sa_bo = (const float*)d_in[12];
  const float* ln2_g = (const float*)d_in[13];
  const float* ln2_b = (const float*)d_in[14];
  const float* w_qv = (const float*)d_in[15];
  const float* b_qv = (const float*)d_in[16];
  const float* w_id = (const float*)d_in[17];
  const float* b_id = (const float*)d_in[18];
  const float* lt_wo = (const float*)d_in[19];
  const float* lt_bo = (const float*)d_in[20];
  const float* st_wo = (const float*)d_in[21];
  const float* st_bo = (const float*)d_in[22];
  const float* ln3_g = (const float*)d_in[23];
  const float* ln3_b = (const float*)d_in[24];
  const float* w1 = (const float*)d_in[25];
  const float* b1 = (const float*)d_in[26];
  const float* gn_g = (const float*)d_in[27];
  const float* gn_b = (const float*)d_in[28];
  const float* dw_k = (const float*)d_in[29];
  const float* w2 = (const float*)d_in[30];
  const float* b2 = (const float*)d_in[31];
  float* out = (float*)d_out;

  float *t, *qkin, *q, *k, *v, *attcat, *tgtb, *qv, *idkv, *gK, *gV, *x, *x2, *stats, *wcat, *bcat, *opart;
  float2 *ml;
  cudaGetSymbolAddress((void**)&t,      g_t);
  cudaGetSymbolAddress((void**)&qkin,   g_qkin);
  cudaGetSymbolAddress((void**)&q,      g_q);
  cudaGetSymbolAddress((void**)&k,      g_k);
  cudaGetSymbolAddress((void**)&v,      g_v);
  cudaGetSymbolAddress((void**)&attcat, g_attcat);
  cudaGetSymbolAddress((void**)&tgtb,   g_tgt);
  cudaGetSymbolAddress((void**)&qv,     g_qv);
  cudaGetSymbolAddress((void**)&idkv,   g_idkv);
  cudaGetSymbolAddress((void**)&gK,     g_gK);
  cudaGetSymbolAddress((void**)&gV,     g_gV);
  cudaGetSymbolAddress((void**)&x,      g_x);
  cudaGetSymbolAddress((void**)&x2,     g_x2);
  cudaGetSymbolAddress((void**)&stats,  g_stats);
  cudaGetSymbolAddress((void**)&wcat,   g_wcat);
  cudaGetSymbolAddress((void**)&bcat,   g_bcat);
  cudaGetSymbolAddress((void**)&opart,  g_opart);
  cudaGetSymbolAddress((void**)&ml,     g_ml);

  dim3 g66(4, 25);
  dim3 gQKV(4, 25, 3);
  dim3 gAttn(25, 8, NSPLIT);

  pack_w<<<512,256>>>(lt_wo, st_wo, lt_bo, st_bo, wcat, bcat);
  cudaMemcpyAsync(tgtb, in_tgt, sizeof(float)*LQ*CD, cudaMemcpyDeviceToDevice, 0);

  // --- self attention ---
  ln_kernel<<<LQ,256>>>(in_tgt, ln1_g, ln1_b, t, self_pos, qkin);
  gemm_qkv<<<gQKV,256>>>(qkin, t, sa_wq, sa_wk, sa_wv, sa_bq, sa_bk, sa_bv, q, k, v);
  attn_kernel<<<gAttn,128>>>(q, k, v, opart, ml);
  attn_merge<<<LQ,256>>>(opart, ml, attcat, 256, 0);
  gemm_nt<<<g66,256>>>(attcat, sa_wo, sa_bo, tgtb, tgtb, LQ, CD, CD);

  // --- long/short term attention ---
  ln_kernel<<<LQ,256>>>(tgtb, ln2_g, ln2_b, t, nullptr, nullptr);
  gemm_nt<<<dim3(8,25),256>>>(t, w_qv, b_qv, nullptr, qv, LQ, 512, CD);
  gemm_nt<<<dim3(5,25),256>>>(id_emb, w_id, b_id, nullptr, idkv, LQ, 264, CD);
  make_kv_kernel<<<LQ,256>>>(qv, idkv, q, gK, gV);
  attn_kernel<<<gAttn,128>>>(q, gK, gV, opart, ml);
  attn_merge<<<LQ,256>>>(opart, ml, attcat, 512, 0);
  local_attn_kernel<<<LQ,256>>>(q, gK, gV, attcat, 512, 256);
  gemm_nt<<<g66,256>>>(attcat, wcat, bcat, tgtb, tgtb, LQ, CD, 512);

  // --- MLP: LN -> w1 -> GN -> GELU -> dwconv -> w2 ---
  ln_kernel<<<LQ,256>>>(tgtb, ln3_g, ln3_b, t, nullptr, nullptr);
  gemm_nt<<<dim3(16,25),256>>>(t, w1, b1, nullptr, x, LQ, DFF, CD);
  gn_stats_kernel<<<32,1024>>>(x, stats);
  gn_gelu_kernel<<<(LQ*DFF)/256,256>>>(x, gn_g, gn_b, stats, x2);
  dwconv_kernel<<<dim3(5,5,32),256>>>(x2, dw_k, x);
  gemm_nt<<<g66,256>>>(x, w2, b2, tgtb, out, LQ, CD, DFF);
}

// round 9
// speedup vs baseline: 1.6400x; 1.1189x over previous
#include <cuda_runtime.h>
#include <math.h>

#define LQ 1600
#define CD 256
#define NHD 8
#define HD 32
#define DFF 1024
#define GH 40
#define GW 40
#define EPSV 1e-5f
#define QSCALE 0.17677669529663687f  // 1/sqrt(32)
#define NSPLIT 3

typedef unsigned long long ull;

// ---------------- f32x2 packed math helpers ----------------
__device__ __forceinline__ ull pk2(float x, float y) {
  ull r; asm("mov.b64 %0, {%1, %2};" : "=l"(r) : "f"(x), "f"(y)); return r;
}
__device__ __forceinline__ float2 up2(ull v) {
  float lo, hi; asm("mov.b64 {%0, %1}, %2;" : "=f"(lo), "=f"(hi) : "l"(v));
  return make_float2(lo, hi);
}
__device__ __forceinline__ void fma2(ull &d, ull a, ull b) {
  asm("fma.rn.f32x2 %0, %1, %2, %0;" : "+l"(d) : "l"(a), "l"(b));
}

// ---------------- tf32 mma helpers ----------------
__device__ __forceinline__ unsigned tf32r(float x) {
  unsigned u; asm("cvt.rna.tf32.f32 %0, %1;" : "=r"(u) : "f"(x)); return u;
}
__device__ __forceinline__ void mma_tf32(float* d, const unsigned* a, unsigned b0, unsigned b1) {
  asm("mma.sync.aligned.m16n8k8.row.col.f32.tf32.tf32.f32 "
      "{%0,%1,%2,%3}, {%4,%5,%6,%7}, {%8,%9}, {%0,%1,%2,%3};"
      : "+f"(d[0]), "+f"(d[1]), "+f"(d[2]), "+f"(d[3])
      : "r"(a[0]), "r"(a[1]), "r"(a[2]), "r"(a[3]), "r"(b0), "r"(b1));
}

// ---------------- scratch (device globals; no allocation) ----------------
static __device__ float g_t[LQ*CD];
static __device__ float g_qkin[LQ*CD];
static __device__ float g_q[LQ*CD];
static __device__ float g_k[LQ*CD];
static __device__ float g_v[LQ*CD];
static __device__ float g_attcat[LQ*512];
static __device__ float g_tgt[LQ*CD];
static __device__ float g_qv[LQ*2*CD];
static __device__ float g_idkv[LQ*264];
static __device__ float g_gK[LQ*CD];
static __device__ float g_gV[LQ*CD];
static __device__ float g_x[LQ*DFF];
static __device__ float g_x2[LQ*DFF];
static __device__ float g_stats[64];
static __device__ float g_wcat[256*512];
static __device__ float g_bcat[256];
static __device__ float g_opart[NSPLIT*LQ*CD];
static __device__ float2 g_ml[NSPLIT*LQ*NHD];

// ---------------- LayerNorm (optionally + pos add) ----------------
__global__ __launch_bounds__(256) void ln_kernel(
    const float* __restrict__ x, const float* __restrict__ g, const float* __restrict__ b,
    float* __restrict__ y, const float* __restrict__ pos, float* __restrict__ qkout) {
  int l = blockIdx.x;
  int c = threadIdx.x;
  float v = x[(size_t)l*CD + c];
  float s = v, s2 = v*v;
  #pragma unroll
  for (int o = 16; o; o >>= 1) {
    s  += __shfl_xor_sync(0xffffffffu, s,  o);
    s2 += __shfl_xor_sync(0xffffffffu, s2, o);
  }
  __shared__ float sh[8], sh2[8], smv[2];
  int w = c >> 5, lane = c & 31;
  if (lane == 0) { sh[w] = s; sh2[w] = s2; }
  __syncthreads();
  if (c == 0) {
    float a = 0.f, a2 = 0.f;
    #pragma unroll
    for (int i = 0; i < 8; i++) { a += sh[i]; a2 += sh2[i]; }
    float mean = a * (1.0f/CD);
    float var  = a2 * (1.0f/CD) - mean*mean;
    smv[0] = mean; smv[1] = rsqrtf(var + EPSV);
  }
  __syncthreads();
  float out = (v - smv[0]) * smv[1] * g[c] + b[c];
  y[(size_t)l*CD + c] = out;
  if (qkout) qkout[(size_t)l*CD + c] = out + pos[(size_t)l*CD + c];
}

// ---------------- GEMM core (f32x2, intra-CTA split-K x2) -------------------
__device__ __forceinline__ void gemm_body(
    const float* __restrict__ A, const float* __restrict__ B,
    const float* __restrict__ bias, const float* __restrict__ res,
    float* __restrict__ Cout, int M, int N, int K, int bm, int bn) {
  __shared__ float As[2][32][68];
  __shared__ float Bs[2][32][68];
  const int tid = threadIdx.x;
  const int h = tid >> 7;
  const int htid = tid & 127;
  const int tx = htid & 15, ty = htid >> 4;
  const int lr = htid >> 1;
  const int lc = (htid & 1) << 4;
  ull acc2[8][2] = {};
  const int nk = K >> 5;
  const int nh = nk >> 1;

  float4 a[4], b[4];
  const bool bok = (bn + lr) < N;
  {
    const int k0 = (h * nh) << 5;
    const float* Ap = A + (size_t)(bm + lr)*K + k0 + lc;
    const float* Bp = B + (size_t)(bn + lr)*K + k0 + lc;
    #pragma unroll
    for (int u = 0; u < 4; u++) {
      a[u] = *(const float4*)(Ap + u*4);
      b[u] = bok ? *(const float4*)(Bp + u*4) : make_float4(0.f,0.f,0.f,0.f);
    }
  }

  for (int c = 0; c < nh; c++) {
    __syncthreads();
    #pragma unroll
    for (int u = 0; u < 4; u++) {
      int kk = lc + u*4;
      As[h][kk+0][lr]=a[u].x; As[h][kk+1][lr]=a[u].y; As[h][kk+2][lr]=a[u].z; As[h][kk+3][lr]=a[u].w;
      Bs[h][kk+0][lr]=b[u].x; Bs[h][kk+1][lr]=b[u].y; Bs[h][kk+2][lr]=b[u].z; Bs[h][kk+3][lr]=b[u].w;
    }
    __syncthreads();
    if (c + 1 < nh) {
      const int k0 = (h * nh + c + 1) << 5;
      const float* Ap = A + (size_t)(bm + lr)*K + k0 + lc;
      const float* Bp = B + (size_t)(bn + lr)*K + k0 + lc;
      #pragma unroll
      for (int u = 0; u < 4; u++) {
        a[u] = *(const float4*)(Ap + u*4);
        b[u] = bok ? *(const float4*)(Bp + u*4) : make_float4(0.f,0.f,0.f,0.f);
      }
    }
    #pragma unroll
    for (int kk = 0; kk < 32; kk++) {
      float4 a4a = *(const float4*)&As[h][kk][ty*8];
      float4 a4b = *(const float4*)&As[h][kk][ty*8+4];
      const ull* bp = (const ull*)&Bs[h][kk][tx*4];
      ull b01 = bp[0], b23 = bp[1];
      float av[8] = {a4a.x, a4a.y, a4a.z, a4a.w, a4b.x, a4b.y, a4b.z, a4b.w};
      #pragma unroll
      for (int i = 0; i < 8; i++) {
        ull aa = pk2(av[i], av[i]);
        fma2(acc2[i][0], aa, b01);
        fma2(acc2[i][1], aa, b23);
      }
    }
  }

  float (*red)[68] = (float(*)[68])&Bs[0][0][0];
  __syncthreads();
  if (h == 1) {
    #pragma unroll
    for (int i = 0; i < 8; i++) {
      float2 v01 = up2(acc2[i][0]);
      float2 v23 = up2(acc2[i][1]);
      *(float4*)&red[ty*8+i][tx*4] = make_float4(v01.x, v01.y, v23.x, v23.y);
    }
  }
  __syncthreads();
  if (h == 0) {
    #pragma unroll
    for (int i = 0; i < 8; i++) {
      int m = bm + ty*8 + i;
      float2 v01 = up2(acc2[i][0]);
      float2 v23 = up2(acc2[i][1]);
      float4 r4 = *(const float4*)&red[ty*8+i][tx*4];
      float vals[4] = {v01.x + r4.x, v01.y + r4.y, v23.x + r4.z, v23.y + r4.w};
      #pragma unroll
      for (int j = 0; j < 4; j++) {
        int n = bn + tx*4 + j;
        if (n < N) {
          float val = vals[j] + bias[n];
          if (res) val += res[(size_t)m*N + n];
          Cout[(size_t)m*N + n] = val;
        }
      }
    }
  }
}

__global__ __launch_bounds__(256) void gemm_nt(
    const float* __restrict__ A, const float* __restrict__ B,
    const float* __restrict__ bias, const float* __restrict__ res,
    float* __restrict__ Cout, int M, int N, int K) {
  gemm_body(A, B, bias, res, Cout, M, N, K, blockIdx.y*64, blockIdx.x*64);
}

__global__ __launch_bounds__(256) void gemm_qkv(
    const float* __restrict__ qkin, const float* __restrict__ t,
    const float* __restrict__ wq, const float* __restrict__ wk, const float* __restrict__ wv,
    const float* __restrict__ bq, const float* __restrict__ bk, const float* __restrict__ bv,
    float* __restrict__ q, float* __restrict__ k, float* __restrict__ v) {
  int z = blockIdx.z;
  const float* A = (z == 2) ? t : qkin;
  const float* B = (z == 0) ? wq : (z == 1 ? wk : wv);
  const float* bias = (z == 0) ? bq : (z == 1 ? bk : bv);
  float* C = (z == 0) ? q : (z == 1 ? k : v);
  gemm_body(A, B, bias, nullptr, C, LQ, CD, CD, blockIdx.y*64, blockIdx.x*64);
}

// pack [lt_wo | st_wo] into (256,512) + combined bias
__global__ __launch_bounds__(256) void pack_w(
    const float* __restrict__ lt, const float* __restrict__ st,
    const float* __restrict__ ltb, const float* __restrict__ stb,
    float* __restrict__ wcat, float* __restrict__ bcat) {
  int idx = blockIdx.x * 256 + threadIdx.x;
  int nrow = idx >> 9, k = idx & 511;
  wcat[idx] = (k < 256) ? lt[nrow*256 + k] : st[nrow*256 + k - 256];
  if (idx < 256) bcat[idx] = ltb[idx] + stb[idx];
}

// ---------------- Fused full attention: tf32 mma (3xTF32), split-KV x3 ------
// grid (25 q-tiles, 8 heads, 3 kv-splits), 128 threads (4 warps x 16 q-rows).
// Shared: Vs hi/lo [64][40]; K region [64][40] x2 reused as P tile [64][68].
__global__ __launch_bounds__(128, 4) void attn_kernel(
    const float* __restrict__ Q, const float* __restrict__ Kp,
    const float* __restrict__ Vp, float* __restrict__ Opart, float2* __restrict__ ml) {
  __shared__ float Vs_hi[64][40];
  __shared__ float Vs_lo[64][40];
  __shared__ float uKP[5120];   // Ks_hi [64][40] | Ks_lo +2560 ; reused as Ps[64][68]
  #define KS_HI(kk,dd) uKP[(kk)*40 + (dd)]
  #define KS_LO(kk,dd) uKP[2560 + (kk)*40 + (dd)]
  #define PS(rr,cc)    uKP[(rr)*68 + (cc)]

  const int h = blockIdx.y;
  const int z = blockIdx.z;
  const int q0 = blockIdx.x * 64;
  const int kt0 = (z == 0) ? 0 : 9 + (z - 1) * 8;
  const int kt1 = (z == 0) ? 9 : kt0 + 8;
  const int tid = threadIdx.x;
  const int w = tid >> 5, lane = tid & 31;
  const int g = lane >> 2, t = lane & 3;
  const int qb = q0 + w*16;

  // --- Q fragments (hi/lo tf32), loaded once ---
  unsigned qhi[4][4], qlo[4][4];
  #pragma unroll
  for (int s = 0; s < 4; s++) {
    const int k0 = s*8;
    float f[4];
    f[0] = Q[(size_t)(qb+g  )*CD + h*HD + k0 + t    ] * QSCALE;
    f[1] = Q[(size_t)(qb+g+8)*CD + h*HD + k0 + t    ] * QSCALE;
    f[2] = Q[(size_t)(qb+g  )*CD + h*HD + k0 + t + 4] * QSCALE;
    f[3] = Q[(size_t)(qb+g+8)*CD + h*HD + k0 + t + 4] * QSCALE;
    #pragma unroll
    for (int i = 0; i < 4; i++) {
      qhi[s][i] = tf32r(f[i]);
      qlo[s][i] = tf32r(f[i] - __uint_as_float(qhi[s][i]));
    }
  }

  float m_i[2] = {-1e30f, -1e30f};
  float l_i[2] = {0.f, 0.f};
  float oacc[4][4] = {};

  for (int kt = kt0; kt < kt1; kt++) {
    const int kb = kt * 64;
    __syncthreads();   // prior tile fully consumed (PV reads Vs, Ps in uKP)
    // --- producer: K/V tile -> smem with tf32 hi/lo split ---
    #pragma unroll
    for (int it = 0; it < 4; it++) {
      int idx = tid + it*128;
      int r = idx >> 3, d4 = (idx & 7) << 2;
      float4 kv = *(const float4*)(Kp + (size_t)(kb + r)*CD + h*HD + d4);
      float4 vv = *(const float4*)(Vp + (size_t)(kb + r)*CD + h*HD + d4);
      float kf[4] = {kv.x, kv.y, kv.z, kv.w};
      float vf[4] = {vv.x, vv.y, vv.z, vv.w};
      float khi[4], klo[4], vhi[4], vlo[4];
      #pragma unroll
      for (int j = 0; j < 4; j++) {
        unsigned u1 = tf32r(kf[j]);
        khi[j] = __uint_as_float(u1);
        klo[j] = __uint_as_float(tf32r(kf[j] - khi[j]));
        unsigned u2 = tf32r(vf[j]);
        vhi[j] = __uint_as_float(u2);
        vlo[j] = __uint_as_float(tf32r(vf[j] - vhi[j]));
      }
      *(float4*)&KS_HI(r, d4) = make_float4(khi[0], khi[1], khi[2], khi[3]);
      *(float4*)&KS_LO(r, d4) = make_float4(klo[0], klo[1], klo[2], klo[3]);
      *(float4*)&Vs_hi[r][d4] = make_float4(vhi[0], vhi[1], vhi[2], vhi[3]);
      *(float4*)&Vs_lo[r][d4] = make_float4(vlo[0], vlo[1], vlo[2], vlo[3]);
    }
    __syncthreads();

    // --- QK^T: S[16 x 64] per warp via 3xTF32 mma ---
    float sacc[8][4];
    #pragma unroll
    for (int n = 0; n < 8; n++)
      #pragma unroll
      for (int i = 0; i < 4; i++) sacc[n][i] = 0.f;
    #pragma unroll
    for (int n = 0; n < 8; n++) {
      #pragma unroll
      for (int s = 0; s < 4; s++) {
        unsigned bh0 = __float_as_uint(KS_HI(n*8+g, s*8+t));
        unsigned bh1 = __float_as_uint(KS_HI(n*8+g, s*8+t+4));
        unsigned bl0 = __float_as_uint(KS_LO(n*8+g, s*8+t));
        unsigned bl1 = __float_as_uint(KS_LO(n*8+g, s*8+t+4));
        mma_tf32(sacc[n], qhi[s], bh0, bh1);
        mma_tf32(sacc[n], qhi[s], bl0, bl1);
        mma_tf32(sacc[n], qlo[s], bh0, bh1);
      }
    }
    __syncthreads();   // all warps done reading Ks before Ps overwrites uKP

    // --- online softmax (rows g and g+8 of this warp's 16) ---
    #pragma unroll
    for (int ri = 0; ri < 2; ri++) {
      float rm = -1e30f;
      #pragma unroll
      for (int n = 0; n < 8; n++)
        rm = fmaxf(rm, fmaxf(sacc[n][2*ri], sacc[n][2*ri+1]));
      rm = fmaxf(rm, __shfl_xor_sync(0xffffffffu, rm, 1));
      rm = fmaxf(rm, __shfl_xor_sync(0xffffffffu, rm, 2));
      float mnew = fmaxf(m_i[ri], rm);
      float alpha = __expf(m_i[ri] - mnew);
      float rs = 0.f;
      int prow = w*16 + g + ri*8;
      #pragma unroll
      for (int n = 0; n < 8; n++) {
        float p0 = __expf(sacc[n][2*ri]   - mnew);
        float p1 = __expf(sacc[n][2*ri+1] - mnew);
        *(float2*)&PS(prow, n*8 + 2*t) = make_float2(p0, p1);
        rs += p0 + p1;
      }
      rs += __shfl_xor_sync(0xffffffffu, rs, 1);
      rs += __shfl_xor_sync(0xffffffffu, rs, 2);
      l_i[ri] = l_i[ri]*alpha + rs;
      m_i[ri] = mnew;
      #pragma unroll
      for (int n = 0; n < 4; n++) { oacc[n][2*ri] *= alpha; oacc[n][2*ri+1] *= alpha; }
    }
    __syncwarp();

    // --- P @ V via 3xTF32 mma ---
    #pragma unroll
    for (int kk = 0; kk < 8; kk++) {
      float pf[4];
      pf[0] = PS(w*16 + g,     kk*8 + t);
      pf[1] = PS(w*16 + g + 8, kk*8 + t);
      pf[2] = PS(w*16 + g,     kk*8 + t + 4);
      pf[3] = PS(w*16 + g + 8, kk*8 + t + 4);
      unsigned ahi[4], alo[4];
      #pragma unroll
      for (int i = 0; i < 4; i++) {
        ahi[i] = tf32r(pf[i]);
        alo[i] = tf32r(pf[i] - __uint_as_float(ahi[i]));
      }
      #pragma unroll
      for (int n = 0; n < 4; n++) {
        unsigned bh0 = __float_as_uint(Vs_hi[kk*8+t  ][n*8+g]);
        unsigned bh1 = __float_as_uint(Vs_hi[kk*8+t+4][n*8+g]);
        unsigned bl0 = __float_as_uint(Vs_lo[kk*8+t  ][n*8+g]);
        unsigned bl1 = __float_as_uint(Vs_lo[kk*8+t+4][n*8+g]);
        mma_tf32(oacc[n], ahi, bh0, bh1);
        mma_tf32(oacc[n], ahi, bl0, bl1);
        mma_tf32(oacc[n], alo, bh0, bh1);
      }
    }
  }

  // --- epilogue: unnormalized partials + (m,l) ---
  #pragma unroll
  for (int n = 0; n < 4; n++) {
    *(float2*)&Opart[((size_t)z*LQ + qb + g    )*CD + h*HD + n*8 + 2*t] =
        make_float2(oacc[n][0], oacc[n][1]);
    *(float2*)&Opart[((size_t)z*LQ + qb + g + 8)*CD + h*HD + n*8 + 2*t] =
        make_float2(oacc[n][2], oacc[n][3]);
  }
  if (t == 0) {
    ml[(z*LQ + qb + g    )*NHD + h] = make_float2(m_i[0], l_i[0]);
    ml[(z*LQ + qb + g + 8)*NHD + h] = make_float2(m_i[1], l_i[1]);
  }
  #undef KS_HI
  #undef KS_LO
  #undef PS
}

// merge the kv-splits
__global__ __launch_bounds__(256) void attn_merge(
    const float* __restrict__ Opart, const float2* __restrict__ ml,
    float* __restrict__ O, int ostride, int ooff) {
  int row = blockIdx.x, c = threadIdx.x;
  int h = c >> 5;
  float2 mlp[NSPLIT];
  float m = -1e30f;
  #pragma unroll
  for (int p = 0; p < NSPLIT; p++) {
    mlp[p] = ml[(p*LQ + row)*NHD + h];
    m = fmaxf(m, mlp[p].x);
  }
  float l = 0.f, o = 0.f;
  #pragma unroll
  for (int p = 0; p < NSPLIT; p++) {
    float e = __expf(mlp[p].x - m);
    l += mlp[p].y * e;
    o += Opart[((size_t)p*LQ + row)*CD + c] * e;
  }
  O[(size_t)row*ostride + ooff + c] = o / l;
}

// ---------------- curr_Q / global_K / global_V construction ----------------
__global__ __launch_bounds__(256) void make_kv_kernel(
    const float* __restrict__ qv, const float* __restrict__ idkv,
    float* __restrict__ q, float* __restrict__ gK, float* __restrict__ gV) {
  int l = blockIdx.x, c = threadIdx.x;
  float cq  = qv[(size_t)l*512 + c];
  float cv  = qv[(size_t)l*512 + 256 + c];
  float idk = idkv[(size_t)l*264 + (c >> 5)];
  float idv = idkv[(size_t)l*264 + 8 + c];
  q [(size_t)l*CD + c] = cq;
  gK[(size_t)l*CD + c] = cq * (1.f + tanhf(idk));
  gV[(size_t)l*CD + c] = cv + idv;
}

// ---------------- Local 15x15 window attention ----------------
__global__ __launch_bounds__(256) void local_attn_kernel(
    const float* __restrict__ Q, const float* __restrict__ Kp,
    const float* __restrict__ Vp, float* __restrict__ O, int ostride, int ooff) {
  __shared__ float p_sh[8][232];
  int n = blockIdx.x;
  int r = n / GW, c = n % GW;
  int h = threadIdx.x >> 5, lane = threadIdx.x & 31;

  const float* qp = Q + (size_t)n*CD + h*HD;
  float4 qreg[8];
  #pragma unroll
  for (int i = 0; i < 8; i++) {
    qreg[i] = *(const float4*)(qp + i*4);
    qreg[i].x *= QSCALE; qreg[i].y *= QSCALE; qreg[i].z *= QSCALE; qreg[i].w *= QSCALE;
  }
  int i0 = max(7 - r, 0), i1 = min(GH + 7 - r, 15);
  int j0 = max(7 - c, 0), j1 = min(GW + 7 - c, 15);

  for (int w = lane; w < 225; w += 32) {
    int wi = w / 15, wj = w - wi*15;
    float logit = -1e30f;
    if (wi >= i0 && wi < i1 && wj >= j0 && wj < j1) {
      const float* kp = Kp + (size_t)((r+wi-7)*GW + (c+wj-7))*CD + h*HD;
      float acc = 0.f;
      #pragma unroll
      for (int i4 = 0; i4 < 8; i4++) {
        float4 kv = *(const float4*)(kp + i4*4);
        acc = fmaf(qreg[i4].x, kv.x, acc);
        acc = fmaf(qreg[i4].y, kv.y, acc);
        acc = fmaf(qreg[i4].z, kv.z, acc);
        acc = fmaf(qreg[i4].w, kv.w, acc);
      }
      logit = acc;
    }
    p_sh[h][w] = logit;
  }
  __syncwarp();
  float m = -1e30f;
  for (int ww = lane; ww < 225; ww += 32) m = fmaxf(m, p_sh[h][ww]);
  #pragma unroll
  for (int o = 16; o; o >>= 1) m = fmaxf(m, __shfl_xor_sync(0xffffffffu, m, o));
  float ssum = 0.f;
  for (int ww = lane; ww < 225; ww += 32) {
    float p = __expf(p_sh[h][ww] - m);
    p_sh[h][ww] = p;
    ssum += p;
  }
  #pragma unroll
  for (int o = 16; o; o >>= 1) ssum += __shfl_xor_sync(0xffffffffu, ssum, o);
  float inv = 1.f / ssum;
  __syncwarp();
  float oacc = 0.f;
  for (int wi = i0; wi < i1; wi++) {
    const float* vrow = Vp + (size_t)((r+wi-7)*GW + (c+j0-7))*CD + h*HD + lane;
    #pragma unroll 3
    for (int wj = j0; wj < j1; wj++, vrow += CD)
      oacc = fmaf(p_sh[h][wi*15+wj], *vrow, oacc);
  }
  O[(size_t)n*ostride + ooff + h*HD + lane] = oacc * inv;
}

// ---------------- GroupNorm stats ----------------
__global__ __launch_bounds__(1024) void gn_stats_kernel(
    const float* __restrict__ x, float* __restrict__ stats) {
  int g = blockIdx.x;
  float s = 0.f, s2 = 0.f;
  for (int idx = threadIdx.x; idx < LQ*32; idx += 1024) {
    int l = idx >> 5, ch = idx & 31;
    float v = x[(size_t)l*DFF + g*32 + ch];
    s += v; s2 += v*v;
  }
  #pragma unroll
  for (int o = 16; o; o >>= 1) {
    s  += __shfl_xor_sync(0xffffffffu, s,  o);
    s2 += __shfl_xor_sync(0xffffffffu, s2, o);
  }
  __shared__ float sh[32], sh2[32];
  int w = threadIdx.x >> 5, lane = threadIdx.x & 31;
  if (lane == 0) { sh[w] = s; sh2[w] = s2; }
  __syncthreads();
  if (w == 0) {
    s = sh[lane]; s2 = sh2[lane];
    #pragma unroll
    for (int o = 16; o; o >>= 1) {
      s  += __shfl_xor_sync(0xffffffffu, s,  o);
      s2 += __shfl_xor_sync(0xffffffffu, s2, o);
    }
    if (lane == 0) {
      const float invn = 1.f / (LQ * 32.f);
      float mean = s * invn;
      float var  = s2 * invn - mean*mean;
      stats[g*2]   = mean;
      stats[g*2+1] = rsqrtf(var + EPSV);
    }
  }
}

// ---------------- GN apply + exact GELU ----------------
__global__ __launch_bounds__(256) void gn_gelu_kernel(
    const float* __restrict__ x, const float* __restrict__ gg, const float* __restrict__ gb,
    const float* __restrict__ stats, float* __restrict__ y) {
  int idx = blockIdx.x * 256 + threadIdx.x;
  int ch = idx & (DFF-1);
  int g = ch >> 5;
  float v = (x[idx] - stats[g*2]) * stats[g*2+1] * gg[ch] + gb[ch];
  y[idx] = 0.5f * v * (1.f + erff(v * 0.70710678118654752f));
}

// ---------------- 5x5 depthwise conv, pad 2 ----------------
__global__ __launch_bounds__(256) void dwconv_kernel(
    const float* __restrict__ x, const float* __restrict__ kern, float* __restrict__ y) {
  __shared__ float tile[12][12][32];
  __shared__ float kw[32][25];
  int tid = threadIdx.x;
  int ch0 = blockIdx.z * 32;
  int r0 = blockIdx.y * 8 - 2, c0 = blockIdx.x * 8 - 2;
  for (int e = tid; e < 12*12*32; e += 256) {
    int ch = e & 31;
    int sp = e >> 5;
    int ri = sp / 12, ci = sp % 12;
    int rr = r0 + ri, cc = c0 + ci;
    float v = 0.f;
    if ((unsigned)rr < (unsigned)GH && (unsigned)cc < (unsigned)GW)
      v = x[(size_t)(rr*GW + cc)*DFF + ch0 + ch];
    tile[ri][ci][ch] = v;
  }
  for (int e = tid; e < 32*25; e += 256)
    kw[e/25][e%25] = kern[(size_t)(ch0 + e/25)*25 + e%25];
  __syncthreads();
  for (int e = tid; e < 8*8*32; e += 256) {
    int ch = e & 31;
    int sp = e >> 5;
    int ri = sp >> 3, ci = sp & 7;
    float acc = 0.f;
    #pragma unroll
    for (int i = 0; i < 5; i++)
      #pragma unroll
      for (int j = 0; j < 5; j++)
        acc = fmaf(tile[ri+i][ci+j][ch], kw[ch][i*5+j], acc);
    int rr = blockIdx.y*8 + ri, cc = blockIdx.x*8 + ci;
    y[(size_t)(rr*GW + cc)*DFF + ch0 + ch] = acc;
  }
}

// ---------------- launcher ----------------
extern "C" void kernel_launch(void* const* d_in, const int* in_sizes, int n_in,
                              void* d_out, int out_size) {
  const float* in_tgt   = (const float*)d_in[0];
  const float* id_emb   = (const float*)d_in[1];
  const float* self_pos = (const float*)d_in[2];
  const float* ln1_g = (const float*)d_in[3];
  const float* ln1_b = (const float*)d_in[4];
  const float* sa_wq = (const float*)d_in[5];
  const float* sa_bq = (const float*)d_in[6];
  const float* sa_wk = (const float*)d_in[7];
  const float* sa_bk = (const float*)d_in[8];
  const float* sa_wv = (const float*)d_in[9];
  const float* sa_bv = (const float*)d_in[10];
  const float* sa_wo = (const float*)d_in[11];
  const float* sa_bo = (const float*)d_in[12];
  const float* ln2_g = (const float*)d_in[13];
  const float* ln2_b = (const float*)d_in[14];
  const float* w_qv = (const float*)d_in[15];
  const float* b_qv = (const float*)d_in[16];
  const float* w_id = (const float*)d_in[17];
  const float* b_id = (const float*)d_in[18];
  const float* lt_wo = (const float*)d_in[19];
  const float* lt_bo = (const float*)d_in[20];
  const float* st_wo = (const float*)d_in[21];
  const float* st_bo = (const float*)d_in[22];
  const float* ln3_g = (const float*)d_in[23];
  const float* ln3_b = (const float*)d_in[24];
  const float* w1 = (const float*)d_in[25];
  const float* b1 = (const float*)d_in[26];
  const float* gn_g = (const float*)d_in[27];
  const float* gn_b = (const float*)d_in[28];
  const float* dw_k = (const float*)d_in[29];
  const float* w2 = (const float*)d_in[30];
  const float* b2 = (const float*)d_in[31];
  float* out = (float*)d_out;

  float *t, *qkin, *q, *k, *v, *attcat, *tgtb, *qv, *idkv, *gK, *gV, *x, *x2, *stats, *wcat, *bcat, *opart;
  float2 *ml;
  cudaGetSymbolAddress((void**)&t,      g_t);
  cudaGetSymbolAddress((void**)&qkin,   g_qkin);
  cudaGetSymbolAddress((void**)&q,      g_q);
  cudaGetSymbolAddress((void**)&k,      g_k);
  cudaGetSymbolAddress((void**)&v,      g_v);
  cudaGetSymbolAddress((void**)&attcat, g_attcat);
  cudaGetSymbolAddress((void**)&tgtb,   g_tgt);
  cudaGetSymbolAddress((void**)&qv,     g_qv);
  cudaGetSymbolAddress((void**)&idkv,   g_idkv);
  cudaGetSymbolAddress((void**)&gK,     g_gK);
  cudaGetSymbolAddress((void**)&gV,     g_gV);
  cudaGetSymbolAddress((void**)&x,      g_x);
  cudaGetSymbolAddress((void**)&x2,     g_x2);
  cudaGetSymbolAddress((void**)&stats,  g_stats);
  cudaGetSymbolAddress((void**)&wcat,   g_wcat);
  cudaGetSymbolAddress((void**)&bcat,   g_bcat);
  cudaGetSymbolAddress((void**)&opart,  g_opart);
  cudaGetSymbolAddress((void**)&ml,     g_ml);

  dim3 g66(4, 25);
  dim3 gQKV(4, 25, 3);
  dim3 gAttn(25, 8, NSPLIT);

  pack_w<<<512,256>>>(lt_wo, st_wo, lt_bo, st_bo, wcat, bcat);
  cudaMemcpyAsync(tgtb, in_tgt, sizeof(float)*LQ*CD, cudaMemcpyDeviceToDevice, 0);

  // --- self attention ---
  ln_kernel<<<LQ,256>>>(in_tgt, ln1_g, ln1_b, t, self_pos, qkin);
  gemm_qkv<<<gQKV,256>>>(qkin, t, sa_wq, sa_wk, sa_wv, sa_bq, sa_bk, sa_bv, q, k, v);
  attn_kernel<<<gAttn,128>>>(q, k, v, opart, ml);
  attn_merge<<<LQ,256>>>(opart, ml, attcat, 256, 0);
  gemm_nt<<<g66,256>>>(attcat, sa_wo, sa_bo, tgtb, tgtb, LQ, CD, CD);

  // --- long/short term attention ---
  ln_kernel<<<LQ,256>>>(tgtb, ln2_g, ln2_b, t, nullptr, nullptr);
  gemm_nt<<<dim3(8,25),256>>>(t, w_qv, b_qv, nullptr, qv, LQ, 512, CD);
  gemm_nt<<<dim3(5,25),256>>>(id_emb, w_id, b_id, nullptr, idkv, LQ, 264, CD);
  make_kv_kernel<<<LQ,256>>>(qv, idkv, q, gK, gV);
  attn_kernel<<<gAttn,128>>>(q, gK, gV, opart, ml);
  attn_merge<<<LQ,256>>>(opart, ml, attcat, 512, 0);
  local_attn_kernel<<<LQ,256>>>(q, gK, gV, attcat, 512, 256);
  gemm_nt<<<g66,256>>>(attcat, wcat, bcat, tgtb, tgtb, LQ, CD, 512);

  // --- MLP: LN -> w1 -> GN -> GELU -> dwconv -> w2 ---
  ln_kernel<<<LQ,256>>>(tgtb, ln3_g, ln3_b, t, nullptr, nullptr);
  gemm_nt<<<dim3(16,25),256>>>(t, w1, b1, nullptr, x, LQ, DFF, CD);
  gn_stats_kernel<<<32,1024>>>(x, stats);
  gn_gelu_kernel<<<(LQ*DFF)/256,256>>>(x, gn_g, gn_b, stats, x2);
  dwconv_kernel<<<dim3(5,5,32),256>>>(x2, dw_k, x);
  gemm_nt<<<g66,256>>>(x, w2, b2, tgtb, out, LQ, CD, DFF);
}

// round 10
// speedup vs baseline: 1.6485x; 1.0052x over previous
#include <cuda_runtime.h>
#include <math.h>

#define LQ 1600
#define CD 256
#define NHD 8
#define HD 32
#define DFF 1024
#define GH 40
#define GW 40
#define EPSV 1e-5f
#define QSCALE 0.17677669529663687f  // 1/sqrt(32)
#define NSPLIT 3

typedef unsigned long long ull;

// ---------------- f32x2 packed math helpers ----------------
__device__ __forceinline__ ull pk2(float x, float y) {
  ull r; asm("mov.b64 %0, {%1, %2};" : "=l"(r) : "f"(x), "f"(y)); return r;
}
__device__ __forceinline__ float2 up2(ull v) {
  float lo, hi; asm("mov.b64 {%0, %1}, %2;" : "=f"(lo), "=f"(hi) : "l"(v));
  return make_float2(lo, hi);
}
__device__ __forceinline__ void fma2(ull &d, ull a, ull b) {
  asm("fma.rn.f32x2 %0, %1, %2, %0;" : "+l"(d) : "l"(a), "l"(b));
}

// ---------------- tf32 mma helpers ----------------
__device__ __forceinline__ unsigned tf32r(float x) {
  unsigned u; asm("cvt.rna.tf32.f32 %0, %1;" : "=r"(u) : "f"(x)); return u;
}
__device__ __forceinline__ void mma_tf32(float* d, const unsigned* a, unsigned b0, unsigned b1) {
  asm("mma.sync.aligned.m16n8k8.row.col.f32.tf32.tf32.f32 "
      "{%0,%1,%2,%3}, {%4,%5,%6,%7}, {%8,%9}, {%0,%1,%2,%3};"
      : "+f"(d[0]), "+f"(d[1]), "+f"(d[2]), "+f"(d[3])
      : "r"(a[0]), "r"(a[1]), "r"(a[2]), "r"(a[3]), "r"(b0), "r"(b1));
}

// ---------------- scratch (device globals; no allocation) ----------------
static __device__ float g_t[LQ*CD];
static __device__ float g_qkin[LQ*CD];
static __device__ float g_q[LQ*CD];
static __device__ float g_k[LQ*CD];
static __device__ float g_v[LQ*CD];
static __device__ float g_attcat[LQ*512];
static __device__ float g_tgt[LQ*CD];
static __device__ float g_qv[LQ*2*CD];
static __device__ float g_idkv[LQ*264];
static __device__ float g_gK[LQ*CD];
static __device__ float g_gV[LQ*CD];
static __device__ float g_x[LQ*DFF];
static __device__ float g_x2[LQ*DFF];
static __device__ float g_stats[64];
static __device__ float g_wcat[256*512];
static __device__ float g_bcat[256];
static __device__ float g_opart[NSPLIT*LQ*CD];
static __device__ float2 g_ml[NSPLIT*LQ*NHD];

// ---------------- LayerNorm (optionally + pos add) ----------------
__global__ __launch_bounds__(256) void ln_kernel(
    const float* __restrict__ x, const float* __restrict__ g, const float* __restrict__ b,
    float* __restrict__ y, const float* __restrict__ pos, float* __restrict__ qkout) {
  int l = blockIdx.x;
  int c = threadIdx.x;
  float v = x[(size_t)l*CD + c];
  float s = v, s2 = v*v;
  #pragma unroll
  for (int o = 16; o; o >>= 1) {
    s  += __shfl_xor_sync(0xffffffffu, s,  o);
    s2 += __shfl_xor_sync(0xffffffffu, s2, o);
  }
  __shared__ float sh[8], sh2[8], smv[2];
  int w = c >> 5, lane = c & 31;
  if (lane == 0) { sh[w] = s; sh2[w] = s2; }
  __syncthreads();
  if (c == 0) {
    float a = 0.f, a2 = 0.f;
    #pragma unroll
    for (int i = 0; i < 8; i++) { a += sh[i]; a2 += sh2[i]; }
    float mean = a * (1.0f/CD);
    float var  = a2 * (1.0f/CD) - mean*mean;
    smv[0] = mean; smv[1] = rsqrtf(var + EPSV);
  }
  __syncthreads();
  float out = (v - smv[0]) * smv[1] * g[c] + b[c];
  y[(size_t)l*CD + c] = out;
  if (qkout) qkout[(size_t)l*CD + c] = out + pos[(size_t)l*CD + c];
}

// ---------------- GEMM core (f32x2, intra-CTA split-K x2) -------------------
__device__ __forceinline__ void gemm_body(
    const float* __restrict__ A, const float* __restrict__ B,
    const float* __restrict__ bias, const float* __restrict__ res,
    float* __restrict__ Cout, int M, int N, int K, int bm, int bn) {
  __shared__ float As[2][32][68];
  __shared__ float Bs[2][32][68];
  const int tid = threadIdx.x;
  const int h = tid >> 7;
  const int htid = tid & 127;
  const int tx = htid & 15, ty = htid >> 4;
  const int lr = htid >> 1;
  const int lc = (htid & 1) << 4;
  ull acc2[8][2] = {};
  const int nk = K >> 5;
  const int nh = nk >> 1;

  float4 a[4], b[4];
  const bool bok = (bn + lr) < N;
  {
    const int k0 = (h * nh) << 5;
    const float* Ap = A + (size_t)(bm + lr)*K + k0 + lc;
    const float* Bp = B + (size_t)(bn + lr)*K + k0 + lc;
    #pragma unroll
    for (int u = 0; u < 4; u++) {
      a[u] = *(const float4*)(Ap + u*4);
      b[u] = bok ? *(const float4*)(Bp + u*4) : make_float4(0.f,0.f,0.f,0.f);
    }
  }

  for (int c = 0; c < nh; c++) {
    __syncthreads();
    #pragma unroll
    for (int u = 0; u < 4; u++) {
      int kk = lc + u*4;
      As[h][kk+0][lr]=a[u].x; As[h][kk+1][lr]=a[u].y; As[h][kk+2][lr]=a[u].z; As[h][kk+3][lr]=a[u].w;
      Bs[h][kk+0][lr]=b[u].x; Bs[h][kk+1][lr]=b[u].y; Bs[h][kk+2][lr]=b[u].z; Bs[h][kk+3][lr]=b[u].w;
    }
    __syncthreads();
    if (c + 1 < nh) {
      const int k0 = (h * nh + c + 1) << 5;
      const float* Ap = A + (size_t)(bm + lr)*K + k0 + lc;
      const float* Bp = B + (size_t)(bn + lr)*K + k0 + lc;
      #pragma unroll
      for (int u = 0; u < 4; u++) {
        a[u] = *(const float4*)(Ap + u*4);
        b[u] = bok ? *(const float4*)(Bp + u*4) : make_float4(0.f,0.f,0.f,0.f);
      }
    }
    #pragma unroll
    for (int kk = 0; kk < 32; kk++) {
      float4 a4a = *(const float4*)&As[h][kk][ty*8];
      float4 a4b = *(const float4*)&As[h][kk][ty*8+4];
      const ull* bp = (const ull*)&Bs[h][kk][tx*4];
      ull b01 = bp[0], b23 = bp[1];
      float av[8] = {a4a.x, a4a.y, a4a.z, a4a.w, a4b.x, a4b.y, a4b.z, a4b.w};
      #pragma unroll
      for (int i = 0; i < 8; i++) {
        ull aa = pk2(av[i], av[i]);
        fma2(acc2[i][0], aa, b01);
        fma2(acc2[i][1], aa, b23);
      }
    }
  }

  float (*red)[68] = (float(*)[68])&Bs[0][0][0];
  __syncthreads();
  if (h == 1) {
    #pragma unroll
    for (int i = 0; i < 8; i++) {
      float2 v01 = up2(acc2[i][0]);
      float2 v23 = up2(acc2[i][1]);
      *(float4*)&red[ty*8+i][tx*4] = make_float4(v01.x, v01.y, v23.x, v23.y);
    }
  }
  __syncthreads();
  if (h == 0) {
    #pragma unroll
    for (int i = 0; i < 8; i++) {
      int m = bm + ty*8 + i;
      float2 v01 = up2(acc2[i][0]);
      float2 v23 = up2(acc2[i][1]);
      float4 r4 = *(const float4*)&red[ty*8+i][tx*4];
      float vals[4] = {v01.x + r4.x, v01.y + r4.y, v23.x + r4.z, v23.y + r4.w};
      #pragma unroll
      for (int j = 0; j < 4; j++) {
        int n = bn + tx*4 + j;
        if (n < N) {
          float val = vals[j] + bias[n];
          if (res) val += res[(size_t)m*N + n];
          Cout[(size_t)m*N + n] = val;
        }
      }
    }
  }
}

__global__ __launch_bounds__(256) void gemm_nt(
    const float* __restrict__ A, const float* __restrict__ B,
    const float* __restrict__ bias, const float* __restrict__ res,
    float* __restrict__ Cout, int M, int N, int K) {
  gemm_body(A, B, bias, res, Cout, M, N, K, blockIdx.y*64, blockIdx.x*64);
}

__global__ __launch_bounds__(256) void gemm_qkv(
    const float* __restrict__ qkin, const float* __restrict__ t,
    const float* __restrict__ wq, const float* __restrict__ wk, const float* __restrict__ wv,
    const float* __restrict__ bq, const float* __restrict__ bk, const float* __restrict__ bv,
    float* __restrict__ q, float* __restrict__ k, float* __restrict__ v) {
  int z = blockIdx.z;
  const float* A = (z == 2) ? t : qkin;
  const float* B = (z == 0) ? wq : (z == 1 ? wk : wv);
  const float* bias = (z == 0) ? bq : (z == 1 ? bk : bv);
  float* C = (z == 0) ? q : (z == 1 ? k : v);
  gemm_body(A, B, bias, nullptr, C, LQ, CD, CD, blockIdx.y*64, blockIdx.x*64);
}

// pack [lt_wo | st_wo] into (256,512) + combined bias
__global__ __launch_bounds__(256) void pack_w(
    const float* __restrict__ lt, const float* __restrict__ st,
    const float* __restrict__ ltb, const float* __restrict__ stb,
    float* __restrict__ wcat, float* __restrict__ bcat) {
  int idx = blockIdx.x * 256 + threadIdx.x;
  int nrow = idx >> 9, k = idx & 511;
  wcat[idx] = (k < 256) ? lt[nrow*256 + k] : st[nrow*256 + k - 256];
  if (idx < 256) bcat[idx] = ltb[idx] + stb[idx];
}

// ---------------- Fused full attention: tf32 mma (3xTF32), split-KV x3 ------
// grid (25 q-tiles, 8 heads, 3 kv-splits), 128 threads (4 warps x 16 q-rows).
// Shared: Vs hi/lo [64][40]; K region [64][40] x2 reused as P tile [64][68].
__global__ __launch_bounds__(128, 4) void attn_kernel(
    const float* __restrict__ Q, const float* __restrict__ Kp,
    const float* __restrict__ Vp, float* __restrict__ Opart, float2* __restrict__ ml) {
  __shared__ float Vs_hi[64][40];
  __shared__ float Vs_lo[64][40];
  __shared__ float uKP[5120];   // Ks_hi [64][40] | Ks_lo +2560 ; reused as Ps[64][68]
  #define KS_HI(kk,dd) uKP[(kk)*40 + (dd)]
  #define KS_LO(kk,dd) uKP[2560 + (kk)*40 + (dd)]
  #define PS(rr,cc)    uKP[(rr)*68 + (cc)]

  const int h = blockIdx.y;
  const int z = blockIdx.z;
  const int q0 = blockIdx.x * 64;
  const int kt0 = (z == 0) ? 0 : 9 + (z - 1) * 8;
  const int kt1 = (z == 0) ? 9 : kt0 + 8;
  const int tid = threadIdx.x;
  const int w = tid >> 5, lane = tid & 31;
  const int g = lane >> 2, t = lane & 3;
  const int qb = q0 + w*16;

  // --- Q fragments (hi/lo tf32), loaded once ---
  unsigned qhi[4][4], qlo[4][4];
  #pragma unroll
  for (int s = 0; s < 4; s++) {
    const int k0 = s*8;
    float f[4];
    f[0] = Q[(size_t)(qb+g  )*CD + h*HD + k0 + t    ] * QSCALE;
    f[1] = Q[(size_t)(qb+g+8)*CD + h*HD + k0 + t    ] * QSCALE;
    f[2] = Q[(size_t)(qb+g  )*CD + h*HD + k0 + t + 4] * QSCALE;
    f[3] = Q[(size_t)(qb+g+8)*CD + h*HD + k0 + t + 4] * QSCALE;
    #pragma unroll
    for (int i = 0; i < 4; i++) {
      qhi[s][i] = tf32r(f[i]);
      qlo[s][i] = tf32r(f[i] - __uint_as_float(qhi[s][i]));
    }
  }

  float m_i[2] = {-1e30f, -1e30f};
  float l_i[2] = {0.f, 0.f};
  float oacc[4][4] = {};

  for (int kt = kt0; kt < kt1; kt++) {
    const int kb = kt * 64;
    __syncthreads();   // prior tile fully consumed (PV reads Vs, Ps in uKP)
    // --- producer: K/V tile -> smem with tf32 hi/lo split ---
    #pragma unroll
    for (int it = 0; it < 4; it++) {
      int idx = tid + it*128;
      int r = idx >> 3, d4 = (idx & 7) << 2;
      float4 kv = *(const float4*)(Kp + (size_t)(kb + r)*CD + h*HD + d4);
      float4 vv = *(const float4*)(Vp + (size_t)(kb + r)*CD + h*HD + d4);
      float kf[4] = {kv.x, kv.y, kv.z, kv.w};
      float vf[4] = {vv.x, vv.y, vv.z, vv.w};
      float khi[4], klo[4], vhi[4], vlo[4];
      #pragma unroll
      for (int j = 0; j < 4; j++) {
        unsigned u1 = tf32r(kf[j]);
        khi[j] = __uint_as_float(u1);
        klo[j] = __uint_as_float(tf32r(kf[j] - khi[j]));
        unsigned u2 = tf32r(vf[j]);
        vhi[j] = __uint_as_float(u2);
        vlo[j] = __uint_as_float(tf32r(vf[j] - vhi[j]));
      }
      *(float4*)&KS_HI(r, d4) = make_float4(khi[0], khi[1], khi[2], khi[3]);
      *(float4*)&KS_LO(r, d4) = make_float4(klo[0], klo[1], klo[2], klo[3]);
      *(float4*)&Vs_hi[r][d4] = make_float4(vhi[0], vhi[1], vhi[2], vhi[3]);
      *(float4*)&Vs_lo[r][d4] = make_float4(vlo[0], vlo[1], vlo[2], vlo[3]);
    }
    __syncthreads();

    // --- QK^T: S[16 x 64] per warp via 3xTF32 mma ---
    float sacc[8][4];
    #pragma unroll
    for (int n = 0; n < 8; n++)
      #pragma unroll
      for (int i = 0; i < 4; i++) sacc[n][i] = 0.f;
    #pragma unroll
    for (int n = 0; n < 8; n++) {
      #pragma unroll
      for (int s = 0; s < 4; s++) {
        unsigned bh0 = __float_as_uint(KS_HI(n*8+g, s*8+t));
        unsigned bh1 = __float_as_uint(KS_HI(n*8+g, s*8+t+4));
        unsigned bl0 = __float_as_uint(KS_LO(n*8+g, s*8+t));
        unsigned bl1 = __float_as_uint(KS_LO(n*8+g, s*8+t+4));
        mma_tf32(sacc[n], qhi[s], bh0, bh1);
        mma_tf32(sacc[n], qhi[s], bl0, bl1);
        mma_tf32(sacc[n], qlo[s], bh0, bh1);
      }
    }
    __syncthreads();   // all warps done reading Ks before Ps overwrites uKP

    // --- online softmax (rows g and g+8 of this warp's 16) ---
    #pragma unroll
    for (int ri = 0; ri < 2; ri++) {
      float rm = -1e30f;
      #pragma unroll
      for (int n = 0; n < 8; n++)
        rm = fmaxf(rm, fmaxf(sacc[n][2*ri], sacc[n][2*ri+1]));
      rm = fmaxf(rm, __shfl_xor_sync(0xffffffffu, rm, 1));
      rm = fmaxf(rm, __shfl_xor_sync(0xffffffffu, rm, 2));
      float mnew = fmaxf(m_i[ri], rm);
      float alpha = __expf(m_i[ri] - mnew);
      float rs = 0.f;
      int prow = w*16 + g + ri*8;
      #pragma unroll
      for (int n = 0; n < 8; n++) {
        float p0 = __expf(sacc[n][2*ri]   - mnew);
        float p1 = __expf(sacc[n][2*ri+1] - mnew);
        *(float2*)&PS(prow, n*8 + 2*t) = make_float2(p0, p1);
        rs += p0 + p1;
      }
      rs += __shfl_xor_sync(0xffffffffu, rs, 1);
      rs += __shfl_xor_sync(0xffffffffu, rs, 2);
      l_i[ri] = l_i[ri]*alpha + rs;
      m_i[ri] = mnew;
      #pragma unroll
      for (int n = 0; n < 4; n++) { oacc[n][2*ri] *= alpha; oacc[n][2*ri+1] *= alpha; }
    }
    __syncwarp();

    // --- P @ V via 3xTF32 mma ---
    #pragma unroll
    for (int kk = 0; kk < 8; kk++) {
      float pf[4];
      pf[0] = PS(w*16 + g,     kk*8 + t);
      pf[1] = PS(w*16 + g + 8, kk*8 + t);
      pf[2] = PS(w*16 + g,     kk*8 + t + 4);
      pf[3] = PS(w*16 + g + 8, kk*8 + t + 4);
      unsigned ahi[4], alo[4];
      #pragma unroll
      for (int i = 0; i < 4; i++) {
        ahi[i] = tf32r(pf[i]);
        alo[i] = tf32r(pf[i] - __uint_as_float(ahi[i]));
      }
      #pragma unroll
      for (int n = 0; n < 4; n++) {
        unsigned bh0 = __float_as_uint(Vs_hi[kk*8+t  ][n*8+g]);
        unsigned bh1 = __float_as_uint(Vs_hi[kk*8+t+4][n*8+g]);
        unsigned bl0 = __float_as_uint(Vs_lo[kk*8+t  ][n*8+g]);
        unsigned bl1 = __float_as_uint(Vs_lo[kk*8+t+4][n*8+g]);
        mma_tf32(oacc[n], ahi, bh0, bh1);
        mma_tf32(oacc[n], ahi, bl0, bl1);
        mma_tf32(oacc[n], alo, bh0, bh1);
      }
    }
  }

  // --- epilogue: unnormalized partials + (m,l) ---
  #pragma unroll
  for (int n = 0; n < 4; n++) {
    *(float2*)&Opart[((size_t)z*LQ + qb + g    )*CD + h*HD + n*8 + 2*t] =
        make_float2(oacc[n][0], oacc[n][1]);
    *(float2*)&Opart[((size_t)z*LQ + qb + g + 8)*CD + h*HD + n*8 + 2*t] =
        make_float2(oacc[n][2], oacc[n][3]);
  }
  if (t == 0) {
    ml[(z*LQ + qb + g    )*NHD + h] = make_float2(m_i[0], l_i[0]);
    ml[(z*LQ + qb + g + 8)*NHD + h] = make_float2(m_i[1], l_i[1]);
  }
  #undef KS_HI
  #undef KS_LO
  #undef PS
}

// merge the kv-splits
__global__ __launch_bounds__(256) void attn_merge(
    const float* __restrict__ Opart, const float2* __restrict__ ml,
    float* __restrict__ O, int ostride, int ooff) {
  int row = blockIdx.x, c = threadIdx.x;
  int h = c >> 5;
  float2 mlp[NSPLIT];
  float m = -1e30f;
  #pragma unroll
  for (int p = 0; p < NSPLIT; p++) {
    mlp[p] = ml[(p*LQ + row)*NHD + h];
    m = fmaxf(m, mlp[p].x);
  }
  float l = 0.f, o = 0.f;
  #pragma unroll
  for (int p = 0; p < NSPLIT; p++) {
    float e = __expf(mlp[p].x - m);
    l += mlp[p].y * e;
    o += Opart[((size_t)p*LQ + row)*CD + c] * e;
  }
  O[(size_t)row*ostride + ooff + c] = o / l;
}

// ---------------- curr_Q / global_K / global_V construction ----------------
__global__ __launch_bounds__(256) void make_kv_kernel(
    const float* __restrict__ qv, const float* __restrict__ idkv,
    float* __restrict__ q, float* __restrict__ gK, float* __restrict__ gV) {
  int l = blockIdx.x, c = threadIdx.x;
  float cq  = qv[(size_t)l*512 + c];
  float cv  = qv[(size_t)l*512 + 256 + c];
  float idk = idkv[(size_t)l*264 + (c >> 5)];
  float idv = idkv[(size_t)l*264 + 8 + c];
  q [(size_t)l*CD + c] = cq;
  gK[(size_t)l*CD + c] = cq * (1.f + tanhf(idk));
  gV[(size_t)l*CD + c] = cv + idv;
}

// ---------------- Local 15x15 window attention ----------------
__global__ __launch_bounds__(256) void local_attn_kernel(
    const float* __restrict__ Q, const float* __restrict__ Kp,
    const float* __restrict__ Vp, float* __restrict__ O, int ostride, int ooff) {
  __shared__ float p_sh[8][232];
  int n = blockIdx.x;
  int r = n / GW, c = n % GW;
  int h = threadIdx.x >> 5, lane = threadIdx.x & 31;

  const float* qp = Q + (size_t)n*CD + h*HD;
  float4 qreg[8];
  #pragma unroll
  for (int i = 0; i < 8; i++) {
    qreg[i] = *(const float4*)(qp + i*4);
    qreg[i].x *= QSCALE; qreg[i].y *= QSCALE; qreg[i].z *= QSCALE; qreg[i].w *= QSCALE;
  }
  int i0 = max(7 - r, 0), i1 = min(GH + 7 - r, 15);
  int j0 = max(7 - c, 0), j1 = min(GW + 7 - c, 15);

  for (int w = lane; w < 225; w += 32) {
    int wi = w / 15, wj = w - wi*15;
    float logit = -1e30f;
    if (wi >= i0 && wi < i1 && wj >= j0 && wj < j1) {
      const float* kp = Kp + (size_t)((r+wi-7)*GW + (c+wj-7))*CD + h*HD;
      float acc = 0.f;
      #pragma unroll
      for (int i4 = 0; i4 < 8; i4++) {
        float4 kv = *(const float4*)(kp + i4*4);
        acc = fmaf(qreg[i4].x, kv.x, acc);
        acc = fmaf(qreg[i4].y, kv.y, acc);
        acc = fmaf(qreg[i4].z, kv.z, acc);
        acc = fmaf(qreg[i4].w, kv.w, acc);
      }
      logit = acc;
    }
    p_sh[h][w] = logit;
  }
  __syncwarp();
  float m = -1e30f;
  for (int ww = lane; ww < 225; ww += 32) m = fmaxf(m, p_sh[h][ww]);
  #pragma unroll
  for (int o = 16; o; o >>= 1) m = fmaxf(m, __shfl_xor_sync(0xffffffffu, m, o));
  float ssum = 0.f;
  for (int ww = lane; ww < 225; ww += 32) {
    float p = __expf(p_sh[h][ww] - m);
    p_sh[h][ww] = p;
    ssum += p;
  }
  #pragma unroll
  for (int o = 16; o; o >>= 1) ssum += __shfl_xor_sync(0xffffffffu, ssum, o);
  float inv = 1.f / ssum;
  __syncwarp();
  float oacc = 0.f;
  for (int wi = i0; wi < i1; wi++) {
    const float* vrow = Vp + (size_t)((r+wi-7)*GW + (c+j0-7))*CD + h*HD + lane;
    #pragma unroll 3
    for (int wj = j0; wj < j1; wj++, vrow += CD)
      oacc = fmaf(p_sh[h][wi*15+wj], *vrow, oacc);
  }
  O[(size_t)n*ostride + ooff + h*HD + lane] = oacc * inv;
}

// ---------------- GroupNorm stats ----------------
__global__ __launch_bounds__(1024) void gn_stats_kernel(
    const float* __restrict__ x, float* __restrict__ stats) {
  int g = blockIdx.x;
  float s = 0.f, s2 = 0.f;
  for (int idx = threadIdx.x; idx < LQ*32; idx += 1024) {
    int l = idx >> 5, ch = idx & 31;
    float v = x[(size_t)l*DFF + g*32 + ch];
    s += v; s2 += v*v;
  }
  #pragma unroll
  for (int o = 16; o; o >>= 1) {
    s  += __shfl_xor_sync(0xffffffffu, s,  o);
    s2 += __shfl_xor_sync(0xffffffffu, s2, o);
  }
  __shared__ float sh[32], sh2[32];
  int w = threadIdx.x >> 5, lane = threadIdx.x & 31;
  if (lane == 0) { sh[w] = s; sh2[w] = s2; }
  __syncthreads();
  if (w == 0) {
    s = sh[lane]; s2 = sh2[lane];
    #pragma unroll
    for (int o = 16; o; o >>= 1) {
      s  += __shfl_xor_sync(0xffffffffu, s,  o);
      s2 += __shfl_xor_sync(0xffffffffu, s2, o);
    }
    if (lane == 0) {
      const float invn = 1.f / (LQ * 32.f);
      float mean = s * invn;
      float var  = s2 * invn - mean*mean;
      stats[g*2]   = mean;
      stats[g*2+1] = rsqrtf(var + EPSV);
    }
  }
}

// ---------------- GN apply + exact GELU ----------------
__global__ __launch_bounds__(256) void gn_gelu_kernel(
    const float* __restrict__ x, const float* __restrict__ gg, const float* __restrict__ gb,
    const float* __restrict__ stats, float* __restrict__ y) {
  int idx = blockIdx.x * 256 + threadIdx.x;
  int ch = idx & (DFF-1);
  int g = ch >> 5;
  float v = (x[idx] - stats[g*2]) * stats[g*2+1] * gg[ch] + gb[ch];
  y[idx] = 0.5f * v * (1.f + erff(v * 0.70710678118654752f));
}

// ---------------- 5x5 depthwise conv, pad 2 ----------------
__global__ __launch_bounds__(256) void dwconv_kernel(
    const float* __restrict__ x, const float* __restrict__ kern, float* __restrict__ y) {
  __shared__ float tile[12][12][32];
  __shared__ float kw[32][25];
  int tid = threadIdx.x;
  int ch0 = blockIdx.z * 32;
  int r0 = blockIdx.y * 8 - 2, c0 = blockIdx.x * 8 - 2;
  for (int e = tid; e < 12*12*32; e += 256) {
    int ch = e & 31;
    int sp = e >> 5;
    int ri = sp / 12, ci = sp % 12;
    int rr = r0 + ri, cc = c0 + ci;
    float v = 0.f;
    if ((unsigned)rr < (unsigned)GH && (unsigned)cc < (unsigned)GW)
      v = x[(size_t)(rr*GW + cc)*DFF + ch0 + ch];
    tile[ri][ci][ch] = v;
  }
  for (int e = tid; e < 32*25; e += 256)
    kw[e/25][e%25] = kern[(size_t)(ch0 + e/25)*25 + e%25];
  __syncthreads();
  for (int e = tid; e < 8*8*32; e += 256) {
    int ch = e & 31;
    int sp = e >> 5;
    int ri = sp >> 3, ci = sp & 7;
    float acc = 0.f;
    #pragma unroll
    for (int i = 0; i < 5; i++)
      #pragma unroll
      for (int j = 0; j < 5; j++)
        acc = fmaf(tile[ri+i][ci+j][ch], kw[ch][i*5+j], acc);
    int rr = blockIdx.y*8 + ri, cc = blockIdx.x*8 + ci;
    y[(size_t)(rr*GW + cc)*DFF + ch0 + ch] = acc;
  }
}

// ---------------- launcher ----------------
extern "C" void kernel_launch(void* const* d_in, const int* in_sizes, int n_in,
                              void* d_out, int out_size) {
  const float* in_tgt   = (const float*)d_in[0];
  const float* id_emb   = (const float*)d_in[1];
  const float* self_pos = (const float*)d_in[2];
  const float* ln1_g = (const float*)d_in[3];
  const float* ln1_b = (const float*)d_in[4];
  const float* sa_wq = (const float*)d_in[5];
  const float* sa_bq = (const float*)d_in[6];
  const float* sa_wk = (const float*)d_in[7];
  const float* sa_bk = (const float*)d_in[8];
  const float* sa_wv = (const float*)d_in[9];
  const float* sa_bv = (const float*)d_in[10];
  const float* sa_wo = (const float*)d_in[11];
  const float* sa_bo = (const float*)d_in[12];
  const float* ln2_g = (const float*)d_in[13];
  const float* ln2_b = (const float*)d_in[14];
  const float* w_qv = (const float*)d_in[15];
  const float* b_qv = (const float*)d_in[16];
  const float* w_id = (const float*)d_in[17];
  const float* b_id = (const float*)d_in[18];
  const float* lt_wo = (const float*)d_in[19];
  const float* lt_bo = (const float*)d_in[20];
  const float* st_wo = (const float*)d_in[21];
  const float* st_bo = (const float*)d_in[22];
  const float* ln3_g = (const float*)d_in[23];
  const float* ln3_b = (const float*)d_in[24];
  const float* w1 = (const float*)d_in[25];
  const float* b1 = (const float*)d_in[26];
  const float* gn_g = (const float*)d_in[27];
  const float* gn_b = (const float*)d_in[28];
  const float* dw_k = (const float*)d_in[29];
  const float* w2 = (const float*)d_in[30];
  const float* b2 = (const float*)d_in[31];
  float* out = (float*)d_out;

  float *t, *qkin, *q, *k, *v, *attcat, *tgtb, *qv, *idkv, *gK, *gV, *x, *x2, *stats, *wcat, *bcat, *opart;
  float2 *ml;
  cudaGetSymbolAddress((void**)&t,      g_t);
  cudaGetSymbolAddress((void**)&qkin,   g_qkin);
  cudaGetSymbolAddress((void**)&q,      g_q);
  cudaGetSymbolAddress((void**)&k,      g_k);
  cudaGetSymbolAddress((void**)&v,      g_v);
  cudaGetSymbolAddress((void**)&attcat, g_attcat);
  cudaGetSymbolAddress((void**)&tgtb,   g_tgt);
  cudaGetSymbolAddress((void**)&qv,     g_qv);
  cudaGetSymbolAddress((void**)&idkv,   g_idkv);
  cudaGetSymbolAddress((void**)&gK,     g_gK);
  cudaGetSymbolAddress((void**)&gV,     g_gV);
  cudaGetSymbolAddress((void**)&x,      g_x);
  cudaGetSymbolAddress((void**)&x2,     g_x2);
  cudaGetSymbolAddress((void**)&stats,  g_stats);
  cudaGetSymbolAddress((void**)&wcat,   g_wcat);
  cudaGetSymbolAddress((void**)&bcat,   g_bcat);
  cudaGetSymbolAddress((void**)&opart,  g_opart);
  cudaGetSymbolAddress((void**)&ml,     g_ml);

  dim3 g66(4, 25);
  dim3 gQKV(4, 25, 3);
  dim3 gAttn(25, 8, NSPLIT);

  pack_w<<<512,256>>>(lt_wo, st_wo, lt_bo, st_bo, wcat, bcat);
  cudaMemcpyAsync(tgtb, in_tgt, sizeof(float)*LQ*CD, cudaMemcpyDeviceToDevice, 0);

  // --- self attention ---
  ln_kernel<<<LQ,256>>>(in_tgt, ln1_g, ln1_b, t, self_pos, qkin);
  gemm_qkv<<<gQKV,256>>>(qkin, t, sa_wq, sa_wk, sa_wv, sa_bq, sa_bk, sa_bv, q, k, v);
  attn_kernel<<<gAttn,128>>>(q, k, v, opart, ml);
  attn_merge<<<LQ,256>>>(opart, ml, attcat, 256, 0);
  gemm_nt<<<g66,256>>>(attcat, sa_wo, sa_bo, tgtb, tgtb, LQ, CD, CD);

  // --- long/short term attention ---
  ln_kernel<<<LQ,256>>>(tgtb, ln2_g, ln2_b, t, nullptr, nullptr);
  gemm_nt<<<dim3(8,25),256>>>(t, w_qv, b_qv, nullptr, qv, LQ, 512, CD);
  gemm_nt<<<dim3(5,25),256>>>(id_emb, w_id, b_id, nullptr, idkv, LQ, 264, CD);
  make_kv_kernel<<<LQ,256>>>(qv, idkv, q, gK, gV);
  attn_kernel<<<gAttn,128>>>(q, gK, gV, opart, ml);
  attn_merge<<<LQ,256>>>(opart, ml, attcat, 512, 0);
  local_attn_kernel<<<LQ,256>>>(q, gK, gV, attcat, 512, 256);
  gemm_nt<<<g66,256>>>(attcat, wcat, bcat, tgtb, tgtb, LQ, CD, 512);

  // --- MLP: LN -> w1 -> GN -> GELU -> dwconv -> w2 ---
  ln_kernel<<<LQ,256>>>(tgtb, ln3_g, ln3_b, t, nullptr, nullptr);
  gemm_nt<<<dim3(16,25),256>>>(t, w1, b1, nullptr, x, LQ, DFF, CD);
  gn_stats_kernel<<<32,1024>>>(x, stats);
  gn_gelu_kernel<<<(LQ*DFF)/256,256>>>(x, gn_g, gn_b, stats, x2);
  dwconv_kernel<<<dim3(5,5,32),256>>>(x2, dw_k, x);
  gemm_nt<<<g66,256>>>(x, w2, b2, tgtb, out, LQ, CD, DFF);
}

// round 15
// speedup vs baseline: 1.6527x; 1.0025x over previous
#include <cuda_runtime.h>
#include <math.h>

#define LQ 1600
#define CD 256
#define NHD 8
#define HD 32
#define DFF 1024
#define GH 40
#define GW 40
#define EPSV 1e-5f
#define QSCALE 0.17677669529663687f  // 1/sqrt(32)
#define NSPLIT 3

// ---------------- tf32 mma helpers ----------------
__device__ __forceinline__ unsigned tf32r(float x) {
  unsigned u; asm("cvt.rna.tf32.f32 %0, %1;" : "=r"(u) : "f"(x)); return u;
}
__device__ __forceinline__ void mma_tf32(float* d, const unsigned* a, unsigned b0, unsigned b1) {
  asm("mma.sync.aligned.m16n8k8.row.col.f32.tf32.tf32.f32 "
      "{%0,%1,%2,%3}, {%4,%5,%6,%7}, {%8,%9}, {%0,%1,%2,%3};"
      : "+f"(d[0]), "+f"(d[1]), "+f"(d[2]), "+f"(d[3])
      : "r"(a[0]), "r"(a[1]), "r"(a[2]), "r"(a[3]), "r"(b0), "r"(b1));
}

// ---------------- scratch (device globals; no allocation) ----------------
static __device__ float g_t[LQ*CD];
static __device__ float g_qkin[LQ*CD];
static __device__ float g_q[LQ*CD];
static __device__ float g_k[LQ*CD];
static __device__ float g_v[LQ*CD];
static __device__ float g_attcat[LQ*512];
static __device__ float g_tgt[LQ*CD];
static __device__ float g_qv[LQ*2*CD];
static __device__ float g_idkv[LQ*264];
static __device__ float g_gK[LQ*CD];
static __device__ float g_gV[LQ*CD];
static __device__ float g_x[LQ*DFF];
static __device__ float g_x2[LQ*DFF];
static __device__ float g_stats[64];
static __device__ float g_wcat[256*512];
static __device__ float g_bcat[256];
static __device__ float g_opart[NSPLIT*LQ*CD];
static __device__ float2 g_ml[NSPLIT*LQ*NHD];

// ---------------- LayerNorm (optionally + pos add) ----------------
__global__ __launch_bounds__(256) void ln_kernel(
    const float* __restrict__ x, const float* __restrict__ g, const float* __restrict__ b,
    float* __restrict__ y, const float* __restrict__ pos, float* __restrict__ qkout) {
  int l = blockIdx.x;
  int c = threadIdx.x;
  float v = x[(size_t)l*CD + c];
  float s = v, s2 = v*v;
  #pragma unroll
  for (int o = 16; o; o >>= 1) {
    s  += __shfl_xor_sync(0xffffffffu, s,  o);
    s2 += __shfl_xor_sync(0xffffffffu, s2, o);
  }
  __shared__ float sh[8], sh2[8], smv[2];
  int w = c >> 5, lane = c & 31;
  if (lane == 0) { sh[w] = s; sh2[w] = s2; }
  __syncthreads();
  if (c == 0) {
    float a = 0.f, a2 = 0.f;
    #pragma unroll
    for (int i = 0; i < 8; i++) { a += sh[i]; a2 += sh2[i]; }
    float mean = a * (1.0f/CD);
    float var  = a2 * (1.0f/CD) - mean*mean;
    smv[0] = mean; smv[1] = rsqrtf(var + EPSV);
  }
  __syncthreads();
  float out = (v - smv[0]) * smv[1] * g[c] + b[c];
  y[(size_t)l*CD + c] = out;
  if (qkout) qkout[(size_t)l*CD + c] = out + pos[(size_t)l*CD + c];
}

// ---------------- GEMM core: tf32 3x mma, intra-CTA split-K x2 --------------
// C[M,N]=A[M,K]@B[N,K]^T + bias (+res). 64x64 tile, 256 threads = 2 K-halves
// x 4 warps (16 rows x 64 cols each). K-chunk 16, stride-20 smem (bank
// pattern 4g+t: conflict-free). Requires K % 32 == 0, M % 64 == 0.
__device__ __forceinline__ void gemm_body(
    const float* __restrict__ A, const float* __restrict__ B,
    const float* __restrict__ bias, const float* __restrict__ res,
    float* __restrict__ Cout, int M, int N, int K, int bm, int bn) {
  __shared__ float pool[2][4][64*20];   // [half][Ah,Al,Bh,Bl][64 rows x 20]
  const int tid = threadIdx.x;
  const int h = tid >> 7;
  const int htid = tid & 127;
  const int w = htid >> 5, lane = htid & 31;
  const int g = lane >> 2, t = lane & 3;
  const int rw = w * 16;
  const int lr = htid >> 1;            // loader row 0..63
  const int c8 = (htid & 1) << 3;      // loader col base 0 or 8
  const int Kh = K >> 1;
  const int nh = K >> 5;               // 16-wide chunks per half
  const bool bok = (bn + lr) < N;

  float acc[8][4];
  #pragma unroll
  for (int n = 0; n < 8; n++) { acc[n][0]=0.f; acc[n][1]=0.f; acc[n][2]=0.f; acc[n][3]=0.f; }

  float4 pa[2], pb[2];
  {
    const float* Ap = A + (size_t)(bm+lr)*K + h*Kh + c8;
    const float* Bp = B + (size_t)(bn+lr)*K + h*Kh + c8;
    pa[0] = *(const float4*)Ap; pa[1] = *(const float4*)(Ap+4);
    pb[0] = bok ? *(const float4*)Bp     : make_float4(0.f,0.f,0.f,0.f);
    pb[1] = bok ? *(const float4*)(Bp+4) : make_float4(0.f,0.f,0.f,0.f);
  }

  for (int c = 0; c < nh; c++) {
    __syncthreads();
    #pragma unroll
    for (int u = 0; u < 2; u++) {
      float vA[4] = {pa[u].x, pa[u].y, pa[u].z, pa[u].w};
      float vB[4] = {pb[u].x, pb[u].y, pb[u].z, pb[u].w};
      float ahi[4], alo[4], bhi[4], blo[4];
      #pragma unroll
      for (int j = 0; j < 4; j++) {
        ahi[j] = __uint_as_float(tf32r(vA[j]));
        alo[j] = __uint_as_float(tf32r(vA[j] - ahi[j]));
        bhi[j] = __uint_as_float(tf32r(vB[j]));
        blo[j] = __uint_as_float(tf32r(vB[j] - bhi[j]));
      }
      int off = lr*20 + c8 + u*4;
      *(float4*)&pool[h][0][off] = make_float4(ahi[0], ahi[1], ahi[2], ahi[3]);
      *(float4*)&pool[h][1][off] = make_float4(alo[0], alo[1], alo[2], alo[3]);
      *(float4*)&pool[h][2][off] = make_float4(bhi[0], bhi[1], bhi[2], bhi[3]);
      *(float4*)&pool[h][3][off] = make_float4(blo[0], blo[1], blo[2], blo[3]);
    }
    __syncthreads();
    if (c + 1 < nh) {
      const int k0 = h*Kh + (c+1)*16;
      const float* Ap = A + (size_t)(bm+lr)*K + k0 + c8;
      const float* Bp = B + (size_t)(bn+lr)*K + k0 + c8;
      pa[0] = *(const float4*)Ap; pa[1] = *(const float4*)(Ap+4);
      pb[0] = bok ? *(const float4*)Bp     : make_float4(0.f,0.f,0.f,0.f);
      pb[1] = bok ? *(const float4*)(Bp+4) : make_float4(0.f,0.f,0.f,0.f);
    }
    #pragma unroll
    for (int ks = 0; ks < 2; ks++) {
      const int acol = ks*8;
      unsigned qh[4], ql[4];
      qh[0] = __float_as_uint(pool[h][0][(rw+g  )*20 + acol + t  ]);
      qh[1] = __float_as_uint(pool[h][0][(rw+g+8)*20 + acol + t  ]);
      qh[2] = __float_as_uint(pool[h][0][(rw+g  )*20 + acol + t+4]);
      qh[3] = __float_as_uint(pool[h][0][(rw+g+8)*20 + acol + t+4]);
      ql[0] = __float_as_uint(pool[h][1][(rw+g  )*20 + acol + t  ]);
      ql[1] = __float_as_uint(pool[h][1][(rw+g+8)*20 + acol + t  ]);
      ql[2] = __float_as_uint(pool[h][1][(rw+g  )*20 + acol + t+4]);
      ql[3] = __float_as_uint(pool[h][1][(rw+g+8)*20 + acol + t+4]);
      #pragma unroll
      for (int n = 0; n < 8; n++) {
        unsigned bh0 = __float_as_uint(pool[h][2][(n*8+g)*20 + acol + t  ]);
        unsigned bh1 = __float_as_uint(pool[h][2][(n*8+g)*20 + acol + t+4]);
        unsigned bl0 = __float_as_uint(pool[h][3][(n*8+g)*20 + acol + t  ]);
        unsigned bl1 = __float_as_uint(pool[h][3][(n*8+g)*20 + acol + t+4]);
        mma_tf32(acc[n], qh, bh0, bh1);
        mma_tf32(acc[n], qh, bl0, bl1);
        mma_tf32(acc[n], ql, bh0, bh1);
      }
    }
  }

  // cross-half reduction through smem (reuse pool as 64x68 buffer)
  float (*red)[68] = (float(*)[68])&pool[0][0][0];
  __syncthreads();
  if (h == 1) {
    #pragma unroll
    for (int n = 0; n < 8; n++) {
      *(float2*)&red[rw+g  ][n*8+2*t] = make_float2(acc[n][0], acc[n][1]);
      *(float2*)&red[rw+g+8][n*8+2*t] = make_float2(acc[n][2], acc[n][3]);
    }
  }
  __syncthreads();
  if (h == 0) {
    #pragma unroll
    for (int n = 0; n < 8; n++) {
      int cn = bn + n*8 + 2*t;
      float2 r0 = *(const float2*)&red[rw+g  ][n*8+2*t];
      float2 r1 = *(const float2*)&red[rw+g+8][n*8+2*t];
      int m0 = bm + rw + g, m1 = bm + rw + g + 8;
      if (cn < N) {
        float v00 = acc[n][0] + r0.x + bias[cn];
        float v10 = acc[n][2] + r1.x + bias[cn];
        if (res) { v00 += res[(size_t)m0*N + cn]; v10 += res[(size_t)m1*N + cn]; }
        Cout[(size_t)m0*N + cn] = v00;
        Cout[(size_t)m1*N + cn] = v10;
      }
      if (cn + 1 < N) {
        float v01 = acc[n][1] + r0.y + bias[cn+1];
        float v11 = acc[n][3] + r1.y + bias[cn+1];
        if (res) { v01 += res[(size_t)m0*N + cn+1]; v11 += res[(size_t)m1*N + cn+1]; }
        Cout[(size_t)m0*N + cn+1] = v01;
        Cout[(size_t)m1*N + cn+1] = v11;
      }
    }
  }
}

__global__ __launch_bounds__(256) void gemm_nt(
    const float* __restrict__ A, const float* __restrict__ B,
    const float* __restrict__ bias, const float* __restrict__ res,
    float* __restrict__ Cout, int M, int N, int K) {
  gemm_body(A, B, bias, res, Cout, M, N, K, blockIdx.y*64, blockIdx.x*64);
}

__global__ __launch_bounds__(256) void gemm_qkv(
    const float* __restrict__ qkin, const float* __restrict__ t,
    const float* __restrict__ wq, const float* __restrict__ wk, const float* __restrict__ wv,
    const float* __restrict__ bq, const float* __restrict__ bk, const float* __restrict__ bv,
    float* __restrict__ q, float* __restrict__ k, float* __restrict__ v) {
  int z = blockIdx.z;
  const float* A = (z == 2) ? t : qkin;
  const float* B = (z == 0) ? wq : (z == 1 ? wk : wv);
  const float* bias = (z == 0) ? bq : (z == 1 ? bk : bv);
  float* C = (z == 0) ? q : (z == 1 ? k : v);
  gemm_body(A, B, bias, nullptr, C, LQ, CD, CD, blockIdx.y*64, blockIdx.x*64);
}

// pack [lt_wo | st_wo] into (256,512) + combined bias
__global__ __launch_bounds__(256) void pack_w(
    const float* __restrict__ lt, const float* __restrict__ st,
    const float* __restrict__ ltb, const float* __restrict__ stb,
    float* __restrict__ wcat, float* __restrict__ bcat) {
  int idx = blockIdx.x * 256 + threadIdx.x;
  int nrow = idx >> 9, k = idx & 511;
  wcat[idx] = (k < 256) ? lt[nrow*256 + k] : st[nrow*256 + k - 256];
  if (idx < 256) bcat[idx] = ltb[idx] + stb[idx];
}

// ---------------- Fused full attention: tf32 mma (3xTF32), split-KV x3 ------
// grid (25 q-tiles, 8 heads, 3 kv-splits), 128 threads (4 warps x 16 q-rows).
// Ks stride 36 (banks 4g+t: conflict-free); Vs stride 40 (banks 8t+g: ok).
__global__ __launch_bounds__(128, 4) void attn_kernel(
    const float* __restrict__ Q, const float* __restrict__ Kp,
    const float* __restrict__ Vp, float* __restrict__ Opart, float2* __restrict__ ml) {
  __shared__ float Vs_hi[64][40];
  __shared__ float Vs_lo[64][40];
  __shared__ float uKP[4608];   // Ks_hi [64][36] | Ks_lo +2304 ; reused as Ps[64][68]
  #define KS_HI(kk,dd) uKP[(kk)*36 + (dd)]
  #define KS_LO(kk,dd) uKP[2304 + (kk)*36 + (dd)]
  #define PS(rr,cc)    uKP[(rr)*68 + (cc)]

  const int h = blockIdx.y;
  const int z = blockIdx.z;
  const int q0 = blockIdx.x * 64;
  const int kt0 = (z == 0) ? 0 : 9 + (z - 1) * 8;
  const int kt1 = (z == 0) ? 9 : kt0 + 8;
  const int tid = threadIdx.x;
  const int w = tid >> 5, lane = tid & 31;
  const int g = lane >> 2, t = lane & 3;
  const int qb = q0 + w*16;

  // --- Q fragments (hi/lo tf32), loaded once ---
  unsigned qhi[4][4], qlo[4][4];
  #pragma unroll
  for (int s = 0; s < 4; s++) {
    const int k0 = s*8;
    float f[4];
    f[0] = Q[(size_t)(qb+g  )*CD + h*HD + k0 + t    ] * QSCALE;
    f[1] = Q[(size_t)(qb+g+8)*CD + h*HD + k0 + t    ] * QSCALE;
    f[2] = Q[(size_t)(qb+g  )*CD + h*HD + k0 + t + 4] * QSCALE;
    f[3] = Q[(size_t)(qb+g+8)*CD + h*HD + k0 + t + 4] * QSCALE;
    #pragma unroll
    for (int i = 0; i < 4; i++) {
      qhi[s][i] = tf32r(f[i]);
      qlo[s][i] = tf32r(f[i] - __uint_as_float(qhi[s][i]));
    }
  }

  float m_i[2] = {-1e30f, -1e30f};
  float l_i[2] = {0.f, 0.f};
  float oacc[4][4] = {};

  for (int kt = kt0; kt < kt1; kt++) {
    const int kb = kt * 64;
    __syncthreads();   // prior tile fully consumed (PV reads Vs, Ps in uKP)
    // --- producer: K/V tile -> smem with tf32 hi/lo split ---
    #pragma unroll
    for (int it = 0; it < 4; it++) {
      int idx = tid + it*128;
      int r = idx >> 3, d4 = (idx & 7) << 2;
      float4 kv = *(const float4*)(Kp + (size_t)(kb + r)*CD + h*HD + d4);
      float4 vv = *(const float4*)(Vp + (size_t)(kb + r)*CD + h*HD + d4);
      float kf[4] = {kv.x, kv.y, kv.z, kv.w};
      float vf[4] = {vv.x, vv.y, vv.z, vv.w};
      float khi[4], klo[4], vhi[4], vlo[4];
      #pragma unroll
      for (int j = 0; j < 4; j++) {
        khi[j] = __uint_as_float(tf32r(kf[j]));
        klo[j] = __uint_as_float(tf32r(kf[j] - khi[j]));
        vhi[j] = __uint_as_float(tf32r(vf[j]));
        vlo[j] = __uint_as_float(tf32r(vf[j] - vhi[j]));
      }
      *(float4*)&KS_HI(r, d4) = make_float4(khi[0], khi[1], khi[2], khi[3]);
      *(float4*)&KS_LO(r, d4) = make_float4(klo[0], klo[1], klo[2], klo[3]);
      *(float4*)&Vs_hi[r][d4] = make_float4(vhi[0], vhi[1], vhi[2], vhi[3]);
      *(float4*)&Vs_lo[r][d4] = make_float4(vlo[0], vlo[1], vlo[2], vlo[3]);
    }
    __syncthreads();

    // --- QK^T: S[16 x 64] per warp via 3xTF32 mma ---
    float sacc[8][4];
    #pragma unroll
    for (int n = 0; n < 8; n++)
      #pragma unroll
      for (int i = 0; i < 4; i++) sacc[n][i] = 0.f;
    #pragma unroll
    for (int n = 0; n < 8; n++) {
      #pragma unroll
      for (int s = 0; s < 4; s++) {
        unsigned bh0 = __float_as_uint(KS_HI(n*8+g, s*8+t));
        unsigned bh1 = __float_as_uint(KS_HI(n*8+g, s*8+t+4));
        unsigned bl0 = __float_as_uint(KS_LO(n*8+g, s*8+t));
        unsigned bl1 = __float_as_uint(KS_LO(n*8+g, s*8+t+4));
        mma_tf32(sacc[n], qhi[s], bh0, bh1);
        mma_tf32(sacc[n], qhi[s], bl0, bl1);
        mma_tf32(sacc[n], qlo[s], bh0, bh1);
      }
    }
    __syncthreads();   // all warps done reading Ks before Ps overwrites uKP

    // --- online softmax (rows g and g+8 of this warp's 16) ---
    #pragma unroll
    for (int ri = 0; ri < 2; ri++) {
      float rm = -1e30f;
      #pragma unroll
      for (int n = 0; n < 8; n++)
        rm = fmaxf(rm, fmaxf(sacc[n][2*ri], sacc[n][2*ri+1]));
      rm = fmaxf(rm, __shfl_xor_sync(0xffffffffu, rm, 1));
      rm = fmaxf(rm, __shfl_xor_sync(0xffffffffu, rm, 2));
      float mnew = fmaxf(m_i[ri], rm);
      float alpha = __expf(m_i[ri] - mnew);
      float rs = 0.f;
      int prow = w*16 + g + ri*8;
      #pragma unroll
      for (int n = 0; n < 8; n++) {
        float p0 = __expf(sacc[n][2*ri]   - mnew);
        float p1 = __expf(sacc[n][2*ri+1] - mnew);
        *(float2*)&PS(prow, n*8 + 2*t) = make_float2(p0, p1);
        rs += p0 + p1;
      }
      rs += __shfl_xor_sync(0xffffffffu, rs, 1);
      rs += __shfl_xor_sync(0xffffffffu, rs, 2);
      l_i[ri] = l_i[ri]*alpha + rs;
      m_i[ri] = mnew;
      #pragma unroll
      for (int n = 0; n < 4; n++) { oacc[n][2*ri] *= alpha; oacc[n][2*ri+1] *= alpha; }
    }
    __syncwarp();

    // --- P @ V via 3xTF32 mma ---
    #pragma unroll
    for (int kk = 0; kk < 8; kk++) {
      float pf[4];
      pf[0] = PS(w*16 + g,     kk*8 + t);
      pf[1] = PS(w*16 + g + 8, kk*8 + t);
      pf[2] = PS(w*16 + g,     kk*8 + t + 4);
      pf[3] = PS(w*16 + g + 8, kk*8 + t + 4);
      unsigned ahi[4], alo[4];
      #pragma unroll
      for (int i = 0; i < 4; i++) {
        ahi[i] = tf32r(pf[i]);
        alo[i] = tf32r(pf[i] - __uint_as_float(ahi[i]));
      }
      #pragma unroll
      for (int n = 0; n < 4; n++) {
        unsigned bh0 = __float_as_uint(Vs_hi[kk*8+t  ][n*8+g]);
        unsigned bh1 = __float_as_uint(Vs_hi[kk*8+t+4][n*8+g]);
        unsigned bl0 = __float_as_uint(Vs_lo[kk*8+t  ][n*8+g]);
        unsigned bl1 = __float_as_uint(Vs_lo[kk*8+t+4][n*8+g]);
        mma_tf32(oacc[n], ahi, bh0, bh1);
        mma_tf32(oacc[n], ahi, bl0, bl1);
        mma_tf32(oacc[n], alo, bh0, bh1);
      }
    }
  }

  // --- epilogue: unnormalized partials + (m,l) ---
  #pragma unroll
  for (int n = 0; n < 4; n++) {
    *(float2*)&Opart[((size_t)z*LQ + qb + g    )*CD + h*HD + n*8 + 2*t] =
        make_float2(oacc[n][0], oacc[n][1]);
    *(float2*)&Opart[((size_t)z*LQ + qb + g + 8)*CD + h*HD + n*8 + 2*t] =
        make_float2(oacc[n][2], oacc[n][3]);
  }
  if (t == 0) {
    ml[(z*LQ + qb + g    )*NHD + h] = make_float2(m_i[0], l_i[0]);
    ml[(z*LQ + qb + g + 8)*NHD + h] = make_float2(m_i[1], l_i[1]);
  }
  #undef KS_HI
  #undef KS_LO
  #undef PS
}

// merge the kv-splits
__global__ __launch_bounds__(256) void attn_merge(
    const float* __restrict__ Opart, const float2* __restrict__ ml,
    float* __restrict__ O, int ostride, int ooff) {
  int row = blockIdx.x, c = threadIdx.x;
  int h = c >> 5;
  float2 mlp[NSPLIT];
  float m = -1e30f;
  #pragma unroll
  for (int p = 0; p < NSPLIT; p++) {
    mlp[p] = ml[(p*LQ + row)*NHD + h];
    m = fmaxf(m, mlp[p].x);
  }
  float l = 0.f, o = 0.f;
  #pragma unroll
  for (int p = 0; p < NSPLIT; p++) {
    float e = __expf(mlp[p].x - m);
    l += mlp[p].y * e;
    o += Opart[((size_t)p*LQ + row)*CD + c] * e;
  }
  O[(size_t)row*ostride + ooff + c] = o / l;
}

// ---------------- curr_Q / global_K / global_V construction ----------------
__global__ __launch_bounds__(256) void make_kv_kernel(
    const float* __restrict__ qv, const float* __restrict__ idkv,
    float* __restrict__ q, float* __restrict__ gK, float* __restrict__ gV) {
  int l = blockIdx.x, c = threadIdx.x;
  float cq  = qv[(size_t)l*512 + c];
  float cv  = qv[(size_t)l*512 + 256 + c];
  float idk = idkv[(size_t)l*264 + (c >> 5)];
  float idv = idkv[(size_t)l*264 + 8 + c];
  q [(size_t)l*CD + c] = cq;
  gK[(size_t)l*CD + c] = cq * (1.f + tanhf(idk));
  gV[(size_t)l*CD + c] = cv + idv;
}

// ---------------- Local 15x15 window attention ----------------
__global__ __launch_bounds__(256) void local_attn_kernel(
    const float* __restrict__ Q, const float* __restrict__ Kp,
    const float* __restrict__ Vp, float* __restrict__ O, int ostride, int ooff) {
  __shared__ float p_sh[8][232];
  int n = blockIdx.x;
  int r = n / GW, c = n % GW;
  int h = threadIdx.x >> 5, lane = threadIdx.x & 31;

  const float* qp = Q + (size_t)n*CD + h*HD;
  float4 qreg[8];
  #pragma unroll
  for (int i = 0; i < 8; i++) {
    qreg[i] = *(const float4*)(qp + i*4);
    qreg[i].x *= QSCALE; qreg[i].y *= QSCALE; qreg[i].z *= QSCALE; qreg[i].w *= QSCALE;
  }
  int i0 = max(7 - r, 0), i1 = min(GH + 7 - r, 15);
  int j0 = max(7 - c, 0), j1 = min(GW + 7 - c, 15);

  for (int w = lane; w < 225; w += 32) {
    int wi = w / 15, wj = w - wi*15;
    float logit = -1e30f;
    if (wi >= i0 && wi < i1 && wj >= j0 && wj < j1) {
      const float* kp = Kp + (size_t)((r+wi-7)*GW + (c+wj-7))*CD + h*HD;
      float acc = 0.f;
      #pragma unroll
      for (int i4 = 0; i4 < 8; i4++) {
        float4 kv = *(const float4*)(kp + i4*4);
        acc = fmaf(qreg[i4].x, kv.x, acc);
        acc = fmaf(qreg[i4].y, kv.y, acc);
        acc = fmaf(qreg[i4].z, kv.z, acc);
        acc = fmaf(qreg[i4].w, kv.w, acc);
      }
      logit = acc;
    }
    p_sh[h][w] = logit;
  }
  __syncwarp();
  float m = -1e30f;
  for (int ww = lane; ww < 225; ww += 32) m = fmaxf(m, p_sh[h][ww]);
  #pragma unroll
  for (int o = 16; o; o >>= 1) m = fmaxf(m, __shfl_xor_sync(0xffffffffu, m, o));
  float ssum = 0.f;
  for (int ww = lane; ww < 225; ww += 32) {
    float p = __expf(p_sh[h][ww] - m);
    p_sh[h][ww] = p;
    ssum += p;
  }
  #pragma unroll
  for (int o = 16; o; o >>= 1) ssum += __shfl_xor_sync(0xffffffffu, ssum, o);
  float inv = 1.f / ssum;
  __syncwarp();
  float oacc = 0.f;
  for (int wi = i0; wi < i1; wi++) {
    const float* vrow = Vp + (size_t)((r+wi-7)*GW + (c+j0-7))*CD + h*HD + lane;
    #pragma unroll 3
    for (int wj = j0; wj < j1; wj++, vrow += CD)
      oacc = fmaf(p_sh[h][wi*15+wj], *vrow, oacc);
  }
  O[(size_t)n*ostride + ooff + h*HD + lane] = oacc * inv;
}

// ---------------- GroupNorm stats ----------------
__global__ __launch_bounds__(1024) void gn_stats_kernel(
    const float* __restrict__ x, float* __restrict__ stats) {
  int g = blockIdx.x;
  float s = 0.f, s2 = 0.f;
  for (int idx = threadIdx.x; idx < LQ*32; idx += 1024) {
    int l = idx >> 5, ch = idx & 31;
    float v = x[(size_t)l*DFF + g*32 + ch];
    s += v; s2 += v*v;
  }
  #pragma unroll
  for (int o = 16; o; o >>= 1) {
    s  += __shfl_xor_sync(0xffffffffu, s,  o);
    s2 += __shfl_xor_sync(0xffffffffu, s2, o);
  }
  __shared__ float sh[32], sh2[32];
  int w = threadIdx.x >> 5, lane = threadIdx.x & 31;
  if (lane == 0) { sh[w] = s; sh2[w] = s2; }
  __syncthreads();
  if (w == 0) {
    s = sh[lane]; s2 = sh2[lane];
    #pragma unroll
    for (int o = 16; o; o >>= 1) {
      s  += __shfl_xor_sync(0xffffffffu, s,  o);
      s2 += __shfl_xor_sync(0xffffffffu, s2, o);
    }
    if (lane == 0) {
      const float invn = 1.f / (LQ * 32.f);
      float mean = s * invn;
      float var  = s2 * invn - mean*mean;
      stats[g*2]   = mean;
      stats[g*2+1] = rsqrtf(var + EPSV);
    }
  }
}

// ---------------- GN apply + exact GELU ----------------
__global__ __launch_bounds__(256) void gn_gelu_kernel(
    const float* __restrict__ x, const float* __restrict__ gg, const float* __restrict__ gb,
    const float* __restrict__ stats, float* __restrict__ y) {
  int idx = blockIdx.x * 256 + threadIdx.x;
  int ch = idx & (DFF-1);
  int g = ch >> 5;
  float v = (x[idx] - stats[g*2]) * stats[g*2+1] * gg[ch] + gb[ch];
  y[idx] = 0.5f * v * (1.f + erff(v * 0.70710678118654752f));
}

// ---------------- 5x5 depthwise conv, pad 2 ----------------
__global__ __launch_bounds__(256) void dwconv_kernel(
    const float* __restrict__ x, const float* __restrict__ kern, float* __restrict__ y) {
  __shared__ float tile[12][12][32];
  __shared__ float kw[32][25];
  int tid = threadIdx.x;
  int ch0 = blockIdx.z * 32;
  int r0 = blockIdx.y * 8 - 2, c0 = blockIdx.x * 8 - 2;
  for (int e = tid; e < 12*12*32; e += 256) {
    int ch = e & 31;
    int sp = e >> 5;
    int ri = sp / 12, ci = sp % 12;
    int rr = r0 + ri, cc = c0 + ci;
    float v = 0.f;
    if ((unsigned)rr < (unsigned)GH && (unsigned)cc < (unsigned)GW)
      v = x[(size_t)(rr*GW + cc)*DFF + ch0 + ch];
    tile[ri][ci][ch] = v;
  }
  for (int e = tid; e < 32*25; e += 256)
    kw[e/25][e%25] = kern[(size_t)(ch0 + e/25)*25 + e%25];
  __syncthreads();
  for (int e = tid; e < 8*8*32; e += 256) {
    int ch = e & 31;
    int sp = e >> 5;
    int ri = sp >> 3, ci = sp & 7;
    float acc = 0.f;
    #pragma unroll
    for (int i = 0; i < 5; i++)
      #pragma unroll
      for (int j = 0; j < 5; j++)
        acc = fmaf(tile[ri+i][ci+j][ch], kw[ch][i*5+j], acc);
    int rr = blockIdx.y*8 + ri, cc = blockIdx.x*8 + ci;
    y[(size_t)(rr*GW + cc)*DFF + ch0 + ch] = acc;
  }
}

// ---------------- launcher ----------------
extern "C" void kernel_launch(void* const* d_in, const int* in_sizes, int n_in,
                              void* d_out, int out_size) {
  const float* in_tgt   = (const float*)d_in[0];
  const float* id_emb   = (const float*)d_in[1];
  const float* self_pos = (const float*)d_in[2];
  const float* ln1_g = (const float*)d_in[3];
  const float* ln1_b = (const float*)d_in[4];
  const float* sa_wq = (const float*)d_in[5];
  const float* sa_bq = (const float*)d_in[6];
  const float* sa_wk = (const float*)d_in[7];
  const float* sa_bk = (const float*)d_in[8];
  const float* sa_wv = (const float*)d_in[9];
  const float* sa_bv = (const float*)d_in[10];
  const float* sa_wo = (const float*)d_in[11];
  const float* sa_bo = (const float*)d_in[12];
  const float* ln2_g = (const float*)d_in[13];
  const float* ln2_b = (const float*)d_in[14];
  const float* w_qv = (const float*)d_in[15];
  const float* b_qv = (const float*)d_in[16];
  const float* w_id = (const float*)d_in[17];
  const float* b_id = (const float*)d_in[18];
  const float* lt_wo = (const float*)d_in[19];
  const float* lt_bo = (const float*)d_in[20];
  const float* st_wo = (const float*)d_in[21];
  const float* st_bo = (const float*)d_in[22];
  const float* ln3_g = (const float*)d_in[23];
  const float* ln3_b = (const float*)d_in[24];
  const float* w1 = (const float*)d_in[25];
  const float* b1 = (const float*)d_in[26];
  const float* gn_g = (const float*)d_in[27];
  const float* gn_b = (const float*)d_in[28];
  const float* dw_k = (const float*)d_in[29];
  const float* w2 = (const float*)d_in[30];
  const float* b2 = (const float*)d_in[31];
  float* out = (float*)d_out;

  float *t, *qkin, *q, *k, *v, *attcat, *tgtb, *qv, *idkv, *gK, *gV, *x, *x2, *stats, *wcat, *bcat, *opart;
  float2 *ml;
  cudaGetSymbolAddress((void**)&t,      g_t);
  cudaGetSymbolAddress((void**)&qkin,   g_qkin);
  cudaGetSymbolAddress((void**)&q,      g_q);
  cudaGetSymbolAddress((void**)&k,      g_k);
  cudaGetSymbolAddress((void**)&v,      g_v);
  cudaGetSymbolAddress((void**)&attcat, g_attcat);
  cudaGetSymbolAddress((void**)&tgtb,   g_tgt);
  cudaGetSymbolAddress((void**)&qv,     g_qv);
  cudaGetSymbolAddress((void**)&idkv,   g_idkv);
  cudaGetSymbolAddress((void**)&gK,     g_gK);
  cudaGetSymbolAddress((void**)&gV,     g_gV);
  cudaGetSymbolAddress((void**)&x,      g_x);
  cudaGetSymbolAddress((void**)&x2,     g_x2);
  cudaGetSymbolAddress((void**)&stats,  g_stats);
  cudaGetSymbolAddress((void**)&wcat,   g_wcat);
  cudaGetSymbolAddress((void**)&bcat,   g_bcat);
  cudaGetSymbolAddress((void**)&opart,  g_opart);
  cudaGetSymbolAddress((void**)&ml,     g_ml);

  dim3 g66(4, 25);
  dim3 gQKV(4, 25, 3);
  dim3 gAttn(25, 8, NSPLIT);

  pack_w<<<512,256>>>(lt_wo, st_wo, lt_bo, st_bo, wcat, bcat);
  cudaMemcpyAsync(tgtb, in_tgt, sizeof(float)*LQ*CD, cudaMemcpyDeviceToDevice, 0);

  // --- self attention ---
  ln_kernel<<<LQ,256>>>(in_tgt, ln1_g, ln1_b, t, self_pos, qkin);
  gemm_qkv<<<gQKV,256>>>(qkin, t, sa_wq, sa_wk, sa_wv, sa_bq, sa_bk, sa_bv, q, k, v);
  attn_kernel<<<gAttn,128>>>(q, k, v, opart, ml);
  attn_merge<<<LQ,256>>>(opart, ml, attcat, 256, 0);
  gemm_nt<<<g66,256>>>(attcat, sa_wo, sa_bo, tgtb, tgtb, LQ, CD, CD);

  // --- long/short term attention ---
  ln_kernel<<<LQ,256>>>(tgtb, ln2_g, ln2_b, t, nullptr, nullptr);
  gemm_nt<<<dim3(8,25),256>>>(t, w_qv, b_qv, nullptr, qv, LQ, 512, CD);
  gemm_nt<<<dim3(5,25),256>>>(id_emb, w_id, b_id, nullptr, idkv, LQ, 264, CD);
  make_kv_kernel<<<LQ,256>>>(qv, idkv, q, gK, gV);
  attn_kernel<<<gAttn,128>>>(q, gK, gV, opart, ml);
  attn_merge<<<LQ,256>>>(opart, ml, attcat, 512, 0);
  local_attn_kernel<<<LQ,256>>>(q, gK, gV, attcat, 512, 256);
  gemm_nt<<<g66,256>>>(attcat, wcat, bcat, tgtb, tgtb, LQ, CD, 512);

  // --- MLP: LN -> w1 -> GN -> GELU -> dwconv -> w2 ---
  ln_kernel<<<LQ,256>>>(tgtb, ln3_g, ln3_b, t, nullptr, nullptr);
  gemm_nt<<<dim3(16,25),256>>>(t, w1, b1, nullptr, x, LQ, DFF, CD);
  gn_stats_kernel<<<32,1024>>>(x, stats);
  gn_gelu_kernel<<<(LQ*DFF)/256,256>>>(x, gn_g, gn_b, stats, x2);
  dwconv_kernel<<<dim3(5,5,32),256>>>(x2, dw_k, x);
  gemm_nt<<<g66,256>>>(x, w2, b2, tgtb, out, LQ, CD, DFF);
}